// round 11
// baseline (speedup 1.0000x reference)
#include <cuda_runtime.h>
#include <cuda_bf16.h>
#include <math.h>
#include <stdint.h>

#define MAXN 50000
#define MAXE 800000
#define D 64
#define XS 130
#define WS 68

// tcgen05 is arch-SPECIFIC: only emit it in the sm_103a/'a'-target device pass.
#if !defined(__CUDA_ARCH__) || defined(__CUDA_ARCH_FEAT_SM103_ALL) || \
    defined(__CUDA_ARCH_FEAT_SM100_ALL) || defined(__CUDA_ARCH_SPECIFIC__) || \
    defined(__CUDA_ARCH_FAMILY_SPECIFIC__)
#define TC_OK 1
#else
#define TC_OK 0
#endif

typedef unsigned long long ull;

// ---------------- scratch ---------------------------------------------------
__device__ uint32_t g_xnh[MAXN * 32];   // xn bf16 hi, packed pairs
__device__ uint32_t g_xnl[MAXN * 32];   // xn bf16 lo (residual)
__device__ float g_qh_s[MAXN * D];
__device__ float g_qh_d[MAXN * D];
__device__ float g_c_s [MAXN];
__device__ float g_c_d [MAXN];
__device__ float g_den [MAXN];
__device__ float g_aggr[MAXN * D];
__device__ int   g_perm_s[MAXE];
__device__ int   g_perm_d[MAXE];
__device__ int   g_cnt[2];
__device__ float g_MsT[4096];
__device__ float g_MdT[4096];
__device__ float g_ds[64], g_dd[64];
__device__ float g_us[64], g_ud[64];
__device__ float g_ec[2];

__device__ __forceinline__ float gelu_erf(float x) {
    return 0.5f * x * (1.0f + erff(x * 0.70710678118654752440f));
}
__device__ __forceinline__ ull dup2(float x) {
    ull r; asm("mov.b64 %0, {%1, %1};" : "=l"(r) : "f"(x)); return r;
}
__device__ __forceinline__ void ffma2(ull& d, ull a, ull b) {
    asm("fma.rn.f32x2 %0, %1, %2, %0;" : "+l"(d) : "l"(a), "l"(b));
}
__device__ __forceinline__ float2 unpk(ull v) {
    float2 f; asm("mov.b64 {%0, %1}, %2;" : "=f"(f.x), "=f"(f.y) : "l"(v)); return f;
}

// ---------------- bf16 pack helpers ------------------------------------------
__device__ __forceinline__ uint32_t packbf(float x0, float x1) {
    uint32_t r;
    asm("cvt.rn.bf16x2.f32 %0, %2, %1;" : "=r"(r) : "f"(x0), "f"(x1));
    return r;
}
__device__ __forceinline__ void split2(float x0, float x1, uint32_t& hp, uint32_t& lp) {
    hp = packbf(x0, x1);
    float h0 = __uint_as_float(hp << 16);
    float h1 = __uint_as_float(hp & 0xffff0000u);
    lp = packbf(x0 - h0, x1 - h1);
}

__device__ __forceinline__ uint32_t smem_u32(const void* p) {
    uint32_t a;
    asm("{ .reg .u64 t; cvta.to.shared.u64 t, %1; cvt.u32.u64 %0, t; }"
        : "=r"(a) : "l"(p));
    return a;
}
#define SW128(o) ((o) ^ (((o) >> 3) & 0x70))

__device__ __forceinline__ uint64_t mkdesc(uint32_t addr) {
    const uint64_t base = (2ull << 61) | (1ull << 46) | (64ull << 32) | (1ull << 16);
    return base | ((addr >> 4) & 0x3FFF);
}

// idesc kind::f16, bf16 x bf16 -> f32, M=128, N=64
#define MMA_IDESC 0x08100490u

#if TC_OK
__device__ __forceinline__ void mma_f16_ss(uint32_t d_tmem, uint64_t a_desc,
                                           uint64_t b_desc, uint32_t en) {
    asm volatile(
        "{\n\t"
        ".reg .pred p;\n\t"
        "setp.ne.u32 p, %5, 0;\n\t"
        "tcgen05.mma.cta_group::1.kind::f16 [%0], %1, %2, %3, {%4, %4, %4, %4}, p;\n\t"
        "}"
        :: "r"(d_tmem), "l"(a_desc), "l"(b_desc), "r"(MMA_IDESC), "r"(0u), "r"(en)
        : "memory");
}

#define TC_ALLOC(smem_addr, n) \
    asm volatile("tcgen05.alloc.cta_group::1.sync.aligned.shared::cta.b32 [%0], %1;" \
                 :: "r"(smem_addr), "r"((uint32_t)(n)) : "memory")
#define TC_RELINQ() \
    asm volatile("tcgen05.relinquish_alloc_permit.cta_group::1.sync.aligned;")
#define TC_DEALLOC(tmem, n) \
    asm volatile("tcgen05.dealloc.cta_group::1.sync.aligned.b32 %0, %1;" \
                 :: "r"(tmem), "r"((uint32_t)(n)))
#define TC_COMMIT(mbar) \
    asm volatile("tcgen05.commit.cta_group::1.mbarrier::arrive::one.shared::cluster.b64 [%0];" \
                 :: "r"(mbar) : "memory")
#define TC_FENCE_AFTER() \
    asm volatile("tcgen05.fence::after_thread_sync;" ::: "memory")
#define TC_WAIT_LD() \
    asm volatile("tcgen05.wait::ld.sync.aligned;" ::: "memory")
#define FENCE_PROXY() \
    asm volatile("fence.proxy.async.shared::cta;" ::: "memory")
#define MBAR_INIT(mbar, n) \
    asm volatile("mbarrier.init.shared.b64 [%0], %1;" :: "r"(mbar), "r"((uint32_t)(n)) : "memory")
#define MBAR_INVAL(mbar) \
    asm volatile("mbarrier.inval.shared.b64 [%0];" :: "r"(mbar) : "memory")

__device__ __forceinline__ void mbar_wait(uint32_t mbar, uint32_t parity) {
    asm volatile(
        "{\n\t"
        ".reg .pred P;\n\t"
        "WLOOP%=:\n\t"
        "mbarrier.try_wait.parity.acquire.cta.shared::cta.b64 P, [%0], %1, 0x989680;\n\t"
        "@P bra.uni WDONE%=;\n\t"
        "bra.uni WLOOP%=;\n\t"
        "WDONE%=:\n\t"
        "}"
        :: "r"(mbar), "r"(parity) : "memory");
}

#define TC_LD_X32(r, tmem_addr) \
    asm volatile( \
        "tcgen05.ld.sync.aligned.32x32b.x32.b32 " \
        "{%0, %1, %2, %3, %4, %5, %6, %7, " \
        " %8, %9, %10, %11, %12, %13, %14, %15, " \
        " %16, %17, %18, %19, %20, %21, %22, %23, " \
        " %24, %25, %26, %27, %28, %29, %30, %31}, [%32];" \
        : "=r"((r)[0]),  "=r"((r)[1]),  "=r"((r)[2]),  "=r"((r)[3]), \
          "=r"((r)[4]),  "=r"((r)[5]),  "=r"((r)[6]),  "=r"((r)[7]), \
          "=r"((r)[8]),  "=r"((r)[9]),  "=r"((r)[10]), "=r"((r)[11]), \
          "=r"((r)[12]), "=r"((r)[13]), "=r"((r)[14]), "=r"((r)[15]), \
          "=r"((r)[16]), "=r"((r)[17]), "=r"((r)[18]), "=r"((r)[19]), \
          "=r"((r)[20]), "=r"((r)[21]), "=r"((r)[22]), "=r"((r)[23]), \
          "=r"((r)[24]), "=r"((r)[25]), "=r"((r)[26]), "=r"((r)[27]), \
          "=r"((r)[28]), "=r"((r)[29]), "=r"((r)[30]), "=r"((r)[31]) \
        : "r"(tmem_addr))
#endif  // TC_OK

// ---------------- kernel 0: init --------------------------------------------
__global__ void init_kernel(int N) {
    int i = blockIdx.x * blockDim.x + threadIdx.x;
    if (i < N * D) g_aggr[i] = 0.0f;
    if (i < N) g_den[i] = 0.0f;
    if (i == 0) { g_cnt[0] = 0; g_cnt[1] = 0; }
}

// ---------------- kernel 0b: partition (warp-aggregated atomics) -------------
__global__ void partition_kernel(const float* __restrict__ esame, int E) {
    int e = blockIdx.x * blockDim.x + threadIdx.x;
    int lane = threadIdx.x & 31;
    bool act = e < E;
    float es = act ? esame[e] : 0.0f;
    bool s = act && (es >= 0.5f);
    bool d = act && (es < 0.5f);
    unsigned ms = __ballot_sync(0xffffffffu, s);
    unsigned md = __ballot_sync(0xffffffffu, d);
    int bs = 0, bd = 0;
    if (lane == 0) {
        if (ms) bs = atomicAdd(&g_cnt[0], __popc(ms));
        if (md) bd = atomicAdd(&g_cnt[1], __popc(md));
    }
    bs = __shfl_sync(0xffffffffu, bs, 0);
    bd = __shfl_sync(0xffffffffu, bd, 0);
    unsigned lower = (1u << lane) - 1u;
    if (s) g_perm_s[bs + __popc(ms & lower)] = e;
    if (d) g_perm_d[bd + __popc(md & lower)] = e;
}

// ---------------- kernel 0c: fold Wq into Wk space ---------------------------
__global__ __launch_bounds__(256) void fold_kernel(
    const float* __restrict__ Wq, const float* __restrict__ bq,
    const float* __restrict__ Wks, const float* __restrict__ bks,
    const float* __restrict__ Wkd, const float* __restrict__ bkd)
{
    int b = blockIdx.x;
    const float* Wk = b ? Wkd : Wks;
    const float* bk = b ? bkd : bks;
    float* MT   = b ? g_MdT : g_MsT;
    float* dvec = b ? g_dd : g_ds;
    float* uvec = b ? g_ud : g_us;

    __shared__ float sWq[4096], sWk[4096], sbq[64], sbk[64];
    int tid = threadIdx.x;
    for (int i = tid; i < 4096; i += 256) { sWq[i] = Wq[i]; sWk[i] = Wk[i]; }
    if (tid < 64) { sbq[tid] = bq[tid]; sbk[tid] = bk[tid]; }
    __syncthreads();
#pragma unroll
    for (int ii = 0; ii < 16; ii++) {
        int o = tid + ii * 256;
        int j = o >> 6, c = o & 63;
        float s = 0.0f;
#pragma unroll 8
        for (int m = 0; m < 64; m++) s += sWk[m * 64 + c] * sWq[m * 64 + j];
        MT[o] = s;
    }
    if (tid < 64) {
        float sd = 0.0f, su = 0.0f;
#pragma unroll 8
        for (int m = 0; m < 64; m++) {
            sd += sWk[m * 64 + tid] * sbq[m];
            su += sbk[m] * sWq[m * 64 + tid];
        }
        dvec[tid] = sd; uvec[tid] = su;
    }
    if (tid == 0) {
        float s = 0.0f;
        for (int m = 0; m < 64; m++) s += sbk[m] * sbq[m];
        g_ec[b] = s;
    }
}

// ---------------- kernel 1: layernorm + qh_s/qh_d/c + packed xn ---------------
#define NODE_SMEM_FLOATS (64*XS + 2*64*WS + 8*64)
__global__ __launch_bounds__(256, 2) void node_kernel(
    const float* __restrict__ x, const float* __restrict__ gamma,
    const float* __restrict__ beta, int N)
{
    extern __shared__ float ns[];
    float* XsT = ns;
    float* sMs = XsT + 64 * XS;
    float* sMd = sMs + 64 * WS;
    float* sg  = sMd + 64 * WS;
    float* sb  = sg + 64;
    float* sus = sb + 64;
    float* sud = sus + 64;
    float* sds = sud + 64;
    float* sdd = sds + 64;

    int tid = threadIdx.x;
    for (int i = tid; i < 4096; i += 256) {
        int j = i >> 6, c = i & 63;
        sMs[j * WS + c] = g_MsT[i];
        sMd[j * WS + c] = g_MdT[i];
    }
    if (tid < 64) {
        sg[tid] = gamma[tid]; sb[tid] = beta[tid];
        sus[tid] = g_us[tid]; sud[tid] = g_ud[tid];
        sds[tid] = g_ds[tid]; sdd[tid] = g_dd[tid];
    }
    __syncthreads();

    int n0 = blockIdx.x * 128;
    int cnt = min(128, N - n0);

    {
        int nl = tid >> 1, half = tid & 1;
        bool act = nl < cnt;
        int n = n0 + nl;
        float4 xv[8];
        float s = 0.0f, t = 0.0f;
        if (act) {
            const float4* xr = (const float4*)(x + (size_t)n * 64) + half * 8;
#pragma unroll
            for (int kk = 0; kk < 8; kk++) {
                xv[kk] = xr[kk];
                s += xv[kk].x + xv[kk].y + xv[kk].z + xv[kk].w;
                t += xv[kk].x * xv[kk].x + xv[kk].y * xv[kk].y
                   + xv[kk].z * xv[kk].z + xv[kk].w * xv[kk].w;
            }
        }
        s += __shfl_xor_sync(0xffffffffu, s, 1);
        t += __shfl_xor_sync(0xffffffffu, t, 1);
        float mu = s * (1.0f / 64.0f);
        float var = t * (1.0f / 64.0f) - mu * mu;
        float inv = rsqrtf(var + 1e-5f);
        float cs = 0.0f, cd = 0.0f;
        if (act) {
            uint32_t* gh = g_xnh + (size_t)n * 32 + half * 16;
            uint32_t* gl = g_xnl + (size_t)n * 32 + half * 16;
#pragma unroll
            for (int kk = 0; kk < 8; kk++) {
                int c0 = half * 32 + 4 * kk;
                float v[4] = {xv[kk].x, xv[kk].y, xv[kk].z, xv[kk].w};
                float xn4[4];
#pragma unroll
                for (int p = 0; p < 4; p++) {
                    int c = c0 + p;
                    float xn = (v[p] - mu) * inv * sg[c] + sb[c];
                    xn4[p] = xn;
                    XsT[c * XS + nl] = xn;
                    cs += xn * sus[c];
                    cd += xn * sud[c];
                }
                uint32_t h01, l01, h23, l23;
                split2(xn4[0], xn4[1], h01, l01);
                split2(xn4[2], xn4[3], h23, l23);
                gh[2 * kk] = h01; gh[2 * kk + 1] = h23;
                gl[2 * kk] = l01; gl[2 * kk + 1] = l23;
            }
        }
        cs += __shfl_xor_sync(0xffffffffu, cs, 1);
        cd += __shfl_xor_sync(0xffffffffu, cd, 1);
        if (act && half == 0) {
            g_c_s[n] = cs + g_ec[0];
            g_c_d[n] = cd + g_ec[1];
        }
    }
    __syncthreads();

    int ty = tid >> 3, tx = tid & 7;
    int row0 = ty << 2, col0 = tx << 3;
#pragma unroll
    for (int pass = 0; pass < 2; pass++) {
        const float* M = pass ? sMd : sMs;
        const float* dv = pass ? sdd : sds;
        float* outp = pass ? g_qh_d : g_qh_s;
        ull acc[16];
        {
            const ull* dp = (const ull*)(dv + col0);
            ull w0 = dp[0], w1 = dp[1], w2 = dp[2], w3 = dp[3];
#pragma unroll
            for (int i = 0; i < 4; i++) {
                acc[i * 4] = w0; acc[i * 4 + 1] = w1; acc[i * 4 + 2] = w2; acc[i * 4 + 3] = w3;
            }
        }
#pragma unroll 4
        for (int k = 0; k < 64; k++) {
            const ull* axp = (const ull*)(XsT + k * XS + row0);
            float2 f01 = unpk(axp[0]), f23 = unpk(axp[1]);
            float aa[4] = {f01.x, f01.y, f23.x, f23.y};
            const ull* bp = (const ull*)(M + k * WS + col0);
            ull w0 = bp[0], w1 = bp[1], w2 = bp[2], w3 = bp[3];
#pragma unroll
            for (int i = 0; i < 4; i++) {
                ull ad = dup2(aa[i]);
                ffma2(acc[i * 4],     ad, w0);
                ffma2(acc[i * 4 + 1], ad, w1);
                ffma2(acc[i * 4 + 2], ad, w2);
                ffma2(acc[i * 4 + 3], ad, w3);
            }
        }
#pragma unroll
        for (int i = 0; i < 4; i++) {
            int nl = row0 + i;
            if (nl < cnt) {
                float* dp = outp + (size_t)(n0 + nl) * 64 + col0;
                float2 v0 = unpk(acc[i * 4]),     v1 = unpk(acc[i * 4 + 1]);
                float2 v2 = unpk(acc[i * 4 + 2]), v3 = unpk(acc[i * 4 + 3]);
                *(float4*)dp       = make_float4(v0.x, v0.y, v1.x, v1.y);
                *(float4*)(dp + 4) = make_float4(v2.x, v2.y, v3.x, v3.y);
            }
        }
    }
}

// ---------------- kernel 2: tensor-core edge kernel (persistent) -------------
#define OFF_AHI 0
#define OFF_ALO 16384
#define OFF_W1H 32768
#define OFF_W1L 40960
#define OFF_W2H 49152
#define OFF_W2L 57344
#define OFF_SBT 65536
#define OFF_SBV 65792
#define OFF_WTL 66048
#define OFF_SDV 66304
#define OFF_TMP 66560
#define OFF_MBR 66568
#define EDGE_SMEM_BYTES (1024 + 66576 + 48)

__global__ __launch_bounds__(128)
void edge_tc_kernel(
    const int* __restrict__ ei, const float* __restrict__ etime,
    const float* __restrict__ Wt,
    const float* __restrict__ bt,
    const float* __restrict__ Wvs, const float* __restrict__ bvs,
    const float* __restrict__ Wvd, const float* __restrict__ bvd,
    int E)
{
    int tid = threadIdx.x;
    int bid = blockIdx.x;

    int cs = g_cnt[0], cd = g_cnt[1];
    int ts = (cs + 127) >> 7;
    int td = (cd + 127) >> 7;
    int total = ts + td;

#if TC_OK
    extern __shared__ char dsm_raw[];
    uint32_t raw_u = smem_u32(dsm_raw);
    uint32_t base_u = (raw_u + 1023u) & ~1023u;
    char* sb = dsm_raw + (base_u - raw_u);
    int wid = tid >> 5;

    if (wid == 0) {
        TC_ALLOC(base_u + OFF_TMP, 128);
        TC_RELINQ();
    }
    if (tid == 0) MBAR_INIT(base_u + OFF_MBR, 1);

    float* sbt  = (float*)(sb + OFF_SBT);
    float* sbv  = (float*)(sb + OFF_SBV);
    float* wtl  = (float*)(sb + OFF_WTL);
    float* sdiv = (float*)(sb + OFF_SDV);

    // ---- one-time: W1 (= Wt, same-independent), bt, wtl, sdiv ----
    for (int i = tid; i < 2048; i += 128) {
        int m = i >> 5, k2 = (i & 31) * 2;
        uint32_t byte = (uint32_t)(m * 128 + k2 * 2);
        uint32_t swo = SW128(byte);
        uint32_t hp, lp;
        split2(Wt[m * 65 + k2], Wt[m * 65 + k2 + 1], hp, lp);
        *(uint32_t*)(sb + OFF_W1H + swo) = hp;
        *(uint32_t*)(sb + OFF_W1L + swo) = lp;
    }
    if (tid < 64) {
        sbt[tid] = bt[tid];
        wtl[tid] = Wt[tid * 65 + 64];
        sdiv[tid] = powf(10000.0f, -(float)(2 * (tid >> 1)) / 64.0f);
    }

    int cur_same = -1;
    int ph = 0;
    for (int ti = bid; ti < total; ti += gridDim.x) {
        int same, off, cnt;
        const int* list;
        if (ti < ts) {
            list = g_perm_s; off = ti << 7; cnt = min(128, cs - off); same = 1;
        } else {
            list = g_perm_d; off = (ti - ts) << 7; cnt = min(128, cd - off); same = 0;
        }
        const float* Wv = same ? Wvs : Wvd;
        const float* bv = same ? bvs : bvd;
        const float* qh = same ? g_qh_s : g_qh_d;
        const float* cv = same ? g_c_s  : g_c_d;

        __syncthreads();   // prev tile fully done with smem

        if (same != cur_same) {
            for (int i = tid; i < 2048; i += 128) {
                int m = i >> 5, k2 = (i & 31) * 2;
                uint32_t byte = (uint32_t)(m * 128 + k2 * 2);
                uint32_t swo = SW128(byte);
                uint32_t hp, lp;
                split2(Wv[m * 64 + k2], Wv[m * 64 + k2 + 1], hp, lp);
                *(uint32_t*)(sb + OFF_W2H + swo) = hp;
                *(uint32_t*)(sb + OFF_W2L + swo) = lp;
            }
            if (tid < 64) sbv[tid] = bv[tid];
            cur_same = same;
        }

        // ---- gather 128 edges: packed bf16 hi/lo rows (FULL 128B row) ----
        int e = tid;
        bool act = e < cnt;
        int src = 0, dn = 0; float t = 0.0f;
        if (act) {
            int pe = list[off + e];
            src = ei[pe]; dn = ei[E + pe]; t = etime[pe];
        }
        {
            const uint4* xh = (const uint4*)(g_xnh + (size_t)src * 32);
            const uint4* xl = (const uint4*)(g_xnl + (size_t)src * 32);
#pragma unroll
            for (int kk = 0; kk < 8; kk++) {
                uint4 h = act ? xh[kk] : make_uint4(0, 0, 0, 0);
                uint4 l = act ? xl[kk] : make_uint4(0, 0, 0, 0);
                uint32_t byte = (uint32_t)(e * 128 + kk * 16);
                uint32_t swo = SW128(byte);
                *(uint4*)(sb + OFF_AHI + swo) = h;
                *(uint4*)(sb + OFF_ALO + swo) = l;
            }
        }
        __syncthreads();

        uint32_t tmem;
        asm volatile("ld.shared.b32 %0, [%1];" : "=r"(tmem) : "r"(base_u + OFF_TMP));

        // ---- MMA1 ----
        if (tid == 0) {
            FENCE_PROXY();
            uint64_t aH = mkdesc(base_u + OFF_AHI), aL = mkdesc(base_u + OFF_ALO);
            uint64_t bH = mkdesc(base_u + OFF_W1H), bL = mkdesc(base_u + OFF_W1L);
#pragma unroll
            for (int kc = 0; kc < 4; kc++) {
                mma_f16_ss(tmem, aH + kc * 2, bH + kc * 2, kc > 0 ? 1u : 0u);
                mma_f16_ss(tmem, aH + kc * 2, bL + kc * 2, 1u);
                mma_f16_ss(tmem, aL + kc * 2, bH + kc * 2, 1u);
            }
            TC_COMMIT(base_u + OFF_MBR);
        }

        // ---- prefetch q-row while MMA1 runs ----
        float4 qv[16];
        {
            const float4* qp = (const float4*)(qh + (size_t)dn * 64);
#pragma unroll
            for (int i = 0; i < 16; i++) qv[i] = qp[i];
        }
        float cvd = cv[dn];

        mbar_wait(base_u + OFF_MBR, ph); ph ^= 1;
        TC_FENCE_AFTER();

        // ---- epilogue 1 ----
        uint32_t d1[64];
        TC_LD_X32(d1, tmem);
        TC_LD_X32(d1 + 32, tmem + 32);
        TC_WAIT_LD();

        float ex = 0.0f;
        {
            float att = 0.0f;
            float t200 = t * 200.0f;
            uint32_t hbuf[4], lbuf[4];
#pragma unroll
            for (int m0 = 0; m0 < 64; m0 += 4) {
                float4 q4 = qv[m0 >> 2];
                float xt4[4];
#pragma unroll
                for (int j = 0; j < 4; j += 2) {
                    int m = m0 + j;
                    float arg = t200 * sdiv[m];
                    float sn = __sinf(arg), cc = __cosf(arg);
                    float xe = __uint_as_float(d1[m])     + sbt[m]     + t * wtl[m];
                    float xo = __uint_as_float(d1[m + 1]) + sbt[m + 1] + t * wtl[m + 1];
                    xt4[j]     = gelu_erf(xe) + sn;
                    xt4[j + 1] = gelu_erf(xo) + cc;
                }
                att += xt4[0] * q4.x + xt4[1] * q4.y + xt4[2] * q4.z + xt4[3] * q4.w;
                int half8 = (m0 & 4) ? 2 : 0;
                split2(xt4[0], xt4[1], hbuf[half8],     lbuf[half8]);
                split2(xt4[2], xt4[3], hbuf[half8 + 1], lbuf[half8 + 1]);
                if (m0 & 4) {
                    uint32_t byte = (uint32_t)(e * 128 + (m0 - 4) * 2);
                    uint32_t swo = SW128(byte);
                    *(uint4*)(sb + OFF_AHI + swo) = make_uint4(hbuf[0], hbuf[1], hbuf[2], hbuf[3]);
                    *(uint4*)(sb + OFF_ALO + swo) = make_uint4(lbuf[0], lbuf[1], lbuf[2], lbuf[3]);
                }
            }
            if (act) {
                ex = __expf((att + cvd) * 0.125f);
                atomicAdd(&g_den[dn], ex);
            }
        }
        __syncthreads();

        // ---- MMA2 ----
        if (tid == 0) {
            FENCE_PROXY();
            uint64_t aH = mkdesc(base_u + OFF_AHI), aL = mkdesc(base_u + OFF_ALO);
            uint64_t bH = mkdesc(base_u + OFF_W2H), bL = mkdesc(base_u + OFF_W2L);
#pragma unroll
            for (int kc = 0; kc < 4; kc++) {
                mma_f16_ss(tmem + 64, aH + kc * 2, bH + kc * 2, kc > 0 ? 1u : 0u);
                mma_f16_ss(tmem + 64, aH + kc * 2, bL + kc * 2, 1u);
                mma_f16_ss(tmem + 64, aL + kc * 2, bH + kc * 2, 1u);
            }
            TC_COMMIT(base_u + OFF_MBR);
        }

        mbar_wait(base_u + OFF_MBR, ph); ph ^= 1;
        TC_FENCE_AFTER();

        uint32_t d2[64];
        TC_LD_X32(d2, tmem + 64);
        TC_LD_X32(d2 + 32, tmem + 96);
        TC_WAIT_LD();

        if (act) {
            float* dp = g_aggr + (size_t)dn * 64;
#pragma unroll
            for (int m0 = 0; m0 < 64; m0 += 4) {
                float v0 = (__uint_as_float(d2[m0])     + sbv[m0])     * ex;
                float v1 = (__uint_as_float(d2[m0 + 1]) + sbv[m0 + 1]) * ex;
                float v2 = (__uint_as_float(d2[m0 + 2]) + sbv[m0 + 2]) * ex;
                float v3 = (__uint_as_float(d2[m0 + 3]) + sbv[m0 + 3]) * ex;
                asm volatile("red.global.add.v4.f32 [%0], {%1, %2, %3, %4};"
                             :: "l"(dp + m0), "f"(v0), "f"(v1), "f"(v2), "f"(v3) : "memory");
            }
        }
    }

    __syncthreads();
    if (tid == 0) MBAR_INVAL(base_u + OFF_MBR);
    __syncthreads();
    {
        uint32_t tmem;
        asm volatile("ld.shared.b32 %0, [%1];" : "=r"(tmem) : "r"(base_u + OFF_TMP));
        if (wid == 0) TC_DEALLOC(tmem, 128);
    }

#else   // ---------------- fp32 fallback (non-'a' PTX pass only) -------------
    for (int ti = bid; ti < total; ti += gridDim.x) {
        int same, off, cnt;
        const int* list;
        if (ti < ts) { list = g_perm_s; off = ti << 7; cnt = min(128, cs - off); same = 1; }
        else         { list = g_perm_d; off = (ti - ts) << 7; cnt = min(128, cd - off); same = 0; }
        const float* Wv = same ? Wvs : Wvd;
        const float* bv = same ? bvs : bvd;
        const float* qh = same ? g_qh_s : g_qh_d;
        const float* cv = same ? g_c_s  : g_c_d;
        int e = tid;
        if (e < cnt) {
            int pe = list[off + e];
            int src = ei[pe], dn = ei[E + pe];
            float t = etime[pe];
            float t200 = t * 200.0f;
            float xrow[64];
            for (int k2 = 0; k2 < 32; k2++) {
                uint32_t h = g_xnh[(size_t)src * 32 + k2];
                uint32_t l = g_xnl[(size_t)src * 32 + k2];
                xrow[2 * k2]     = __uint_as_float(h << 16) + __uint_as_float(l << 16);
                xrow[2 * k2 + 1] = __uint_as_float(h & 0xffff0000u) + __uint_as_float(l & 0xffff0000u);
            }
            float xt[64];
            float att = 0.0f;
            for (int m = 0; m < 64; m++) {
                float a = bt[m] + t * Wt[m * 65 + 64];
                for (int k = 0; k < 64; k++) a += xrow[k] * Wt[m * 65 + k];
                float dv = powf(10000.0f, -(float)(2 * (m / 2)) / 64.0f);
                float te = (m & 1) ? cosf(t200 * dv) : sinf(t200 * dv);
                xt[m] = gelu_erf(a) + te;
                att += xt[m] * qh[(size_t)dn * 64 + m];
            }
            float ex = expf((att + cv[dn]) * 0.125f);
            atomicAdd(&g_den[dn], ex);
            for (int m = 0; m < 64; m++) {
                float v = bv[m];
                for (int k = 0; k < 64; k++) v += xt[k] * Wv[m * 64 + k];
                atomicAdd(&g_aggr[(size_t)dn * 64 + m], ex * v);
            }
        }
    }
#endif
}

// ---------------- kernel 5: epilogue (normalize by den) ----------------------
__global__ void final_kernel(const float* __restrict__ x, float* __restrict__ out, int N) {
    int i = blockIdx.x * blockDim.x + threadIdx.x;
    if (i < N * D) {
        float den = g_den[i >> 6];
        out[i] = x[i] + gelu_erf(g_aggr[i] / (den + 1e-16f));
    }
}

// ---------------- launch ------------------------------------------------------
extern "C" void kernel_launch(void* const* d_in, const int* in_sizes, int n_in,
                              void* d_out, int out_size) {
    const float* x     = (const float*)d_in[0];
    const int*   ei    = (const int*)  d_in[1];
    const float* etime = (const float*)d_in[2];
    const float* esame = (const float*)d_in[4];
    const float* lng   = (const float*)d_in[5];
    const float* lnb   = (const float*)d_in[6];
    const float* Wt    = (const float*)d_in[7];
    const float* bt    = (const float*)d_in[8];
    const float* Wq    = (const float*)d_in[9];
    const float* bq    = (const float*)d_in[10];
    const float* Wks   = (const float*)d_in[11];
    const float* bks   = (const float*)d_in[12];
    const float* Wkd   = (const float*)d_in[13];
    const float* bkd   = (const float*)d_in[14];
    const float* Wvs   = (const float*)d_in[15];
    const float* bvs   = (const float*)d_in[16];
    const float* Wvd   = (const float*)d_in[17];
    const float* bvd   = (const float*)d_in[18];
    float* out = (float*)d_out;

    int N = in_sizes[0] / D;
    int E = in_sizes[2];
    if (N > MAXN) N = MAXN;
    if (E > MAXE) E = MAXE;

    const int node_smem = NODE_SMEM_FLOATS * (int)sizeof(float);
    cudaFuncSetAttribute(node_kernel, cudaFuncAttributeMaxDynamicSharedMemorySize, node_smem);
    cudaFuncSetAttribute(edge_tc_kernel, cudaFuncAttributeMaxDynamicSharedMemorySize,
                         EDGE_SMEM_BYTES);

    // persistent: 2 CTAs/SM max (smem bound)
    int max_tiles = (E + 127) / 128 + 2;
    int edge_grid = max_tiles < 296 ? max_tiles : 296;

    init_kernel<<<(N * D + 255) / 256, 256>>>(N);
    partition_kernel<<<(E + 255) / 256, 256>>>(esame, E);
    fold_kernel<<<2, 256>>>(Wq, bq, Wks, bks, Wkd, bkd);
    node_kernel<<<(N + 127) / 128, 256, node_smem>>>(x, lng, lnb, N);
    edge_tc_kernel<<<edge_grid, 128, EDGE_SMEM_BYTES>>>(
        ei, etime, Wt, bt, Wvs, bvs, Wvd, bvd, E);
    final_kernel<<<(N * D + 255) / 256, 256>>>(x, out, N);
}

// round 13
// speedup vs baseline: 1.0703x; 1.0703x over previous
#include <cuda_runtime.h>
#include <cuda_bf16.h>
#include <math.h>
#include <stdint.h>

#define MAXN 50000
#define MAXE 800000
#define D 64
#define XS 130
#define WS 68

// tcgen05 is arch-SPECIFIC: only emit it in the sm_103a/'a'-target device pass.
#if !defined(__CUDA_ARCH__) || defined(__CUDA_ARCH_FEAT_SM103_ALL) || \
    defined(__CUDA_ARCH_FEAT_SM100_ALL) || defined(__CUDA_ARCH_SPECIFIC__) || \
    defined(__CUDA_ARCH_FAMILY_SPECIFIC__)
#define TC_OK 1
#else
#define TC_OK 0
#endif

typedef unsigned long long ull;

// ---------------- scratch ---------------------------------------------------
__device__ uint32_t g_xnh[MAXN * 32];
__device__ uint32_t g_xnl[MAXN * 32];
__device__ float g_qh_s[MAXN * D];
__device__ float g_qh_d[MAXN * D];
__device__ float g_c_s [MAXN];
__device__ float g_c_d [MAXN];
__device__ float g_den [MAXN];        // zeroed in prep_kernel each run
__device__ float g_aggr[MAXN * D];    // zeroed in prep_kernel each run
__device__ int   g_perm_s[MAXE];
__device__ int   g_perm_d[MAXE];
__device__ int   g_cnt[2];            // static zero; reset by final_kernel
__device__ float g_MsT[4096];
__device__ float g_MdT[4096];
__device__ float g_ds[64], g_dd[64];
__device__ float g_us[64], g_ud[64];
__device__ float g_ec[2];

__device__ __forceinline__ float gelu_erf(float x) {
    return 0.5f * x * (1.0f + erff(x * 0.70710678118654752440f));
}
__device__ __forceinline__ ull dup2(float x) {
    ull r; asm("mov.b64 %0, {%1, %1};" : "=l"(r) : "f"(x)); return r;
}
__device__ __forceinline__ void ffma2(ull& d, ull a, ull b) {
    asm("fma.rn.f32x2 %0, %1, %2, %0;" : "+l"(d) : "l"(a), "l"(b));
}
__device__ __forceinline__ float2 unpk(ull v) {
    float2 f; asm("mov.b64 {%0, %1}, %2;" : "=f"(f.x), "=f"(f.y) : "l"(v)); return f;
}

// ---------------- bf16 pack helpers ------------------------------------------
__device__ __forceinline__ uint32_t packbf(float x0, float x1) {
    uint32_t r;
    asm("cvt.rn.bf16x2.f32 %0, %2, %1;" : "=r"(r) : "f"(x0), "f"(x1));
    return r;
}
__device__ __forceinline__ void split2(float x0, float x1, uint32_t& hp, uint32_t& lp) {
    hp = packbf(x0, x1);
    float h0 = __uint_as_float(hp << 16);
    float h1 = __uint_as_float(hp & 0xffff0000u);
    lp = packbf(x0 - h0, x1 - h1);
}

__device__ __forceinline__ uint32_t smem_u32(const void* p) {
    uint32_t a;
    asm("{ .reg .u64 t; cvta.to.shared.u64 t, %1; cvt.u32.u64 %0, t; }"
        : "=r"(a) : "l"(p));
    return a;
}
#define SW128(o) ((o) ^ (((o) >> 3) & 0x70))

__device__ __forceinline__ uint64_t mkdesc(uint32_t addr) {
    const uint64_t base = (2ull << 61) | (1ull << 46) | (64ull << 32) | (1ull << 16);
    return base | ((addr >> 4) & 0x3FFF);
}

// idesc kind::f16, bf16 x bf16 -> f32, M=128, N=64
#define MMA_IDESC 0x08100490u

#if TC_OK
__device__ __forceinline__ void mma_f16_ss(uint32_t d_tmem, uint64_t a_desc,
                                           uint64_t b_desc, uint32_t en) {
    asm volatile(
        "{\n\t"
        ".reg .pred p;\n\t"
        "setp.ne.u32 p, %5, 0;\n\t"
        "tcgen05.mma.cta_group::1.kind::f16 [%0], %1, %2, %3, {%4, %4, %4, %4}, p;\n\t"
        "}"
        :: "r"(d_tmem), "l"(a_desc), "l"(b_desc), "r"(MMA_IDESC), "r"(0u), "r"(en)
        : "memory");
}

#define TC_ALLOC(smem_addr, n) \
    asm volatile("tcgen05.alloc.cta_group::1.sync.aligned.shared::cta.b32 [%0], %1;" \
                 :: "r"(smem_addr), "r"((uint32_t)(n)) : "memory")
#define TC_RELINQ() \
    asm volatile("tcgen05.relinquish_alloc_permit.cta_group::1.sync.aligned;")
#define TC_DEALLOC(tmem, n) \
    asm volatile("tcgen05.dealloc.cta_group::1.sync.aligned.b32 %0, %1;" \
                 :: "r"(tmem), "r"((uint32_t)(n)))
#define TC_COMMIT(mbar) \
    asm volatile("tcgen05.commit.cta_group::1.mbarrier::arrive::one.shared::cluster.b64 [%0];" \
                 :: "r"(mbar) : "memory")
#define TC_FENCE_AFTER() \
    asm volatile("tcgen05.fence::after_thread_sync;" ::: "memory")
#define TC_WAIT_LD() \
    asm volatile("tcgen05.wait::ld.sync.aligned;" ::: "memory")
#define FENCE_PROXY() \
    asm volatile("fence.proxy.async.shared::cta;" ::: "memory")
#define MBAR_INIT(mbar, n) \
    asm volatile("mbarrier.init.shared.b64 [%0], %1;" :: "r"(mbar), "r"((uint32_t)(n)) : "memory")
#define MBAR_INVAL(mbar) \
    asm volatile("mbarrier.inval.shared.b64 [%0];" :: "r"(mbar) : "memory")

__device__ __forceinline__ void mbar_wait(uint32_t mbar, uint32_t parity) {
    asm volatile(
        "{\n\t"
        ".reg .pred P;\n\t"
        "WLOOP%=:\n\t"
        "mbarrier.try_wait.parity.acquire.cta.shared::cta.b64 P, [%0], %1, 0x989680;\n\t"
        "@P bra.uni WDONE%=;\n\t"
        "bra.uni WLOOP%=;\n\t"
        "WDONE%=:\n\t"
        "}"
        :: "r"(mbar), "r"(parity) : "memory");
}

#define TC_LD_X32(r, tmem_addr) \
    asm volatile( \
        "tcgen05.ld.sync.aligned.32x32b.x32.b32 " \
        "{%0, %1, %2, %3, %4, %5, %6, %7, " \
        " %8, %9, %10, %11, %12, %13, %14, %15, " \
        " %16, %17, %18, %19, %20, %21, %22, %23, " \
        " %24, %25, %26, %27, %28, %29, %30, %31}, [%32];" \
        : "=r"((r)[0]),  "=r"((r)[1]),  "=r"((r)[2]),  "=r"((r)[3]), \
          "=r"((r)[4]),  "=r"((r)[5]),  "=r"((r)[6]),  "=r"((r)[7]), \
          "=r"((r)[8]),  "=r"((r)[9]),  "=r"((r)[10]), "=r"((r)[11]), \
          "=r"((r)[12]), "=r"((r)[13]), "=r"((r)[14]), "=r"((r)[15]), \
          "=r"((r)[16]), "=r"((r)[17]), "=r"((r)[18]), "=r"((r)[19]), \
          "=r"((r)[20]), "=r"((r)[21]), "=r"((r)[22]), "=r"((r)[23]), \
          "=r"((r)[24]), "=r"((r)[25]), "=r"((r)[26]), "=r"((r)[27]), \
          "=r"((r)[28]), "=r"((r)[29]), "=r"((r)[30]), "=r"((r)[31]) \
        : "r"(tmem_addr))
#endif  // TC_OK

// ---------------- kernel A: fold (blocks 0,1) + partition & zero (blocks>=2) --
__global__ __launch_bounds__(256) void prep_kernel(
    const float* __restrict__ esame,
    const float* __restrict__ Wq, const float* __restrict__ bq,
    const float* __restrict__ Wks, const float* __restrict__ bks,
    const float* __restrict__ Wkd, const float* __restrict__ bkd,
    int E, int N)
{
    __shared__ float sWq[4096], sWk[4096], sbq[64], sbk[64];
    int tid = threadIdx.x;
    int bidx = blockIdx.x;

    if (bidx < 2) {
        // ---- fold: M = Wk^T Wq, d = Wk^T bq, u = bk^T Wq, ec = bk.bq ----
        int b = bidx;
        const float* Wk = b ? Wkd : Wks;
        const float* bk = b ? bkd : bks;
        float* MT   = b ? g_MdT : g_MsT;
        float* dvec = b ? g_dd : g_ds;
        float* uvec = b ? g_ud : g_us;

        for (int i = tid; i < 4096; i += 256) { sWq[i] = Wq[i]; sWk[i] = Wk[i]; }
        if (tid < 64) { sbq[tid] = bq[tid]; sbk[tid] = bk[tid]; }
        __syncthreads();
#pragma unroll
        for (int ii = 0; ii < 16; ii++) {
            int o = tid + ii * 256;
            int j = o >> 6, c = o & 63;
            float s = 0.0f;
#pragma unroll 8
            for (int m = 0; m < 64; m++) s += sWk[m * 64 + c] * sWq[m * 64 + j];
            MT[o] = s;
        }
        if (tid < 64) {
            float sd = 0.0f, su = 0.0f;
#pragma unroll 8
            for (int m = 0; m < 64; m++) {
                sd += sWk[m * 64 + tid] * sbq[m];
                su += sbk[m] * sWq[m * 64 + tid];
            }
            dvec[tid] = sd; uvec[tid] = su;
        }
        if (tid == 0) {
            float s = 0.0f;
            for (int m = 0; m < 64; m++) s += sbk[m] * sbq[m];
            g_ec[b] = s;
        }
    } else {
        int gi = (bidx - 2) * 256 + tid;   // 0 .. >=E-1
        // ---- zero g_aggr (N*D = 4*E-ish; strided float4) and g_den ----
        {
            float4 z = make_float4(0.f, 0.f, 0.f, 0.f);
            int total4 = N * D / 4;        // N*D divisible by 4
            int nthr = (gridDim.x - 2) * 256;
            for (int p = gi; p < total4; p += nthr)
                *(((float4*)g_aggr) + p) = z;
            if (gi < N) g_den[gi] = 0.0f;
        }
        // ---- partition (warp-aggregated atomics) ----
        int e = gi;
        int lane = tid & 31;
        bool act = e < E;
        float es = act ? esame[e] : 0.0f;
        bool s = act && (es >= 0.5f);
        bool d = act && (es < 0.5f);
        unsigned ms = __ballot_sync(0xffffffffu, s);
        unsigned md = __ballot_sync(0xffffffffu, d);
        int bs = 0, bd = 0;
        if (lane == 0) {
            if (ms) bs = atomicAdd(&g_cnt[0], __popc(ms));
            if (md) bd = atomicAdd(&g_cnt[1], __popc(md));
        }
        bs = __shfl_sync(0xffffffffu, bs, 0);
        bd = __shfl_sync(0xffffffffu, bd, 0);
        unsigned lower = (1u << lane) - 1u;
        if (s) g_perm_s[bs + __popc(ms & lower)] = e;
        if (d) g_perm_d[bd + __popc(md & lower)] = e;
    }
}

// ---------------- kernel 1: layernorm + qh_s/qh_d/c + packed xn ---------------
#define NODE_SMEM_FLOATS (64*XS + 2*64*WS + 8*64)
__global__ __launch_bounds__(256, 2) void node_kernel(
    const float* __restrict__ x, const float* __restrict__ gamma,
    const float* __restrict__ beta, int N)
{
    extern __shared__ float ns[];
    float* XsT = ns;
    float* sMs = XsT + 64 * XS;
    float* sMd = sMs + 64 * WS;
    float* sg  = sMd + 64 * WS;
    float* sb  = sg + 64;
    float* sus = sb + 64;
    float* sud = sus + 64;
    float* sds = sud + 64;
    float* sdd = sds + 64;

    int tid = threadIdx.x;
    for (int i = tid; i < 4096; i += 256) {
        int j = i >> 6, c = i & 63;
        sMs[j * WS + c] = g_MsT[i];
        sMd[j * WS + c] = g_MdT[i];
    }
    if (tid < 64) {
        sg[tid] = gamma[tid]; sb[tid] = beta[tid];
        sus[tid] = g_us[tid]; sud[tid] = g_ud[tid];
        sds[tid] = g_ds[tid]; sdd[tid] = g_dd[tid];
    }
    __syncthreads();

    int n0 = blockIdx.x * 128;
    int cnt = min(128, N - n0);

    {
        int nl = tid >> 1, half = tid & 1;
        bool act = nl < cnt;
        int n = n0 + nl;
        float4 xv[8];
        float s = 0.0f, t = 0.0f;
        if (act) {
            const float4* xr = (const float4*)(x + (size_t)n * 64) + half * 8;
#pragma unroll
            for (int kk = 0; kk < 8; kk++) {
                xv[kk] = xr[kk];
                s += xv[kk].x + xv[kk].y + xv[kk].z + xv[kk].w;
                t += xv[kk].x * xv[kk].x + xv[kk].y * xv[kk].y
                   + xv[kk].z * xv[kk].z + xv[kk].w * xv[kk].w;
            }
        }
        s += __shfl_xor_sync(0xffffffffu, s, 1);
        t += __shfl_xor_sync(0xffffffffu, t, 1);
        float mu = s * (1.0f / 64.0f);
        float var = t * (1.0f / 64.0f) - mu * mu;
        float inv = rsqrtf(var + 1e-5f);
        float cs = 0.0f, cd = 0.0f;
        if (act) {
            uint32_t* gh = g_xnh + (size_t)n * 32 + half * 16;
            uint32_t* gl = g_xnl + (size_t)n * 32 + half * 16;
#pragma unroll
            for (int kk = 0; kk < 8; kk++) {
                int c0 = half * 32 + 4 * kk;
                float v[4] = {xv[kk].x, xv[kk].y, xv[kk].z, xv[kk].w};
                float xn4[4];
#pragma unroll
                for (int p = 0; p < 4; p++) {
                    int c = c0 + p;
                    float xn = (v[p] - mu) * inv * sg[c] + sb[c];
                    xn4[p] = xn;
                    XsT[c * XS + nl] = xn;
                    cs += xn * sus[c];
                    cd += xn * sud[c];
                }
                uint32_t h01, l01, h23, l23;
                split2(xn4[0], xn4[1], h01, l01);
                split2(xn4[2], xn4[3], h23, l23);
                gh[2 * kk] = h01; gh[2 * kk + 1] = h23;
                gl[2 * kk] = l01; gl[2 * kk + 1] = l23;
            }
        }
        cs += __shfl_xor_sync(0xffffffffu, cs, 1);
        cd += __shfl_xor_sync(0xffffffffu, cd, 1);
        if (act && half == 0) {
            g_c_s[n] = cs + g_ec[0];
            g_c_d[n] = cd + g_ec[1];
        }
    }
    __syncthreads();

    int ty = tid >> 3, tx = tid & 7;
    int row0 = ty << 2, col0 = tx << 3;
#pragma unroll
    for (int pass = 0; pass < 2; pass++) {
        const float* M = pass ? sMd : sMs;
        const float* dv = pass ? sdd : sds;
        float* outp = pass ? g_qh_d : g_qh_s;
        ull acc[16];
        {
            const ull* dp = (const ull*)(dv + col0);
            ull w0 = dp[0], w1 = dp[1], w2 = dp[2], w3 = dp[3];
#pragma unroll
            for (int i = 0; i < 4; i++) {
                acc[i * 4] = w0; acc[i * 4 + 1] = w1; acc[i * 4 + 2] = w2; acc[i * 4 + 3] = w3;
            }
        }
#pragma unroll 4
        for (int k = 0; k < 64; k++) {
            const ull* axp = (const ull*)(XsT + k * XS + row0);
            float2 f01 = unpk(axp[0]), f23 = unpk(axp[1]);
            float aa[4] = {f01.x, f01.y, f23.x, f23.y};
            const ull* bp = (const ull*)(M + k * WS + col0);
            ull w0 = bp[0], w1 = bp[1], w2 = bp[2], w3 = bp[3];
#pragma unroll
            for (int i = 0; i < 4; i++) {
                ull ad = dup2(aa[i]);
                ffma2(acc[i * 4],     ad, w0);
                ffma2(acc[i * 4 + 1], ad, w1);
                ffma2(acc[i * 4 + 2], ad, w2);
                ffma2(acc[i * 4 + 3], ad, w3);
            }
        }
#pragma unroll
        for (int i = 0; i < 4; i++) {
            int nl = row0 + i;
            if (nl < cnt) {
                float* dp = outp + (size_t)(n0 + nl) * 64 + col0;
                float2 v0 = unpk(acc[i * 4]),     v1 = unpk(acc[i * 4 + 1]);
                float2 v2 = unpk(acc[i * 4 + 2]), v3 = unpk(acc[i * 4 + 3]);
                *(float4*)dp       = make_float4(v0.x, v0.y, v1.x, v1.y);
                *(float4*)(dp + 4) = make_float4(v2.x, v2.y, v3.x, v3.y);
            }
        }
    }
}

// ---------------- kernel 2: tensor-core edge kernel (persistent) -------------
#define OFF_AHI 0
#define OFF_ALO 16384
#define OFF_W1H 32768
#define OFF_W1L 40960
#define OFF_W2H 49152
#define OFF_W2L 57344
#define OFF_SBT 65536
#define OFF_SBV 65792
#define OFF_WTL 66048
#define OFF_SDV 66304
#define OFF_TMP 66560
#define OFF_MBR 66568
#define EDGE_SMEM_BYTES (1024 + 66576 + 48)

__global__ __launch_bounds__(128)
void edge_tc_kernel(
    const int* __restrict__ ei, const float* __restrict__ etime,
    const float* __restrict__ Wt,
    const float* __restrict__ bt,
    const float* __restrict__ Wvs, const float* __restrict__ bvs,
    const float* __restrict__ Wvd, const float* __restrict__ bvd,
    int E)
{
    int tid = threadIdx.x;
    int bid = blockIdx.x;

    int cs = g_cnt[0], cd = g_cnt[1];
    int ts = (cs + 127) >> 7;
    int td = (cd + 127) >> 7;
    int total = ts + td;

#if TC_OK
    extern __shared__ char dsm_raw[];
    uint32_t raw_u = smem_u32(dsm_raw);
    uint32_t base_u = (raw_u + 1023u) & ~1023u;
    char* sb = dsm_raw + (base_u - raw_u);
    int wid = tid >> 5;

    if (wid == 0) {
        TC_ALLOC(base_u + OFF_TMP, 128);
        TC_RELINQ();
    }
    if (tid == 0) MBAR_INIT(base_u + OFF_MBR, 1);

    float* sbt  = (float*)(sb + OFF_SBT);
    float* sbv  = (float*)(sb + OFF_SBV);
    float* wtl  = (float*)(sb + OFF_WTL);
    float* sdiv = (float*)(sb + OFF_SDV);

    // ---- one-time: W1 (= Wt, same-independent), bt, wtl, sdiv ----
    for (int i = tid; i < 2048; i += 128) {
        int m = i >> 5, k2 = (i & 31) * 2;
        uint32_t byte = (uint32_t)(m * 128 + k2 * 2);
        uint32_t swo = SW128(byte);
        uint32_t hp, lp;
        split2(Wt[m * 65 + k2], Wt[m * 65 + k2 + 1], hp, lp);
        *(uint32_t*)(sb + OFF_W1H + swo) = hp;
        *(uint32_t*)(sb + OFF_W1L + swo) = lp;
    }
    if (tid < 64) {
        sbt[tid] = bt[tid];
        wtl[tid] = Wt[tid * 65 + 64];
        sdiv[tid] = powf(10000.0f, -(float)(2 * (tid >> 1)) / 64.0f);
    }

    int cur_same = -1;
    int ph = 0;
    for (int ti = bid; ti < total; ti += gridDim.x) {
        int same, off, cnt;
        const int* list;
        if (ti < ts) {
            list = g_perm_s; off = ti << 7; cnt = min(128, cs - off); same = 1;
        } else {
            list = g_perm_d; off = (ti - ts) << 7; cnt = min(128, cd - off); same = 0;
        }
        const float* Wv = same ? Wvs : Wvd;
        const float* bv = same ? bvs : bvd;
        const float* qh = same ? g_qh_s : g_qh_d;
        const float* cv = same ? g_c_s  : g_c_d;

        __syncthreads();   // prev tile fully done with smem

        if (same != cur_same) {
            for (int i = tid; i < 2048; i += 128) {
                int m = i >> 5, k2 = (i & 31) * 2;
                uint32_t byte = (uint32_t)(m * 128 + k2 * 2);
                uint32_t swo = SW128(byte);
                uint32_t hp, lp;
                split2(Wv[m * 64 + k2], Wv[m * 64 + k2 + 1], hp, lp);
                *(uint32_t*)(sb + OFF_W2H + swo) = hp;
                *(uint32_t*)(sb + OFF_W2L + swo) = lp;
            }
            if (tid < 64) sbv[tid] = bv[tid];
            cur_same = same;
        }

        // ---- gather 128 edges: packed bf16 hi/lo rows (full 128B row) ----
        int e = tid;
        bool act = e < cnt;
        int src = 0, dn = 0; float t = 0.0f;
        if (act) {
            int pe = list[off + e];
            src = ei[pe]; dn = ei[E + pe]; t = etime[pe];
        }
        {
            const uint4* xh = (const uint4*)(g_xnh + (size_t)src * 32);
            const uint4* xl = (const uint4*)(g_xnl + (size_t)src * 32);
#pragma unroll
            for (int kk = 0; kk < 8; kk++) {
                uint4 h = act ? xh[kk] : make_uint4(0, 0, 0, 0);
                uint4 l = act ? xl[kk] : make_uint4(0, 0, 0, 0);
                uint32_t byte = (uint32_t)(e * 128 + kk * 16);
                uint32_t swo = SW128(byte);
                *(uint4*)(sb + OFF_AHI + swo) = h;
                *(uint4*)(sb + OFF_ALO + swo) = l;
            }
        }
        __syncthreads();

        uint32_t tmem;
        asm volatile("ld.shared.b32 %0, [%1];" : "=r"(tmem) : "r"(base_u + OFF_TMP));

        // ---- MMA1 ----
        if (tid == 0) {
            FENCE_PROXY();
            uint64_t aH = mkdesc(base_u + OFF_AHI), aL = mkdesc(base_u + OFF_ALO);
            uint64_t bH = mkdesc(base_u + OFF_W1H), bL = mkdesc(base_u + OFF_W1L);
#pragma unroll
            for (int kc = 0; kc < 4; kc++) {
                mma_f16_ss(tmem, aH + kc * 2, bH + kc * 2, kc > 0 ? 1u : 0u);
                mma_f16_ss(tmem, aH + kc * 2, bL + kc * 2, 1u);
                mma_f16_ss(tmem, aL + kc * 2, bH + kc * 2, 1u);
            }
            TC_COMMIT(base_u + OFF_MBR);
        }

        // ---- prefetch q-row while MMA1 runs ----
        float4 qv[16];
        {
            const float4* qp = (const float4*)(qh + (size_t)dn * 64);
#pragma unroll
            for (int i = 0; i < 16; i++) qv[i] = qp[i];
        }
        float cvd = cv[dn];

        mbar_wait(base_u + OFF_MBR, ph); ph ^= 1;
        TC_FENCE_AFTER();

        // ---- epilogue 1 ----
        uint32_t d1[64];
        TC_LD_X32(d1, tmem);
        TC_LD_X32(d1 + 32, tmem + 32);
        TC_WAIT_LD();

        float ex = 0.0f;
        {
            float att = 0.0f;
            float t200 = t * 200.0f;
            uint32_t hbuf[4], lbuf[4];
#pragma unroll
            for (int m0 = 0; m0 < 64; m0 += 4) {
                float4 q4 = qv[m0 >> 2];
                float xt4[4];
#pragma unroll
                for (int j = 0; j < 4; j += 2) {
                    int m = m0 + j;
                    float arg = t200 * sdiv[m];
                    float sn = __sinf(arg), cc = __cosf(arg);
                    float xe = __uint_as_float(d1[m])     + sbt[m]     + t * wtl[m];
                    float xo = __uint_as_float(d1[m + 1]) + sbt[m + 1] + t * wtl[m + 1];
                    xt4[j]     = gelu_erf(xe) + sn;
                    xt4[j + 1] = gelu_erf(xo) + cc;
                }
                att += xt4[0] * q4.x + xt4[1] * q4.y + xt4[2] * q4.z + xt4[3] * q4.w;
                int half8 = (m0 & 4) ? 2 : 0;
                split2(xt4[0], xt4[1], hbuf[half8],     lbuf[half8]);
                split2(xt4[2], xt4[3], hbuf[half8 + 1], lbuf[half8 + 1]);
                if (m0 & 4) {
                    uint32_t byte = (uint32_t)(e * 128 + (m0 - 4) * 2);
                    uint32_t swo = SW128(byte);
                    *(uint4*)(sb + OFF_AHI + swo) = make_uint4(hbuf[0], hbuf[1], hbuf[2], hbuf[3]);
                    *(uint4*)(sb + OFF_ALO + swo) = make_uint4(lbuf[0], lbuf[1], lbuf[2], lbuf[3]);
                }
            }
            if (act) {
                ex = __expf((att + cvd) * 0.125f);
                atomicAdd(&g_den[dn], ex);
            }
        }
        __syncthreads();

        // ---- MMA2 ----
        if (tid == 0) {
            FENCE_PROXY();
            uint64_t aH = mkdesc(base_u + OFF_AHI), aL = mkdesc(base_u + OFF_ALO);
            uint64_t bH = mkdesc(base_u + OFF_W2H), bL = mkdesc(base_u + OFF_W2L);
#pragma unroll
            for (int kc = 0; kc < 4; kc++) {
                mma_f16_ss(tmem + 64, aH + kc * 2, bH + kc * 2, kc > 0 ? 1u : 0u);
                mma_f16_ss(tmem + 64, aH + kc * 2, bL + kc * 2, 1u);
                mma_f16_ss(tmem + 64, aL + kc * 2, bH + kc * 2, 1u);
            }
            TC_COMMIT(base_u + OFF_MBR);
        }

        mbar_wait(base_u + OFF_MBR, ph); ph ^= 1;
        TC_FENCE_AFTER();

        uint32_t d2[64];
        TC_LD_X32(d2, tmem + 64);
        TC_LD_X32(d2 + 32, tmem + 96);
        TC_WAIT_LD();

        if (act) {
            float* dp = g_aggr + (size_t)dn * 64;
#pragma unroll
            for (int m0 = 0; m0 < 64; m0 += 4) {
                float v0 = (__uint_as_float(d2[m0])     + sbv[m0])     * ex;
                float v1 = (__uint_as_float(d2[m0 + 1]) + sbv[m0 + 1]) * ex;
                float v2 = (__uint_as_float(d2[m0 + 2]) + sbv[m0 + 2]) * ex;
                float v3 = (__uint_as_float(d2[m0 + 3]) + sbv[m0 + 3]) * ex;
                asm volatile("red.global.add.v4.f32 [%0], {%1, %2, %3, %4};"
                             :: "l"(dp + m0), "f"(v0), "f"(v1), "f"(v2), "f"(v3) : "memory");
            }
        }
    }

    __syncthreads();
    if (tid == 0) MBAR_INVAL(base_u + OFF_MBR);
    __syncthreads();
    {
        uint32_t tmem;
        asm volatile("ld.shared.b32 %0, [%1];" : "=r"(tmem) : "r"(base_u + OFF_TMP));
        if (wid == 0) TC_DEALLOC(tmem, 128);
    }

#else   // ---------------- fp32 fallback (non-'a' PTX pass only) -------------
    for (int ti = bid; ti < total; ti += gridDim.x) {
        int same, off, cnt;
        const int* list;
        if (ti < ts) { list = g_perm_s; off = ti << 7; cnt = min(128, cs - off); same = 1; }
        else         { list = g_perm_d; off = (ti - ts) << 7; cnt = min(128, cd - off); same = 0; }
        const float* Wv = same ? Wvs : Wvd;
        const float* bv = same ? bvs : bvd;
        const float* qh = same ? g_qh_s : g_qh_d;
        const float* cv = same ? g_c_s  : g_c_d;
        int e = tid;
        if (e < cnt) {
            int pe = list[off + e];
            int src = ei[pe], dn = ei[E + pe];
            float t = etime[pe];
            float t200 = t * 200.0f;
            float xrow[64];
            for (int k2 = 0; k2 < 32; k2++) {
                uint32_t h = g_xnh[(size_t)src * 32 + k2];
                uint32_t l = g_xnl[(size_t)src * 32 + k2];
                xrow[2 * k2]     = __uint_as_float(h << 16) + __uint_as_float(l << 16);
                xrow[2 * k2 + 1] = __uint_as_float(h & 0xffff0000u) + __uint_as_float(l & 0xffff0000u);
            }
            float xt[64];
            float att = 0.0f;
            for (int m = 0; m < 64; m++) {
                float a = bt[m] + t * Wt[m * 65 + 64];
                for (int k = 0; k < 64; k++) a += xrow[k] * Wt[m * 65 + k];
                float dv = powf(10000.0f, -(float)(2 * (m / 2)) / 64.0f);
                float te = (m & 1) ? cosf(t200 * dv) : sinf(t200 * dv);
                xt[m] = gelu_erf(a) + te;
                att += xt[m] * qh[(size_t)dn * 64 + m];
            }
            float ex = expf((att + cv[dn]) * 0.125f);
            atomicAdd(&g_den[dn], ex);
            for (int m = 0; m < 64; m++) {
                float v = bv[m];
                for (int k = 0; k < 64; k++) v += xt[k] * Wv[m * 64 + k];
                atomicAdd(&g_aggr[(size_t)dn * 64 + m], ex * v);
            }
        }
    }
#endif
}

// ---------------- kernel 5: epilogue (normalize) + cnt reset ------------------
__global__ void final_kernel(const float* __restrict__ x, float* __restrict__ out, int N) {
    int i = blockIdx.x * blockDim.x + threadIdx.x;
    if (i < N * D) {
        float den = g_den[i >> 6];
        out[i] = x[i] + gelu_erf(g_aggr[i] / (den + 1e-16f));
    }
    if (i == 0) { g_cnt[0] = 0; g_cnt[1] = 0; }  // safe: no reader in this kernel
}

// ---------------- launch ------------------------------------------------------
extern "C" void kernel_launch(void* const* d_in, const int* in_sizes, int n_in,
                              void* d_out, int out_size) {
    const float* x     = (const float*)d_in[0];
    const int*   ei    = (const int*)  d_in[1];
    const float* etime = (const float*)d_in[2];
    const float* esame = (const float*)d_in[4];
    const float* lng   = (const float*)d_in[5];
    const float* lnb   = (const float*)d_in[6];
    const float* Wt    = (const float*)d_in[7];
    const float* bt    = (const float*)d_in[8];
    const float* Wq    = (const float*)d_in[9];
    const float* bq    = (const float*)d_in[10];
    const float* Wks   = (const float*)d_in[11];
    const float* bks   = (const float*)d_in[12];
    const float* Wkd   = (const float*)d_in[13];
    const float* bkd   = (const float*)d_in[14];
    const float* Wvs   = (const float*)d_in[15];
    const float* bvs   = (const float*)d_in[16];
    const float* Wvd   = (const float*)d_in[17];
    const float* bvd   = (const float*)d_in[18];
    float* out = (float*)d_out;

    int N = in_sizes[0] / D;
    int E = in_sizes[2];
    if (N > MAXN) N = MAXN;
    if (E > MAXE) E = MAXE;

    const int node_smem = NODE_SMEM_FLOATS * (int)sizeof(float);
    cudaFuncSetAttribute(node_kernel, cudaFuncAttributeMaxDynamicSharedMemorySize, node_smem);
    cudaFuncSetAttribute(edge_tc_kernel, cudaFuncAttributeMaxDynamicSharedMemorySize,
                         EDGE_SMEM_BYTES);

    int max_tiles = (E + 127) / 128 + 2;
    int edge_grid = max_tiles < 296 ? max_tiles : 296;

    prep_kernel<<<2 + (E + 255) / 256, 256>>>(esame, Wq, bq, Wks, bks, Wkd, bkd, E, N);
    node_kernel<<<(N + 127) / 128, 256, node_smem>>>(x, lng, lnb, N);
    edge_tc_kernel<<<edge_grid, 128, EDGE_SMEM_BYTES>>>(
        ei, etime, Wt, bt, Wvs, bvs, Wvd, bvd, E);
    final_kernel<<<(N * D + 255) / 256, 256>>>(x, out, N);
}

// round 14
// speedup vs baseline: 1.1341x; 1.0596x over previous
#include <cuda_runtime.h>
#include <cuda_bf16.h>
#include <math.h>
#include <stdint.h>

#define MAXN 50000
#define MAXE 800000
#define D 64
#define XS 130
#define WS 68

// tcgen05 is arch-SPECIFIC: only emit it in the sm_103a/'a'-target device pass.
#if !defined(__CUDA_ARCH__) || defined(__CUDA_ARCH_FEAT_SM103_ALL) || \
    defined(__CUDA_ARCH_FEAT_SM100_ALL) || defined(__CUDA_ARCH_SPECIFIC__) || \
    defined(__CUDA_ARCH_FAMILY_SPECIFIC__)
#define TC_OK 1
#else
#define TC_OK 0
#endif

typedef unsigned long long ull;

// ---------------- scratch ---------------------------------------------------
__device__ uint32_t g_xnh[MAXN * 32];
__device__ uint32_t g_xnl[MAXN * 32];
__device__ float g_qh_s[MAXN * D];
__device__ float g_qh_d[MAXN * D];
__device__ float g_c_s [MAXN];
__device__ float g_c_d [MAXN];
__device__ float g_den [MAXN];        // zeroed in prep_kernel each run
__device__ float g_aggr[MAXN * D];    // zeroed in prep_kernel each run
__device__ int   g_perm_s[MAXE];
__device__ int   g_perm_d[MAXE];
__device__ int   g_cnt[2];            // static zero; reset by final_kernel
__device__ float g_MsT[4096];
__device__ float g_MdT[4096];
__device__ float g_ds[64], g_dd[64];
__device__ float g_us[64], g_ud[64];
__device__ float g_ec[2];

__device__ __forceinline__ float gelu_erf(float x) {
    return 0.5f * x * (1.0f + erff(x * 0.70710678118654752440f));
}
__device__ __forceinline__ ull dup2(float x) {
    ull r; asm("mov.b64 %0, {%1, %1};" : "=l"(r) : "f"(x)); return r;
}
__device__ __forceinline__ void ffma2(ull& d, ull a, ull b) {
    asm("fma.rn.f32x2 %0, %1, %2, %0;" : "+l"(d) : "l"(a), "l"(b));
}
__device__ __forceinline__ float2 unpk(ull v) {
    float2 f; asm("mov.b64 {%0, %1}, %2;" : "=f"(f.x), "=f"(f.y) : "l"(v)); return f;
}

// ---------------- bf16 pack helpers ------------------------------------------
__device__ __forceinline__ uint32_t packbf(float x0, float x1) {
    uint32_t r;
    asm("cvt.rn.bf16x2.f32 %0, %2, %1;" : "=r"(r) : "f"(x0), "f"(x1));
    return r;
}
__device__ __forceinline__ void split2(float x0, float x1, uint32_t& hp, uint32_t& lp) {
    hp = packbf(x0, x1);
    float h0 = __uint_as_float(hp << 16);
    float h1 = __uint_as_float(hp & 0xffff0000u);
    lp = packbf(x0 - h0, x1 - h1);
}

__device__ __forceinline__ uint32_t smem_u32(const void* p) {
    uint32_t a;
    asm("{ .reg .u64 t; cvta.to.shared.u64 t, %1; cvt.u32.u64 %0, t; }"
        : "=r"(a) : "l"(p));
    return a;
}
#define SW128(o) ((o) ^ (((o) >> 3) & 0x70))

__device__ __forceinline__ uint64_t mkdesc(uint32_t addr) {
    const uint64_t base = (2ull << 61) | (1ull << 46) | (64ull << 32) | (1ull << 16);
    return base | ((addr >> 4) & 0x3FFF);
}

// idesc kind::f16, bf16 x bf16 -> f32, M=128, N=64
#define MMA_IDESC 0x08100490u

#if TC_OK
__device__ __forceinline__ void mma_f16_ss(uint32_t d_tmem, uint64_t a_desc,
                                           uint64_t b_desc, uint32_t en) {
    asm volatile(
        "{\n\t"
        ".reg .pred p;\n\t"
        "setp.ne.u32 p, %5, 0;\n\t"
        "tcgen05.mma.cta_group::1.kind::f16 [%0], %1, %2, %3, {%4, %4, %4, %4}, p;\n\t"
        "}"
        :: "r"(d_tmem), "l"(a_desc), "l"(b_desc), "r"(MMA_IDESC), "r"(0u), "r"(en)
        : "memory");
}

#define TC_ALLOC(smem_addr, n) \
    asm volatile("tcgen05.alloc.cta_group::1.sync.aligned.shared::cta.b32 [%0], %1;" \
                 :: "r"(smem_addr), "r"((uint32_t)(n)) : "memory")
#define TC_RELINQ() \
    asm volatile("tcgen05.relinquish_alloc_permit.cta_group::1.sync.aligned;")
#define TC_DEALLOC(tmem, n) \
    asm volatile("tcgen05.dealloc.cta_group::1.sync.aligned.b32 %0, %1;" \
                 :: "r"(tmem), "r"((uint32_t)(n)))
#define TC_COMMIT(mbar) \
    asm volatile("tcgen05.commit.cta_group::1.mbarrier::arrive::one.shared::cluster.b64 [%0];" \
                 :: "r"(mbar) : "memory")
#define TC_FENCE_AFTER() \
    asm volatile("tcgen05.fence::after_thread_sync;" ::: "memory")
#define TC_WAIT_LD() \
    asm volatile("tcgen05.wait::ld.sync.aligned;" ::: "memory")
#define FENCE_PROXY() \
    asm volatile("fence.proxy.async.shared::cta;" ::: "memory")
#define MBAR_INIT(mbar, n) \
    asm volatile("mbarrier.init.shared.b64 [%0], %1;" :: "r"(mbar), "r"((uint32_t)(n)) : "memory")
#define MBAR_INVAL(mbar) \
    asm volatile("mbarrier.inval.shared.b64 [%0];" :: "r"(mbar) : "memory")

__device__ __forceinline__ void mbar_wait(uint32_t mbar, uint32_t parity) {
    asm volatile(
        "{\n\t"
        ".reg .pred P;\n\t"
        "WLOOP%=:\n\t"
        "mbarrier.try_wait.parity.acquire.cta.shared::cta.b64 P, [%0], %1, 0x989680;\n\t"
        "@P bra.uni WDONE%=;\n\t"
        "bra.uni WLOOP%=;\n\t"
        "WDONE%=:\n\t"
        "}"
        :: "r"(mbar), "r"(parity) : "memory");
}

#define TC_LD_X32(r, tmem_addr) \
    asm volatile( \
        "tcgen05.ld.sync.aligned.32x32b.x32.b32 " \
        "{%0, %1, %2, %3, %4, %5, %6, %7, " \
        " %8, %9, %10, %11, %12, %13, %14, %15, " \
        " %16, %17, %18, %19, %20, %21, %22, %23, " \
        " %24, %25, %26, %27, %28, %29, %30, %31}, [%32];" \
        : "=r"((r)[0]),  "=r"((r)[1]),  "=r"((r)[2]),  "=r"((r)[3]), \
          "=r"((r)[4]),  "=r"((r)[5]),  "=r"((r)[6]),  "=r"((r)[7]), \
          "=r"((r)[8]),  "=r"((r)[9]),  "=r"((r)[10]), "=r"((r)[11]), \
          "=r"((r)[12]), "=r"((r)[13]), "=r"((r)[14]), "=r"((r)[15]), \
          "=r"((r)[16]), "=r"((r)[17]), "=r"((r)[18]), "=r"((r)[19]), \
          "=r"((r)[20]), "=r"((r)[21]), "=r"((r)[22]), "=r"((r)[23]), \
          "=r"((r)[24]), "=r"((r)[25]), "=r"((r)[26]), "=r"((r)[27]), \
          "=r"((r)[28]), "=r"((r)[29]), "=r"((r)[30]), "=r"((r)[31]) \
        : "r"(tmem_addr))
#endif  // TC_OK

// ---------------- kernel A: fold (blocks 0,1) + partition & zero (blocks>=2) --
__global__ __launch_bounds__(256) void prep_kernel(
    const float* __restrict__ esame,
    const float* __restrict__ Wq, const float* __restrict__ bq,
    const float* __restrict__ Wks, const float* __restrict__ bks,
    const float* __restrict__ Wkd, const float* __restrict__ bkd,
    int E, int N)
{
    __shared__ float sWq[4096], sWk[4096], sbq[64], sbk[64];
    int tid = threadIdx.x;
    int bidx = blockIdx.x;

    if (bidx < 2) {
        int b = bidx;
        const float* Wk = b ? Wkd : Wks;
        const float* bk = b ? bkd : bks;
        float* MT   = b ? g_MdT : g_MsT;
        float* dvec = b ? g_dd : g_ds;
        float* uvec = b ? g_ud : g_us;

        for (int i = tid; i < 4096; i += 256) { sWq[i] = Wq[i]; sWk[i] = Wk[i]; }
        if (tid < 64) { sbq[tid] = bq[tid]; sbk[tid] = bk[tid]; }
        __syncthreads();
#pragma unroll
        for (int ii = 0; ii < 16; ii++) {
            int o = tid + ii * 256;
            int j = o >> 6, c = o & 63;
            float s = 0.0f;
#pragma unroll 8
            for (int m = 0; m < 64; m++) s += sWk[m * 64 + c] * sWq[m * 64 + j];
            MT[o] = s;
        }
        if (tid < 64) {
            float sd = 0.0f, su = 0.0f;
#pragma unroll 8
            for (int m = 0; m < 64; m++) {
                sd += sWk[m * 64 + tid] * sbq[m];
                su += sbk[m] * sWq[m * 64 + tid];
            }
            dvec[tid] = sd; uvec[tid] = su;
        }
        if (tid == 0) {
            float s = 0.0f;
            for (int m = 0; m < 64; m++) s += sbk[m] * sbq[m];
            g_ec[b] = s;
        }
    } else {
        int gi = (bidx - 2) * 256 + tid;
        {
            float4 z = make_float4(0.f, 0.f, 0.f, 0.f);
            int total4 = N * D / 4;
            int nthr = (gridDim.x - 2) * 256;
            for (int p = gi; p < total4; p += nthr)
                *(((float4*)g_aggr) + p) = z;
            if (gi < N) g_den[gi] = 0.0f;
        }
        int e = gi;
        int lane = tid & 31;
        bool act = e < E;
        float es = act ? esame[e] : 0.0f;
        bool s = act && (es >= 0.5f);
        bool d = act && (es < 0.5f);
        unsigned ms = __ballot_sync(0xffffffffu, s);
        unsigned md = __ballot_sync(0xffffffffu, d);
        int bs = 0, bd = 0;
        if (lane == 0) {
            if (ms) bs = atomicAdd(&g_cnt[0], __popc(ms));
            if (md) bd = atomicAdd(&g_cnt[1], __popc(md));
        }
        bs = __shfl_sync(0xffffffffu, bs, 0);
        bd = __shfl_sync(0xffffffffu, bd, 0);
        unsigned lower = (1u << lane) - 1u;
        if (s) g_perm_s[bs + __popc(ms & lower)] = e;
        if (d) g_perm_d[bd + __popc(md & lower)] = e;
    }
}

// ---------------- kernel 1: layernorm + qh_s/qh_d/c + packed xn ---------------
#define NODE_SMEM_FLOATS (64*XS + 2*64*WS + 8*64)
__global__ __launch_bounds__(256, 2) void node_kernel(
    const float* __restrict__ x, const float* __restrict__ gamma,
    const float* __restrict__ beta, int N)
{
    extern __shared__ float ns[];
    float* XsT = ns;
    float* sMs = XsT + 64 * XS;
    float* sMd = sMs + 64 * WS;
    float* sg  = sMd + 64 * WS;
    float* sb  = sg + 64;
    float* sus = sb + 64;
    float* sud = sus + 64;
    float* sds = sud + 64;
    float* sdd = sds + 64;

    int tid = threadIdx.x;
    for (int i = tid; i < 4096; i += 256) {
        int j = i >> 6, c = i & 63;
        sMs[j * WS + c] = g_MsT[i];
        sMd[j * WS + c] = g_MdT[i];
    }
    if (tid < 64) {
        sg[tid] = gamma[tid]; sb[tid] = beta[tid];
        sus[tid] = g_us[tid]; sud[tid] = g_ud[tid];
        sds[tid] = g_ds[tid]; sdd[tid] = g_dd[tid];
    }
    __syncthreads();

    int n0 = blockIdx.x * 128;
    int cnt = min(128, N - n0);

    {
        int nl = tid >> 1, half = tid & 1;
        bool act = nl < cnt;
        int n = n0 + nl;
        float4 xv[8];
        float s = 0.0f, t = 0.0f;
        if (act) {
            const float4* xr = (const float4*)(x + (size_t)n * 64) + half * 8;
#pragma unroll
            for (int kk = 0; kk < 8; kk++) {
                xv[kk] = xr[kk];
                s += xv[kk].x + xv[kk].y + xv[kk].z + xv[kk].w;
                t += xv[kk].x * xv[kk].x + xv[kk].y * xv[kk].y
                   + xv[kk].z * xv[kk].z + xv[kk].w * xv[kk].w;
            }
        }
        s += __shfl_xor_sync(0xffffffffu, s, 1);
        t += __shfl_xor_sync(0xffffffffu, t, 1);
        float mu = s * (1.0f / 64.0f);
        float var = t * (1.0f / 64.0f) - mu * mu;
        float inv = rsqrtf(var + 1e-5f);
        float cs = 0.0f, cd = 0.0f;
        if (act) {
            uint32_t* gh = g_xnh + (size_t)n * 32 + half * 16;
            uint32_t* gl = g_xnl + (size_t)n * 32 + half * 16;
#pragma unroll
            for (int kk = 0; kk < 8; kk++) {
                int c0 = half * 32 + 4 * kk;
                float v[4] = {xv[kk].x, xv[kk].y, xv[kk].z, xv[kk].w};
                float xn4[4];
#pragma unroll
                for (int p = 0; p < 4; p++) {
                    int c = c0 + p;
                    float xn = (v[p] - mu) * inv * sg[c] + sb[c];
                    xn4[p] = xn;
                    XsT[c * XS + nl] = xn;
                    cs += xn * sus[c];
                    cd += xn * sud[c];
                }
                uint32_t h01, l01, h23, l23;
                split2(xn4[0], xn4[1], h01, l01);
                split2(xn4[2], xn4[3], h23, l23);
                gh[2 * kk] = h01; gh[2 * kk + 1] = h23;
                gl[2 * kk] = l01; gl[2 * kk + 1] = l23;
            }
        }
        cs += __shfl_xor_sync(0xffffffffu, cs, 1);
        cd += __shfl_xor_sync(0xffffffffu, cd, 1);
        if (act && half == 0) {
            g_c_s[n] = cs + g_ec[0];
            g_c_d[n] = cd + g_ec[1];
        }
    }
    __syncthreads();

    int ty = tid >> 3, tx = tid & 7;
    int row0 = ty << 2, col0 = tx << 3;
#pragma unroll
    for (int pass = 0; pass < 2; pass++) {
        const float* M = pass ? sMd : sMs;
        const float* dv = pass ? sdd : sds;
        float* outp = pass ? g_qh_d : g_qh_s;
        ull acc[16];
        {
            const ull* dp = (const ull*)(dv + col0);
            ull w0 = dp[0], w1 = dp[1], w2 = dp[2], w3 = dp[3];
#pragma unroll
            for (int i = 0; i < 4; i++) {
                acc[i * 4] = w0; acc[i * 4 + 1] = w1; acc[i * 4 + 2] = w2; acc[i * 4 + 3] = w3;
            }
        }
#pragma unroll 4
        for (int k = 0; k < 64; k++) {
            const ull* axp = (const ull*)(XsT + k * XS + row0);
            float2 f01 = unpk(axp[0]), f23 = unpk(axp[1]);
            float aa[4] = {f01.x, f01.y, f23.x, f23.y};
            const ull* bp = (const ull*)(M + k * WS + col0);
            ull w0 = bp[0], w1 = bp[1], w2 = bp[2], w3 = bp[3];
#pragma unroll
            for (int i = 0; i < 4; i++) {
                ull ad = dup2(aa[i]);
                ffma2(acc[i * 4],     ad, w0);
                ffma2(acc[i * 4 + 1], ad, w1);
                ffma2(acc[i * 4 + 2], ad, w2);
                ffma2(acc[i * 4 + 3], ad, w3);
            }
        }
#pragma unroll
        for (int i = 0; i < 4; i++) {
            int nl = row0 + i;
            if (nl < cnt) {
                float* dp = outp + (size_t)(n0 + nl) * 64 + col0;
                float2 v0 = unpk(acc[i * 4]),     v1 = unpk(acc[i * 4 + 1]);
                float2 v2 = unpk(acc[i * 4 + 2]), v3 = unpk(acc[i * 4 + 3]);
                *(float4*)dp       = make_float4(v0.x, v0.y, v1.x, v1.y);
                *(float4*)(dp + 4) = make_float4(v2.x, v2.y, v3.x, v3.y);
            }
        }
    }
}

// ---------------- kernel 2: tensor-core edge kernel (persistent, 3 CTA/SM) ---
#define OFF_AHI 0
#define OFF_ALO 16384
#define OFF_W1H 32768
#define OFF_W1L 40960
#define OFF_W2H 49152
#define OFF_W2L 57344
#define OFF_SBT 65536
#define OFF_SBV 65792
#define OFF_WTL 66048
#define OFF_SDV 66304
#define OFF_TMP 66560
#define OFF_MBR 66568
#define EDGE_SMEM_BYTES (1024 + 66576 + 48)

__global__ __launch_bounds__(128)
void edge_tc_kernel(
    const int* __restrict__ ei, const float* __restrict__ etime,
    const float* __restrict__ Wt,
    const float* __restrict__ bt,
    const float* __restrict__ Wvs, const float* __restrict__ bvs,
    const float* __restrict__ Wvd, const float* __restrict__ bvd,
    int E)
{
    int tid = threadIdx.x;
    int bid = blockIdx.x;

    int cs = g_cnt[0], cd = g_cnt[1];
    int ts = (cs + 127) >> 7;
    int td = (cd + 127) >> 7;
    int total = ts + td;

#if TC_OK
    extern __shared__ char dsm_raw[];
    uint32_t raw_u = smem_u32(dsm_raw);
    uint32_t base_u = (raw_u + 1023u) & ~1023u;
    char* sb = dsm_raw + (base_u - raw_u);
    int wid = tid >> 5;

    if (wid == 0) {
        TC_ALLOC(base_u + OFF_TMP, 128);
        TC_RELINQ();
    }
    if (tid == 0) MBAR_INIT(base_u + OFF_MBR, 1);

    float* sbt  = (float*)(sb + OFF_SBT);
    float* sbv  = (float*)(sb + OFF_SBV);
    float* wtl  = (float*)(sb + OFF_WTL);
    float* sdiv = (float*)(sb + OFF_SDV);

    for (int i = tid; i < 2048; i += 128) {
        int m = i >> 5, k2 = (i & 31) * 2;
        uint32_t byte = (uint32_t)(m * 128 + k2 * 2);
        uint32_t swo = SW128(byte);
        uint32_t hp, lp;
        split2(Wt[m * 65 + k2], Wt[m * 65 + k2 + 1], hp, lp);
        *(uint32_t*)(sb + OFF_W1H + swo) = hp;
        *(uint32_t*)(sb + OFF_W1L + swo) = lp;
    }
    if (tid < 64) {
        sbt[tid] = bt[tid];
        wtl[tid] = Wt[tid * 65 + 64];
        sdiv[tid] = powf(10000.0f, -(float)(2 * (tid >> 1)) / 64.0f);
    }

    int cur_same = -1;
    int ph = 0;
    for (int ti = bid; ti < total; ti += gridDim.x) {
        int same, off, cnt;
        const int* list;
        if (ti < ts) {
            list = g_perm_s; off = ti << 7; cnt = min(128, cs - off); same = 1;
        } else {
            list = g_perm_d; off = (ti - ts) << 7; cnt = min(128, cd - off); same = 0;
        }
        const float* Wv = same ? Wvs : Wvd;
        const float* bv = same ? bvs : bvd;
        const float* qh = same ? g_qh_s : g_qh_d;
        const float* cv = same ? g_c_s  : g_c_d;

        __syncthreads();

        if (same != cur_same) {
            for (int i = tid; i < 2048; i += 128) {
                int m = i >> 5, k2 = (i & 31) * 2;
                uint32_t byte = (uint32_t)(m * 128 + k2 * 2);
                uint32_t swo = SW128(byte);
                uint32_t hp, lp;
                split2(Wv[m * 64 + k2], Wv[m * 64 + k2 + 1], hp, lp);
                *(uint32_t*)(sb + OFF_W2H + swo) = hp;
                *(uint32_t*)(sb + OFF_W2L + swo) = lp;
            }
            if (tid < 64) sbv[tid] = bv[tid];
            cur_same = same;
        }

        int e = tid;
        bool act = e < cnt;
        int src = 0, dn = 0; float t = 0.0f;
        if (act) {
            int pe = list[off + e];
            src = ei[pe]; dn = ei[E + pe]; t = etime[pe];
        }
        {
            const uint4* xh = (const uint4*)(g_xnh + (size_t)src * 32);
            const uint4* xl = (const uint4*)(g_xnl + (size_t)src * 32);
#pragma unroll
            for (int kk = 0; kk < 8; kk++) {
                uint4 h = act ? xh[kk] : make_uint4(0, 0, 0, 0);
                uint4 l = act ? xl[kk] : make_uint4(0, 0, 0, 0);
                uint32_t byte = (uint32_t)(e * 128 + kk * 16);
                uint32_t swo = SW128(byte);
                *(uint4*)(sb + OFF_AHI + swo) = h;
                *(uint4*)(sb + OFF_ALO + swo) = l;
            }
        }
        __syncthreads();

        uint32_t tmem;
        asm volatile("ld.shared.b32 %0, [%1];" : "=r"(tmem) : "r"(base_u + OFF_TMP));

        if (tid == 0) {
            FENCE_PROXY();
            uint64_t aH = mkdesc(base_u + OFF_AHI), aL = mkdesc(base_u + OFF_ALO);
            uint64_t bH = mkdesc(base_u + OFF_W1H), bL = mkdesc(base_u + OFF_W1L);
#pragma unroll
            for (int kc = 0; kc < 4; kc++) {
                mma_f16_ss(tmem, aH + kc * 2, bH + kc * 2, kc > 0 ? 1u : 0u);
                mma_f16_ss(tmem, aH + kc * 2, bL + kc * 2, 1u);
                mma_f16_ss(tmem, aL + kc * 2, bH + kc * 2, 1u);
            }
            TC_COMMIT(base_u + OFF_MBR);
        }

        float4 qv[16];
        {
            const float4* qp = (const float4*)(qh + (size_t)dn * 64);
#pragma unroll
            for (int i = 0; i < 16; i++) qv[i] = qp[i];
        }
        float cvd = cv[dn];

        mbar_wait(base_u + OFF_MBR, ph); ph ^= 1;
        TC_FENCE_AFTER();

        uint32_t d1[64];
        TC_LD_X32(d1, tmem);
        TC_LD_X32(d1 + 32, tmem + 32);
        TC_WAIT_LD();

        float ex = 0.0f;
        {
            float att = 0.0f;
            float t200 = t * 200.0f;
            uint32_t hbuf[4], lbuf[4];
#pragma unroll
            for (int m0 = 0; m0 < 64; m0 += 4) {
                float4 q4 = qv[m0 >> 2];
                float xt4[4];
#pragma unroll
                for (int j = 0; j < 4; j += 2) {
                    int m = m0 + j;
                    float arg = t200 * sdiv[m];
                    float sn = __sinf(arg), cc = __cosf(arg);
                    float xe = __uint_as_float(d1[m])     + sbt[m]     + t * wtl[m];
                    float xo = __uint_as_float(d1[m + 1]) + sbt[m + 1] + t * wtl[m + 1];
                    xt4[j]     = gelu_erf(xe) + sn;
                    xt4[j + 1] = gelu_erf(xo) + cc;
                }
                att += xt4[0] * q4.x + xt4[1] * q4.y + xt4[2] * q4.z + xt4[3] * q4.w;
                int half8 = (m0 & 4) ? 2 : 0;
                split2(xt4[0], xt4[1], hbuf[half8],     lbuf[half8]);
                split2(xt4[2], xt4[3], hbuf[half8 + 1], lbuf[half8 + 1]);
                if (m0 & 4) {
                    uint32_t byte = (uint32_t)(e * 128 + (m0 - 4) * 2);
                    uint32_t swo = SW128(byte);
                    *(uint4*)(sb + OFF_AHI + swo) = make_uint4(hbuf[0], hbuf[1], hbuf[2], hbuf[3]);
                    *(uint4*)(sb + OFF_ALO + swo) = make_uint4(lbuf[0], lbuf[1], lbuf[2], lbuf[3]);
                }
            }
            if (act) {
                ex = __expf((att + cvd) * 0.125f);
                atomicAdd(&g_den[dn], ex);
            }
        }
        __syncthreads();

        if (tid == 0) {
            FENCE_PROXY();
            uint64_t aH = mkdesc(base_u + OFF_AHI), aL = mkdesc(base_u + OFF_ALO);
            uint64_t bH = mkdesc(base_u + OFF_W2H), bL = mkdesc(base_u + OFF_W2L);
#pragma unroll
            for (int kc = 0; kc < 4; kc++) {
                mma_f16_ss(tmem + 64, aH + kc * 2, bH + kc * 2, kc > 0 ? 1u : 0u);
                mma_f16_ss(tmem + 64, aH + kc * 2, bL + kc * 2, 1u);
                mma_f16_ss(tmem + 64, aL + kc * 2, bH + kc * 2, 1u);
            }
            TC_COMMIT(base_u + OFF_MBR);
        }

        mbar_wait(base_u + OFF_MBR, ph); ph ^= 1;
        TC_FENCE_AFTER();

        uint32_t d2[64];
        TC_LD_X32(d2, tmem + 64);
        TC_LD_X32(d2 + 32, tmem + 96);
        TC_WAIT_LD();

        if (act) {
            float* dp = g_aggr + (size_t)dn * 64;
#pragma unroll
            for (int m0 = 0; m0 < 64; m0 += 4) {
                float v0 = (__uint_as_float(d2[m0])     + sbv[m0])     * ex;
                float v1 = (__uint_as_float(d2[m0 + 1]) + sbv[m0 + 1]) * ex;
                float v2 = (__uint_as_float(d2[m0 + 2]) + sbv[m0 + 2]) * ex;
                float v3 = (__uint_as_float(d2[m0 + 3]) + sbv[m0 + 3]) * ex;
                asm volatile("red.global.add.v4.f32 [%0], {%1, %2, %3, %4};"
                             :: "l"(dp + m0), "f"(v0), "f"(v1), "f"(v2), "f"(v3) : "memory");
            }
        }
    }

    __syncthreads();
    if (tid == 0) MBAR_INVAL(base_u + OFF_MBR);
    __syncthreads();
    {
        uint32_t tmem;
        asm volatile("ld.shared.b32 %0, [%1];" : "=r"(tmem) : "r"(base_u + OFF_TMP));
        if (wid == 0) TC_DEALLOC(tmem, 128);
    }

#else   // ---------------- fp32 fallback (non-'a' PTX pass only) -------------
    for (int ti = bid; ti < total; ti += gridDim.x) {
        int same, off, cnt;
        const int* list;
        if (ti < ts) { list = g_perm_s; off = ti << 7; cnt = min(128, cs - off); same = 1; }
        else         { list = g_perm_d; off = (ti - ts) << 7; cnt = min(128, cd - off); same = 0; }
        const float* Wv = same ? Wvs : Wvd;
        const float* bv = same ? bvs : bvd;
        const float* qh = same ? g_qh_s : g_qh_d;
        const float* cv = same ? g_c_s  : g_c_d;
        int e = tid;
        if (e < cnt) {
            int pe = list[off + e];
            int src = ei[pe], dn = ei[E + pe];
            float t = etime[pe];
            float t200 = t * 200.0f;
            float xrow[64];
            for (int k2 = 0; k2 < 32; k2++) {
                uint32_t h = g_xnh[(size_t)src * 32 + k2];
                uint32_t l = g_xnl[(size_t)src * 32 + k2];
                xrow[2 * k2]     = __uint_as_float(h << 16) + __uint_as_float(l << 16);
                xrow[2 * k2 + 1] = __uint_as_float(h & 0xffff0000u) + __uint_as_float(l & 0xffff0000u);
            }
            float xt[64];
            float att = 0.0f;
            for (int m = 0; m < 64; m++) {
                float a = bt[m] + t * Wt[m * 65 + 64];
                for (int k = 0; k < 64; k++) a += xrow[k] * Wt[m * 65 + k];
                float dv = powf(10000.0f, -(float)(2 * (m / 2)) / 64.0f);
                float te = (m & 1) ? cosf(t200 * dv) : sinf(t200 * dv);
                xt[m] = gelu_erf(a) + te;
                att += xt[m] * qh[(size_t)dn * 64 + m];
            }
            float ex = expf((att + cv[dn]) * 0.125f);
            atomicAdd(&g_den[dn], ex);
            for (int m = 0; m < 64; m++) {
                float v = bv[m];
                for (int k = 0; k < 64; k++) v += xt[k] * Wv[m * 64 + k];
                atomicAdd(&g_aggr[(size_t)dn * 64 + m], ex * v);
            }
        }
    }
#endif
}

// ---------------- kernel 5: epilogue (normalize) + cnt reset ------------------
__global__ void final_kernel(const float* __restrict__ x, float* __restrict__ out, int N) {
    int i = blockIdx.x * blockDim.x + threadIdx.x;
    if (i < N * D) {
        float den = g_den[i >> 6];
        out[i] = x[i] + gelu_erf(g_aggr[i] / (den + 1e-16f));
    }
    if (i == 0) { g_cnt[0] = 0; g_cnt[1] = 0; }
}

// ---------------- launch ------------------------------------------------------
extern "C" void kernel_launch(void* const* d_in, const int* in_sizes, int n_in,
                              void* d_out, int out_size) {
    const float* x     = (const float*)d_in[0];
    const int*   ei    = (const int*)  d_in[1];
    const float* etime = (const float*)d_in[2];
    const float* esame = (const float*)d_in[4];
    const float* lng   = (const float*)d_in[5];
    const float* lnb   = (const float*)d_in[6];
    const float* Wt    = (const float*)d_in[7];
    const float* bt    = (const float*)d_in[8];
    const float* Wq    = (const float*)d_in[9];
    const float* bq    = (const float*)d_in[10];
    const float* Wks   = (const float*)d_in[11];
    const float* bks   = (const float*)d_in[12];
    const float* Wkd   = (const float*)d_in[13];
    const float* bkd   = (const float*)d_in[14];
    const float* Wvs   = (const float*)d_in[15];
    const float* bvs   = (const float*)d_in[16];
    const float* Wvd   = (const float*)d_in[17];
    const float* bvd   = (const float*)d_in[18];
    float* out = (float*)d_out;

    int N = in_sizes[0] / D;
    int E = in_sizes[2];
    if (N > MAXN) N = MAXN;
    if (E > MAXE) E = MAXE;

    const int node_smem = NODE_SMEM_FLOATS * (int)sizeof(float);
    cudaFuncSetAttribute(node_kernel, cudaFuncAttributeMaxDynamicSharedMemorySize, node_smem);
    cudaFuncSetAttribute(edge_tc_kernel, cudaFuncAttributeMaxDynamicSharedMemorySize,
                         EDGE_SMEM_BYTES);

    // persistent: 3 CTAs/SM (smem 3x67.6KB = 203KB <= 228KB; TMEM 3x128 <= 512)
    int max_tiles = (E + 127) / 128 + 2;
    int edge_grid = max_tiles < 444 ? max_tiles : 444;

    prep_kernel<<<2 + (E + 255) / 256, 256>>>(esame, Wq, bq, Wks, bks, Wkd, bkd, E, N);
    node_kernel<<<(N + 127) / 128, 256, node_smem>>>(x, lng, lnb, N);
    edge_tc_kernel<<<edge_grid, 128, EDGE_SMEM_BYTES>>>(
        ei, etime, Wt, bt, Wvs, bvs, Wvd, bvd, E);
    final_kernel<<<(N * D + 255) / 256, 256>>>(x, out, N);
}

// round 15
// speedup vs baseline: 1.2098x; 1.0668x over previous
#include <cuda_runtime.h>
#include <cuda_bf16.h>
#include <math.h>
#include <stdint.h>

#define MAXN 50000
#define MAXE 800000
#define D 64

// tcgen05 is arch-SPECIFIC: only emit it in the sm_103a/'a'-target device pass.
#if !defined(__CUDA_ARCH__) || defined(__CUDA_ARCH_FEAT_SM103_ALL) || \
    defined(__CUDA_ARCH_FEAT_SM100_ALL) || defined(__CUDA_ARCH_SPECIFIC__) || \
    defined(__CUDA_ARCH_FAMILY_SPECIFIC__)
#define TC_OK 1
#else
#define TC_OK 0
#endif

typedef unsigned long long ull;

// ---------------- scratch ---------------------------------------------------
__device__ uint32_t g_xnh[MAXN * 32];
__device__ uint32_t g_xnl[MAXN * 32];
__device__ float g_qh_s[MAXN * D];
__device__ float g_qh_d[MAXN * D];
__device__ float g_c_s [MAXN];
__device__ float g_c_d [MAXN];
__device__ float g_den [MAXN];        // zeroed in prep_kernel each run
__device__ float g_aggr[MAXN * D];    // zeroed in prep_kernel each run
__device__ int   g_perm_s[MAXE];
__device__ int   g_perm_d[MAXE];
__device__ int   g_cnt[2];            // static zero; reset by final_kernel
__device__ float g_Ms[4096];          // [c][j] = sum_m Wks[m,c]*Wq[m,j]
__device__ float g_Md[4096];
__device__ float g_ds[64], g_dd[64];
__device__ float g_us[64], g_ud[64];
__device__ float g_ec[2];

__device__ __forceinline__ float gelu_erf(float x) {
    return 0.5f * x * (1.0f + erff(x * 0.70710678118654752440f));
}

// ---------------- bf16 pack helpers ------------------------------------------
__device__ __forceinline__ uint32_t packbf(float x0, float x1) {
    uint32_t r;
    asm("cvt.rn.bf16x2.f32 %0, %2, %1;" : "=r"(r) : "f"(x0), "f"(x1));
    return r;
}
__device__ __forceinline__ void split2(float x0, float x1, uint32_t& hp, uint32_t& lp) {
    hp = packbf(x0, x1);
    float h0 = __uint_as_float(hp << 16);
    float h1 = __uint_as_float(hp & 0xffff0000u);
    lp = packbf(x0 - h0, x1 - h1);
}

__device__ __forceinline__ uint32_t smem_u32(const void* p) {
    uint32_t a;
    asm("{ .reg .u64 t; cvta.to.shared.u64 t, %1; cvt.u32.u64 %0, t; }"
        : "=r"(a) : "l"(p));
    return a;
}
#define SW128(o) ((o) ^ (((o) >> 3) & 0x70))

__device__ __forceinline__ uint64_t mkdesc(uint32_t addr) {
    const uint64_t base = (2ull << 61) | (1ull << 46) | (64ull << 32) | (1ull << 16);
    return base | ((addr >> 4) & 0x3FFF);
}

// idesc kind::f16, bf16 x bf16 -> f32, M=128, N=64
#define MMA_IDESC 0x08100490u

#if TC_OK
__device__ __forceinline__ void mma_f16_ss(uint32_t d_tmem, uint64_t a_desc,
                                           uint64_t b_desc, uint32_t en) {
    asm volatile(
        "{\n\t"
        ".reg .pred p;\n\t"
        "setp.ne.u32 p, %5, 0;\n\t"
        "tcgen05.mma.cta_group::1.kind::f16 [%0], %1, %2, %3, {%4, %4, %4, %4}, p;\n\t"
        "}"
        :: "r"(d_tmem), "l"(a_desc), "l"(b_desc), "r"(MMA_IDESC), "r"(0u), "r"(en)
        : "memory");
}

#define TC_ALLOC(smem_addr, n) \
    asm volatile("tcgen05.alloc.cta_group::1.sync.aligned.shared::cta.b32 [%0], %1;" \
                 :: "r"(smem_addr), "r"((uint32_t)(n)) : "memory")
#define TC_RELINQ() \
    asm volatile("tcgen05.relinquish_alloc_permit.cta_group::1.sync.aligned;")
#define TC_DEALLOC(tmem, n) \
    asm volatile("tcgen05.dealloc.cta_group::1.sync.aligned.b32 %0, %1;" \
                 :: "r"(tmem), "r"((uint32_t)(n)))
#define TC_COMMIT(mbar) \
    asm volatile("tcgen05.commit.cta_group::1.mbarrier::arrive::one.shared::cluster.b64 [%0];" \
                 :: "r"(mbar) : "memory")
#define TC_FENCE_AFTER() \
    asm volatile("tcgen05.fence::after_thread_sync;" ::: "memory")
#define TC_WAIT_LD() \
    asm volatile("tcgen05.wait::ld.sync.aligned;" ::: "memory")
#define FENCE_PROXY() \
    asm volatile("fence.proxy.async.shared::cta;" ::: "memory")
#define MBAR_INIT(mbar, n) \
    asm volatile("mbarrier.init.shared.b64 [%0], %1;" :: "r"(mbar), "r"((uint32_t)(n)) : "memory")
#define MBAR_INVAL(mbar) \
    asm volatile("mbarrier.inval.shared.b64 [%0];" :: "r"(mbar) : "memory")

__device__ __forceinline__ void mbar_wait(uint32_t mbar, uint32_t parity) {
    asm volatile(
        "{\n\t"
        ".reg .pred P;\n\t"
        "WLOOP%=:\n\t"
        "mbarrier.try_wait.parity.acquire.cta.shared::cta.b64 P, [%0], %1, 0x989680;\n\t"
        "@P bra.uni WDONE%=;\n\t"
        "bra.uni WLOOP%=;\n\t"
        "WDONE%=:\n\t"
        "}"
        :: "r"(mbar), "r"(parity) : "memory");
}

#define TC_LD_X32(r, tmem_addr) \
    asm volatile( \
        "tcgen05.ld.sync.aligned.32x32b.x32.b32 " \
        "{%0, %1, %2, %3, %4, %5, %6, %7, " \
        " %8, %9, %10, %11, %12, %13, %14, %15, " \
        " %16, %17, %18, %19, %20, %21, %22, %23, " \
        " %24, %25, %26, %27, %28, %29, %30, %31}, [%32];" \
        : "=r"((r)[0]),  "=r"((r)[1]),  "=r"((r)[2]),  "=r"((r)[3]), \
          "=r"((r)[4]),  "=r"((r)[5]),  "=r"((r)[6]),  "=r"((r)[7]), \
          "=r"((r)[8]),  "=r"((r)[9]),  "=r"((r)[10]), "=r"((r)[11]), \
          "=r"((r)[12]), "=r"((r)[13]), "=r"((r)[14]), "=r"((r)[15]), \
          "=r"((r)[16]), "=r"((r)[17]), "=r"((r)[18]), "=r"((r)[19]), \
          "=r"((r)[20]), "=r"((r)[21]), "=r"((r)[22]), "=r"((r)[23]), \
          "=r"((r)[24]), "=r"((r)[25]), "=r"((r)[26]), "=r"((r)[27]), \
          "=r"((r)[28]), "=r"((r)[29]), "=r"((r)[30]), "=r"((r)[31]) \
        : "r"(tmem_addr))
#endif  // TC_OK

// ---------------- kernel A: fold (blocks 0,1) + partition & zero (blocks>=2) --
__global__ __launch_bounds__(256) void prep_kernel(
    const float* __restrict__ esame,
    const float* __restrict__ Wq, const float* __restrict__ bq,
    const float* __restrict__ Wks, const float* __restrict__ bks,
    const float* __restrict__ Wkd, const float* __restrict__ bkd,
    int E, int N)
{
    __shared__ float sWq[4096], sWk[4096], sbq[64], sbk[64];
    int tid = threadIdx.x;
    int bidx = blockIdx.x;

    if (bidx < 2) {
        int b = bidx;
        const float* Wk = b ? Wkd : Wks;
        const float* bk = b ? bkd : bks;
        float* MT   = b ? g_Md : g_Ms;
        float* dvec = b ? g_dd : g_ds;
        float* uvec = b ? g_ud : g_us;

        for (int i = tid; i < 4096; i += 256) { sWq[i] = Wq[i]; sWk[i] = Wk[i]; }
        if (tid < 64) { sbq[tid] = bq[tid]; sbk[tid] = bk[tid]; }
        __syncthreads();
#pragma unroll
        for (int ii = 0; ii < 16; ii++) {
            int o = tid + ii * 256;
            int j = o >> 6, c = o & 63;
            float s = 0.0f;
#pragma unroll 8
            for (int m = 0; m < 64; m++) s += sWk[m * 64 + c] * sWq[m * 64 + j];
            MT[c * 64 + j] = s;        // c-major rows for TC B operand
        }
        if (tid < 64) {
            float sd = 0.0f, su = 0.0f;
#pragma unroll 8
            for (int m = 0; m < 64; m++) {
                sd += sWk[m * 64 + tid] * sbq[m];
                su += sbk[m] * sWq[m * 64 + tid];
            }
            dvec[tid] = sd; uvec[tid] = su;
        }
        if (tid == 0) {
            float s = 0.0f;
            for (int m = 0; m < 64; m++) s += sbk[m] * sbq[m];
            g_ec[b] = s;
        }
    } else {
        int gi = (bidx - 2) * 256 + tid;
        {
            float4 z = make_float4(0.f, 0.f, 0.f, 0.f);
            int total4 = N * D / 4;
            int nthr = (gridDim.x - 2) * 256;
            for (int p = gi; p < total4; p += nthr)
                *(((float4*)g_aggr) + p) = z;
            if (gi < N) g_den[gi] = 0.0f;
        }
        int e = gi;
        int lane = tid & 31;
        bool act = e < E;
        float es = act ? esame[e] : 0.0f;
        bool s = act && (es >= 0.5f);
        bool d = act && (es < 0.5f);
        unsigned ms = __ballot_sync(0xffffffffu, s);
        unsigned md = __ballot_sync(0xffffffffu, d);
        int bs = 0, bd = 0;
        if (lane == 0) {
            if (ms) bs = atomicAdd(&g_cnt[0], __popc(ms));
            if (md) bd = atomicAdd(&g_cnt[1], __popc(md));
        }
        bs = __shfl_sync(0xffffffffu, bs, 0);
        bd = __shfl_sync(0xffffffffu, bd, 0);
        unsigned lower = (1u << lane) - 1u;
        if (s) g_perm_s[bs + __popc(ms & lower)] = e;
        if (d) g_perm_d[bd + __popc(md & lower)] = e;
    }
}

// ---------------- kernel 1: tensor-core node kernel (LN + qh via tcgen05) -----
#define NOFF_AHI 0
#define NOFF_ALO 16384
#define NOFF_MSH 32768
#define NOFF_MSL 40960
#define NOFF_MDH 49152
#define NOFF_MDL 57344
#define NOFF_DS  65536
#define NOFF_DD  65792
#define NOFF_G   66048
#define NOFF_B   66304
#define NOFF_US  66560
#define NOFF_UD  66816
#define NOFF_TMP 67072
#define NOFF_MBR 67080
#define NODE_SMEM_BYTES (1024 + 67088 + 48)

__global__ __launch_bounds__(128)
void node_tc_kernel(const float* __restrict__ x, const float* __restrict__ gamma,
                    const float* __restrict__ beta, int N)
{
    int tid = threadIdx.x;
    int n0 = blockIdx.x * 128;
    int cnt = min(128, N - n0);
    int n = n0 + tid;
    bool act = tid < cnt;

#if TC_OK
    extern __shared__ char dsm_raw[];
    uint32_t raw_u = smem_u32(dsm_raw);
    uint32_t base_u = (raw_u + 1023u) & ~1023u;
    char* sb_ = dsm_raw + (base_u - raw_u);
    int wid = tid >> 5;

    if (wid == 0) {
        TC_ALLOC(base_u + NOFF_TMP, 128);
        TC_RELINQ();
    }
    if (tid == 0) MBAR_INIT(base_u + NOFF_MBR, 1);

    float* sds = (float*)(sb_ + NOFF_DS);
    float* sdd = (float*)(sb_ + NOFF_DD);
    float* sg  = (float*)(sb_ + NOFF_G);
    float* sbv = (float*)(sb_ + NOFF_B);
    float* sus = (float*)(sb_ + NOFF_US);
    float* sud = (float*)(sb_ + NOFF_UD);

    // ---- B operands: Ms/Md (c-major) -> bf16 hi/lo swizzled ----
    for (int i = tid; i < 2048; i += 128) {
        int c = i >> 5, k2 = (i & 31) * 2;
        uint32_t byte = (uint32_t)(c * 128 + k2 * 2);
        uint32_t swo = SW128(byte);
        uint32_t hp, lp;
        split2(g_Ms[c * 64 + k2], g_Ms[c * 64 + k2 + 1], hp, lp);
        *(uint32_t*)(sb_ + NOFF_MSH + swo) = hp;
        *(uint32_t*)(sb_ + NOFF_MSL + swo) = lp;
        split2(g_Md[c * 64 + k2], g_Md[c * 64 + k2 + 1], hp, lp);
        *(uint32_t*)(sb_ + NOFF_MDH + swo) = hp;
        *(uint32_t*)(sb_ + NOFF_MDL + swo) = lp;
    }
    if (tid < 64) {
        sds[tid] = g_ds[tid]; sdd[tid] = g_dd[tid];
        sg[tid] = gamma[tid]; sbv[tid] = beta[tid];
        sus[tid] = g_us[tid]; sud[tid] = g_ud[tid];
    }
    __syncthreads();

    // ---- per-thread LN; write xn hi/lo to A smem + globals; c dots ----
    float4 xv[16];
    float mu = 0.0f, inv = 0.0f;
    if (act) {
        const float4* xr = (const float4*)(x + (size_t)n * 64);
        float s = 0.0f, t2 = 0.0f;
#pragma unroll
        for (int kk = 0; kk < 16; kk++) {
            xv[kk] = xr[kk];
            s  += xv[kk].x + xv[kk].y + xv[kk].z + xv[kk].w;
            t2 += xv[kk].x * xv[kk].x + xv[kk].y * xv[kk].y
                + xv[kk].z * xv[kk].z + xv[kk].w * xv[kk].w;
        }
        mu = s * (1.0f / 64.0f);
        float var = t2 * (1.0f / 64.0f) - mu * mu;
        inv = rsqrtf(var + 1e-5f);
    }
    {
        float cs = 0.0f, cd = 0.0f;
        uint32_t hb[4], lb[4];
        uint4* gh = (uint4*)(g_xnh + (size_t)n * 32);
        uint4* gl = (uint4*)(g_xnl + (size_t)n * 32);
#pragma unroll
        for (int kk = 0; kk < 16; kk++) {
            float a0 = 0.f, a1 = 0.f, a2 = 0.f, a3 = 0.f;
            if (act) {
                int c0 = kk * 4;
                a0 = (xv[kk].x - mu) * inv * sg[c0]     + sbv[c0];
                a1 = (xv[kk].y - mu) * inv * sg[c0 + 1] + sbv[c0 + 1];
                a2 = (xv[kk].z - mu) * inv * sg[c0 + 2] + sbv[c0 + 2];
                a3 = (xv[kk].w - mu) * inv * sg[c0 + 3] + sbv[c0 + 3];
                cs += a0 * sus[c0] + a1 * sus[c0 + 1] + a2 * sus[c0 + 2] + a3 * sus[c0 + 3];
                cd += a0 * sud[c0] + a1 * sud[c0 + 1] + a2 * sud[c0 + 2] + a3 * sud[c0 + 3];
            }
            int h8 = (kk & 1) * 2;
            split2(a0, a1, hb[h8],     lb[h8]);
            split2(a2, a3, hb[h8 + 1], lb[h8 + 1]);
            if (kk & 1) {
                uint32_t byte = (uint32_t)(tid * 128 + (kk >> 1) * 16);
                uint32_t swo = SW128(byte);
                uint4 h4 = make_uint4(hb[0], hb[1], hb[2], hb[3]);
                uint4 l4 = make_uint4(lb[0], lb[1], lb[2], lb[3]);
                *(uint4*)(sb_ + NOFF_AHI + swo) = h4;
                *(uint4*)(sb_ + NOFF_ALO + swo) = l4;
                if (act) { gh[kk >> 1] = h4; gl[kk >> 1] = l4; }
            }
        }
        if (act) {
            g_c_s[n] = cs + g_ec[0];
            g_c_d[n] = cd + g_ec[1];
        }
    }
    __syncthreads();

    uint32_t tmem;
    asm volatile("ld.shared.b32 %0, [%1];" : "=r"(tmem) : "r"(base_u + NOFF_TMP));

    // ---- both MMA passes, one commit ----
    if (tid == 0) {
        FENCE_PROXY();
        uint64_t aH = mkdesc(base_u + NOFF_AHI), aL = mkdesc(base_u + NOFF_ALO);
        uint64_t sH = mkdesc(base_u + NOFF_MSH), sL = mkdesc(base_u + NOFF_MSL);
        uint64_t dH = mkdesc(base_u + NOFF_MDH), dL = mkdesc(base_u + NOFF_MDL);
#pragma unroll
        for (int kc = 0; kc < 4; kc++) {
            mma_f16_ss(tmem, aH + kc * 2, sH + kc * 2, kc > 0 ? 1u : 0u);
            mma_f16_ss(tmem, aH + kc * 2, sL + kc * 2, 1u);
            mma_f16_ss(tmem, aL + kc * 2, sH + kc * 2, 1u);
        }
#pragma unroll
        for (int kc = 0; kc < 4; kc++) {
            mma_f16_ss(tmem + 64, aH + kc * 2, dH + kc * 2, kc > 0 ? 1u : 0u);
            mma_f16_ss(tmem + 64, aH + kc * 2, dL + kc * 2, 1u);
            mma_f16_ss(tmem + 64, aL + kc * 2, dH + kc * 2, 1u);
        }
        TC_COMMIT(base_u + NOFF_MBR);
    }

    mbar_wait(base_u + NOFF_MBR, 0);
    TC_FENCE_AFTER();

    {
        uint32_t d1[64];
        TC_LD_X32(d1, tmem);
        TC_LD_X32(d1 + 32, tmem + 32);
        TC_WAIT_LD();
        if (act) {
            float* qp = g_qh_s + (size_t)n * 64;
#pragma unroll
            for (int c = 0; c < 64; c += 4) {
                *(float4*)(qp + c) = make_float4(
                    __uint_as_float(d1[c])     + sds[c],
                    __uint_as_float(d1[c + 1]) + sds[c + 1],
                    __uint_as_float(d1[c + 2]) + sds[c + 2],
                    __uint_as_float(d1[c + 3]) + sds[c + 3]);
            }
        }
    }
    {
        uint32_t d2[64];
        TC_LD_X32(d2, tmem + 64);
        TC_LD_X32(d2 + 32, tmem + 96);
        TC_WAIT_LD();
        if (act) {
            float* qp = g_qh_d + (size_t)n * 64;
#pragma unroll
            for (int c = 0; c < 64; c += 4) {
                *(float4*)(qp + c) = make_float4(
                    __uint_as_float(d2[c])     + sdd[c],
                    __uint_as_float(d2[c + 1]) + sdd[c + 1],
                    __uint_as_float(d2[c + 2]) + sdd[c + 2],
                    __uint_as_float(d2[c + 3]) + sdd[c + 3]);
            }
        }
    }

    __syncthreads();
    if (tid == 0) MBAR_INVAL(base_u + NOFF_MBR);
    __syncthreads();
    if (wid == 0) TC_DEALLOC(tmem, 128);

#else   // ---------------- fp32 fallback (non-'a' PTX pass only) -------------
    if (act) {
        float xr[64];
        float s = 0.0f, t2 = 0.0f;
        for (int k = 0; k < 64; k++) {
            xr[k] = x[(size_t)n * 64 + k];
            s += xr[k]; t2 += xr[k] * xr[k];
        }
        float mu = s / 64.0f;
        float inv = rsqrtf(t2 / 64.0f - mu * mu + 1e-5f);
        float xn[64];
        float cs = 0.0f, cd = 0.0f;
        for (int k = 0; k < 64; k++) {
            xn[k] = (xr[k] - mu) * inv * gamma[k] + beta[k];
            cs += xn[k] * g_us[k];
            cd += xn[k] * g_ud[k];
        }
        g_c_s[n] = cs + g_ec[0];
        g_c_d[n] = cd + g_ec[1];
        for (int k2 = 0; k2 < 32; k2++) {
            uint32_t hp, lp;
            split2(xn[2 * k2], xn[2 * k2 + 1], hp, lp);
            g_xnh[(size_t)n * 32 + k2] = hp;
            g_xnl[(size_t)n * 32 + k2] = lp;
        }
        for (int c = 0; c < 64; c++) {
            float qs = g_ds[c], qd = g_dd[c];
            for (int j = 0; j < 64; j++) {
                qs += xn[j] * g_Ms[c * 64 + j];
                qd += xn[j] * g_Md[c * 64 + j];
            }
            g_qh_s[(size_t)n * 64 + c] = qs;
            g_qh_d[(size_t)n * 64 + c] = qd;
        }
    }
#endif
}

// ---------------- kernel 2: tensor-core edge kernel (persistent, 3 CTA/SM) ---
#define OFF_AHI 0
#define OFF_ALO 16384
#define OFF_W1H 32768
#define OFF_W1L 40960
#define OFF_W2H 49152
#define OFF_W2L 57344
#define OFF_SBT 65536
#define OFF_SBV 65792
#define OFF_WTL 66048
#define OFF_SDV 66304
#define OFF_TMP 66560
#define OFF_MBR 66568
#define EDGE_SMEM_BYTES (1024 + 66576 + 48)

__global__ __launch_bounds__(128)
void edge_tc_kernel(
    const int* __restrict__ ei, const float* __restrict__ etime,
    const float* __restrict__ Wt,
    const float* __restrict__ bt,
    const float* __restrict__ Wvs, const float* __restrict__ bvs,
    const float* __restrict__ Wvd, const float* __restrict__ bvd,
    int E)
{
    int tid = threadIdx.x;
    int bid = blockIdx.x;

    int cs = g_cnt[0], cd = g_cnt[1];
    int ts = (cs + 127) >> 7;
    int td = (cd + 127) >> 7;
    int total = ts + td;

#if TC_OK
    extern __shared__ char dsm_raw[];
    uint32_t raw_u = smem_u32(dsm_raw);
    uint32_t base_u = (raw_u + 1023u) & ~1023u;
    char* sb = dsm_raw + (base_u - raw_u);
    int wid = tid >> 5;

    if (wid == 0) {
        TC_ALLOC(base_u + OFF_TMP, 128);
        TC_RELINQ();
    }
    if (tid == 0) MBAR_INIT(base_u + OFF_MBR, 1);

    float* sbt  = (float*)(sb + OFF_SBT);
    float* sbv  = (float*)(sb + OFF_SBV);
    float* wtl  = (float*)(sb + OFF_WTL);
    float* sdiv = (float*)(sb + OFF_SDV);

    for (int i = tid; i < 2048; i += 128) {
        int m = i >> 5, k2 = (i & 31) * 2;
        uint32_t byte = (uint32_t)(m * 128 + k2 * 2);
        uint32_t swo = SW128(byte);
        uint32_t hp, lp;
        split2(Wt[m * 65 + k2], Wt[m * 65 + k2 + 1], hp, lp);
        *(uint32_t*)(sb + OFF_W1H + swo) = hp;
        *(uint32_t*)(sb + OFF_W1L + swo) = lp;
    }
    if (tid < 64) {
        sbt[tid] = bt[tid];
        wtl[tid] = Wt[tid * 65 + 64];
        sdiv[tid] = powf(10000.0f, -(float)(2 * (tid >> 1)) / 64.0f);
    }

    int cur_same = -1;
    int ph = 0;
    for (int ti = bid; ti < total; ti += gridDim.x) {
        int same, off, cnt;
        const int* list;
        if (ti < ts) {
            list = g_perm_s; off = ti << 7; cnt = min(128, cs - off); same = 1;
        } else {
            list = g_perm_d; off = (ti - ts) << 7; cnt = min(128, cd - off); same = 0;
        }
        const float* Wv = same ? Wvs : Wvd;
        const float* bv = same ? bvs : bvd;
        const float* qh = same ? g_qh_s : g_qh_d;
        const float* cv = same ? g_c_s  : g_c_d;

        __syncthreads();

        if (same != cur_same) {
            for (int i = tid; i < 2048; i += 128) {
                int m = i >> 5, k2 = (i & 31) * 2;
                uint32_t byte = (uint32_t)(m * 128 + k2 * 2);
                uint32_t swo = SW128(byte);
                uint32_t hp, lp;
                split2(Wv[m * 64 + k2], Wv[m * 64 + k2 + 1], hp, lp);
                *(uint32_t*)(sb + OFF_W2H + swo) = hp;
                *(uint32_t*)(sb + OFF_W2L + swo) = lp;
            }
            if (tid < 64) sbv[tid] = bv[tid];
            cur_same = same;
        }

        int e = tid;
        bool act = e < cnt;
        int src = 0, dn = 0; float t = 0.0f;
        if (act) {
            int pe = list[off + e];
            src = ei[pe]; dn = ei[E + pe]; t = etime[pe];
        }
        {
            const uint4* xh = (const uint4*)(g_xnh + (size_t)src * 32);
            const uint4* xl = (const uint4*)(g_xnl + (size_t)src * 32);
#pragma unroll
            for (int kk = 0; kk < 8; kk++) {
                uint4 h = act ? xh[kk] : make_uint4(0, 0, 0, 0);
                uint4 l = act ? xl[kk] : make_uint4(0, 0, 0, 0);
                uint32_t byte = (uint32_t)(e * 128 + kk * 16);
                uint32_t swo = SW128(byte);
                *(uint4*)(sb + OFF_AHI + swo) = h;
                *(uint4*)(sb + OFF_ALO + swo) = l;
            }
        }
        __syncthreads();

        uint32_t tmem;
        asm volatile("ld.shared.b32 %0, [%1];" : "=r"(tmem) : "r"(base_u + OFF_TMP));

        if (tid == 0) {
            FENCE_PROXY();
            uint64_t aH = mkdesc(base_u + OFF_AHI), aL = mkdesc(base_u + OFF_ALO);
            uint64_t bH = mkdesc(base_u + OFF_W1H), bL = mkdesc(base_u + OFF_W1L);
#pragma unroll
            for (int kc = 0; kc < 4; kc++) {
                mma_f16_ss(tmem, aH + kc * 2, bH + kc * 2, kc > 0 ? 1u : 0u);
                mma_f16_ss(tmem, aH + kc * 2, bL + kc * 2, 1u);
                mma_f16_ss(tmem, aL + kc * 2, bH + kc * 2, 1u);
            }
            TC_COMMIT(base_u + OFF_MBR);
        }

        float4 qv[16];
        {
            const float4* qp = (const float4*)(qh + (size_t)dn * 64);
#pragma unroll
            for (int i = 0; i < 16; i++) qv[i] = qp[i];
        }
        float cvd = cv[dn];

        mbar_wait(base_u + OFF_MBR, ph); ph ^= 1;
        TC_FENCE_AFTER();

        uint32_t d1[64];
        TC_LD_X32(d1, tmem);
        TC_LD_X32(d1 + 32, tmem + 32);
        TC_WAIT_LD();

        float ex = 0.0f;
        {
            float att = 0.0f;
            float t200 = t * 200.0f;
            uint32_t hbuf[4], lbuf[4];
#pragma unroll
            for (int m0 = 0; m0 < 64; m0 += 4) {
                float4 q4 = qv[m0 >> 2];
                float xt4[4];
#pragma unroll
                for (int j = 0; j < 4; j += 2) {
                    int m = m0 + j;
                    float arg = t200 * sdiv[m];
                    float sn = __sinf(arg), cc = __cosf(arg);
                    float xe = __uint_as_float(d1[m])     + sbt[m]     + t * wtl[m];
                    float xo = __uint_as_float(d1[m + 1]) + sbt[m + 1] + t * wtl[m + 1];
                    xt4[j]     = gelu_erf(xe) + sn;
                    xt4[j + 1] = gelu_erf(xo) + cc;
                }
                att += xt4[0] * q4.x + xt4[1] * q4.y + xt4[2] * q4.z + xt4[3] * q4.w;
                int half8 = (m0 & 4) ? 2 : 0;
                split2(xt4[0], xt4[1], hbuf[half8],     lbuf[half8]);
                split2(xt4[2], xt4[3], hbuf[half8 + 1], lbuf[half8 + 1]);
                if (m0 & 4) {
                    uint32_t byte = (uint32_t)(e * 128 + (m0 - 4) * 2);
                    uint32_t swo = SW128(byte);
                    *(uint4*)(sb + OFF_AHI + swo) = make_uint4(hbuf[0], hbuf[1], hbuf[2], hbuf[3]);
                    *(uint4*)(sb + OFF_ALO + swo) = make_uint4(lbuf[0], lbuf[1], lbuf[2], lbuf[3]);
                }
            }
            if (act) {
                ex = __expf((att + cvd) * 0.125f);
                atomicAdd(&g_den[dn], ex);
            }
        }
        __syncthreads();

        if (tid == 0) {
            FENCE_PROXY();
            uint64_t aH = mkdesc(base_u + OFF_AHI), aL = mkdesc(base_u + OFF_ALO);
            uint64_t bH = mkdesc(base_u + OFF_W2H), bL = mkdesc(base_u + OFF_W2L);
#pragma unroll
            for (int kc = 0; kc < 4; kc++) {
                mma_f16_ss(tmem + 64, aH + kc * 2, bH + kc * 2, kc > 0 ? 1u : 0u);
                mma_f16_ss(tmem + 64, aH + kc * 2, bL + kc * 2, 1u);
                mma_f16_ss(tmem + 64, aL + kc * 2, bH + kc * 2, 1u);
            }
            TC_COMMIT(base_u + OFF_MBR);
        }

        mbar_wait(base_u + OFF_MBR, ph); ph ^= 1;
        TC_FENCE_AFTER();

        uint32_t d2[64];
        TC_LD_X32(d2, tmem + 64);
        TC_LD_X32(d2 + 32, tmem + 96);
        TC_WAIT_LD();

        if (act) {
            float* dp = g_aggr + (size_t)dn * 64;
#pragma unroll
            for (int m0 = 0; m0 < 64; m0 += 4) {
                float v0 = (__uint_as_float(d2[m0])     + sbv[m0])     * ex;
                float v1 = (__uint_as_float(d2[m0 + 1]) + sbv[m0 + 1]) * ex;
                float v2 = (__uint_as_float(d2[m0 + 2]) + sbv[m0 + 2]) * ex;
                float v3 = (__uint_as_float(d2[m0 + 3]) + sbv[m0 + 3]) * ex;
                asm volatile("red.global.add.v4.f32 [%0], {%1, %2, %3, %4};"
                             :: "l"(dp + m0), "f"(v0), "f"(v1), "f"(v2), "f"(v3) : "memory");
            }
        }
    }

    __syncthreads();
    if (tid == 0) MBAR_INVAL(base_u + OFF_MBR);
    __syncthreads();
    {
        uint32_t tmem;
        asm volatile("ld.shared.b32 %0, [%1];" : "=r"(tmem) : "r"(base_u + OFF_TMP));
        if (wid == 0) TC_DEALLOC(tmem, 128);
    }

#else   // ---------------- fp32 fallback (non-'a' PTX pass only) -------------
    for (int ti = bid; ti < total; ti += gridDim.x) {
        int same, off, cnt;
        const int* list;
        if (ti < ts) { list = g_perm_s; off = ti << 7; cnt = min(128, cs - off); same = 1; }
        else         { list = g_perm_d; off = (ti - ts) << 7; cnt = min(128, cd - off); same = 0; }
        const float* Wv = same ? Wvs : Wvd;
        const float* bv = same ? bvs : bvd;
        const float* qh = same ? g_qh_s : g_qh_d;
        const float* cv = same ? g_c_s  : g_c_d;
        int e = tid;
        if (e < cnt) {
            int pe = list[off + e];
            int src = ei[pe], dn = ei[E + pe];
            float t = etime[pe];
            float t200 = t * 200.0f;
            float xrow[64];
            for (int k2 = 0; k2 < 32; k2++) {
                uint32_t h = g_xnh[(size_t)src * 32 + k2];
                uint32_t l = g_xnl[(size_t)src * 32 + k2];
                xrow[2 * k2]     = __uint_as_float(h << 16) + __uint_as_float(l << 16);
                xrow[2 * k2 + 1] = __uint_as_float(h & 0xffff0000u) + __uint_as_float(l & 0xffff0000u);
            }
            float xt[64];
            float att = 0.0f;
            for (int m = 0; m < 64; m++) {
                float a = bt[m] + t * Wt[m * 65 + 64];
                for (int k = 0; k < 64; k++) a += xrow[k] * Wt[m * 65 + k];
                float dv = powf(10000.0f, -(float)(2 * (m / 2)) / 64.0f);
                float te = (m & 1) ? cosf(t200 * dv) : sinf(t200 * dv);
                xt[m] = gelu_erf(a) + te;
                att += xt[m] * qh[(size_t)dn * 64 + m];
            }
            float ex = expf((att + cv[dn]) * 0.125f);
            atomicAdd(&g_den[dn], ex);
            for (int m = 0; m < 64; m++) {
                float v = bv[m];
                for (int k = 0; k < 64; k++) v += xt[k] * Wv[m * 64 + k];
                atomicAdd(&g_aggr[(size_t)dn * 64 + m], ex * v);
            }
        }
    }
#endif
}

// ---------------- kernel 5: epilogue (normalize) + cnt reset ------------------
__global__ void final_kernel(const float* __restrict__ x, float* __restrict__ out, int N) {
    int i = blockIdx.x * blockDim.x + threadIdx.x;
    if (i < N * D) {
        float den = g_den[i >> 6];
        out[i] = x[i] + gelu_erf(g_aggr[i] / (den + 1e-16f));
    }
    if (i == 0) { g_cnt[0] = 0; g_cnt[1] = 0; }
}

// ---------------- launch ------------------------------------------------------
extern "C" void kernel_launch(void* const* d_in, const int* in_sizes, int n_in,
                              void* d_out, int out_size) {
    const float* x     = (const float*)d_in[0];
    const int*   ei    = (const int*)  d_in[1];
    const float* etime = (const float*)d_in[2];
    const float* esame = (const float*)d_in[4];
    const float* lng   = (const float*)d_in[5];
    const float* lnb   = (const float*)d_in[6];
    const float* Wt    = (const float*)d_in[7];
    const float* bt    = (const float*)d_in[8];
    const float* Wq    = (const float*)d_in[9];
    const float* bq    = (const float*)d_in[10];
    const float* Wks   = (const float*)d_in[11];
    const float* bks   = (const float*)d_in[12];
    const float* Wkd   = (const float*)d_in[13];
    const float* bkd   = (const float*)d_in[14];
    const float* Wvs   = (const float*)d_in[15];
    const float* bvs   = (const float*)d_in[16];
    const float* Wvd   = (const float*)d_in[17];
    const float* bvd   = (const float*)d_in[18];
    float* out = (float*)d_out;

    int N = in_sizes[0] / D;
    int E = in_sizes[2];
    if (N > MAXN) N = MAXN;
    if (E > MAXE) E = MAXE;

    cudaFuncSetAttribute(node_tc_kernel, cudaFuncAttributeMaxDynamicSharedMemorySize,
                         NODE_SMEM_BYTES);
    cudaFuncSetAttribute(edge_tc_kernel, cudaFuncAttributeMaxDynamicSharedMemorySize,
                         EDGE_SMEM_BYTES);

    int max_tiles = (E + 127) / 128 + 2;
    int edge_grid = max_tiles < 444 ? max_tiles : 444;

    prep_kernel<<<2 + (E + 255) / 256, 256>>>(esame, Wq, bq, Wks, bks, Wkd, bkd, E, N);
    node_tc_kernel<<<(N + 127) / 128, 128, NODE_SMEM_BYTES>>>(x, lng, lnb, N);
    edge_tc_kernel<<<edge_grid, 128, EDGE_SMEM_BYTES>>>(
        ei, etime, Wt, bt, Wvs, bvs, Wvd, bvd, E);
    final_kernel<<<(N * D + 255) / 256, 256>>>(x, out, N);
}

// round 16
// speedup vs baseline: 1.3411x; 1.1085x over previous
#include <cuda_runtime.h>
#include <cuda_bf16.h>
#include <math.h>
#include <stdint.h>

#define MAXN 50000
#define MAXE 800000
#define D 64

// tcgen05 is arch-SPECIFIC: only emit it in the sm_103a/'a'-target device pass.
#if !defined(__CUDA_ARCH__) || defined(__CUDA_ARCH_FEAT_SM103_ALL) || \
    defined(__CUDA_ARCH_FEAT_SM100_ALL) || defined(__CUDA_ARCH_SPECIFIC__) || \
    defined(__CUDA_ARCH_FAMILY_SPECIFIC__)
#define TC_OK 1
#else
#define TC_OK 0
#endif

typedef unsigned long long ull;

// ---------------- scratch ---------------------------------------------------
__device__ uint32_t g_xnh[MAXN * 32];
__device__ uint32_t g_xnl[MAXN * 32];
__device__ float g_qh_s[MAXN * D];
__device__ float g_qh_d[MAXN * D];
__device__ float g_c_s [MAXN];
__device__ float g_c_d [MAXN];
__device__ float g_den [MAXN];        // zeroed in prep_kernel each run
__device__ float g_aggr[MAXN * D];    // zeroed in prep_kernel each run
__device__ int   g_perm_s[MAXE];
__device__ int   g_perm_d[MAXE];
__device__ int   g_cnt[2];            // static zero; reset by final_kernel
__device__ float g_Ms[4096];          // [c][j]
__device__ float g_Md[4096];
__device__ float g_ds[64], g_dd[64];
__device__ float g_us[64], g_ud[64];
__device__ float g_ec[2];

__device__ __forceinline__ float gelu_erf(float x) {
    return 0.5f * x * (1.0f + erff(x * 0.70710678118654752440f));
}

// ---------------- bf16 pack helpers ------------------------------------------
__device__ __forceinline__ uint32_t packbf(float x0, float x1) {
    uint32_t r;
    asm("cvt.rn.bf16x2.f32 %0, %2, %1;" : "=r"(r) : "f"(x0), "f"(x1));
    return r;
}
__device__ __forceinline__ void split2(float x0, float x1, uint32_t& hp, uint32_t& lp) {
    hp = packbf(x0, x1);
    float h0 = __uint_as_float(hp << 16);
    float h1 = __uint_as_float(hp & 0xffff0000u);
    lp = packbf(x0 - h0, x1 - h1);
}

__device__ __forceinline__ uint32_t smem_u32(const void* p) {
    uint32_t a;
    asm("{ .reg .u64 t; cvta.to.shared.u64 t, %1; cvt.u32.u64 %0, t; }"
        : "=r"(a) : "l"(p));
    return a;
}
#define SW128(o) ((o) ^ (((o) >> 3) & 0x70))

__device__ __forceinline__ uint64_t mkdesc(uint32_t addr) {
    const uint64_t base = (2ull << 61) | (1ull << 46) | (64ull << 32) | (1ull << 16);
    return base | ((addr >> 4) & 0x3FFF);
}

// idesc kind::f16, bf16 x bf16 -> f32, M=128, N=64
#define MMA_IDESC 0x08100490u

#if TC_OK
__device__ __forceinline__ void mma_f16_ss(uint32_t d_tmem, uint64_t a_desc,
                                           uint64_t b_desc, uint32_t en) {
    asm volatile(
        "{\n\t"
        ".reg .pred p;\n\t"
        "setp.ne.u32 p, %5, 0;\n\t"
        "tcgen05.mma.cta_group::1.kind::f16 [%0], %1, %2, %3, {%4, %4, %4, %4}, p;\n\t"
        "}"
        :: "r"(d_tmem), "l"(a_desc), "l"(b_desc), "r"(MMA_IDESC), "r"(0u), "r"(en)
        : "memory");
}

#define TC_ALLOC(smem_addr, n) \
    asm volatile("tcgen05.alloc.cta_group::1.sync.aligned.shared::cta.b32 [%0], %1;" \
                 :: "r"(smem_addr), "r"((uint32_t)(n)) : "memory")
#define TC_RELINQ() \
    asm volatile("tcgen05.relinquish_alloc_permit.cta_group::1.sync.aligned;")
#define TC_DEALLOC(tmem, n) \
    asm volatile("tcgen05.dealloc.cta_group::1.sync.aligned.b32 %0, %1;" \
                 :: "r"(tmem), "r"((uint32_t)(n)))
#define TC_COMMIT(mbar) \
    asm volatile("tcgen05.commit.cta_group::1.mbarrier::arrive::one.shared::cluster.b64 [%0];" \
                 :: "r"(mbar) : "memory")
#define TC_FENCE_AFTER() \
    asm volatile("tcgen05.fence::after_thread_sync;" ::: "memory")
#define TC_WAIT_LD() \
    asm volatile("tcgen05.wait::ld.sync.aligned;" ::: "memory")
#define FENCE_PROXY() \
    asm volatile("fence.proxy.async.shared::cta;" ::: "memory")
#define MBAR_INIT(mbar, n) \
    asm volatile("mbarrier.init.shared.b64 [%0], %1;" :: "r"(mbar), "r"((uint32_t)(n)) : "memory")
#define MBAR_INVAL(mbar) \
    asm volatile("mbarrier.inval.shared.b64 [%0];" :: "r"(mbar) : "memory")
#define CP_ASYNC16(dst_u32, gptr) \
    asm volatile("cp.async.cg.shared.global [%0], [%1], 16;" \
                 :: "r"(dst_u32), "l"(gptr) : "memory")
#define CP_COMMIT() asm volatile("cp.async.commit_group;" ::: "memory")
#define CP_WAIT0()  asm volatile("cp.async.wait_group 0;" ::: "memory")

__device__ __forceinline__ void mbar_wait(uint32_t mbar, uint32_t parity) {
    asm volatile(
        "{\n\t"
        ".reg .pred P;\n\t"
        "WLOOP%=:\n\t"
        "mbarrier.try_wait.parity.acquire.cta.shared::cta.b64 P, [%0], %1, 0x989680;\n\t"
        "@P bra.uni WDONE%=;\n\t"
        "bra.uni WLOOP%=;\n\t"
        "WDONE%=:\n\t"
        "}"
        :: "r"(mbar), "r"(parity) : "memory");
}

#define TC_LD_X32(r, tmem_addr) \
    asm volatile( \
        "tcgen05.ld.sync.aligned.32x32b.x32.b32 " \
        "{%0, %1, %2, %3, %4, %5, %6, %7, " \
        " %8, %9, %10, %11, %12, %13, %14, %15, " \
        " %16, %17, %18, %19, %20, %21, %22, %23, " \
        " %24, %25, %26, %27, %28, %29, %30, %31}, [%32];" \
        : "=r"((r)[0]),  "=r"((r)[1]),  "=r"((r)[2]),  "=r"((r)[3]), \
          "=r"((r)[4]),  "=r"((r)[5]),  "=r"((r)[6]),  "=r"((r)[7]), \
          "=r"((r)[8]),  "=r"((r)[9]),  "=r"((r)[10]), "=r"((r)[11]), \
          "=r"((r)[12]), "=r"((r)[13]), "=r"((r)[14]), "=r"((r)[15]), \
          "=r"((r)[16]), "=r"((r)[17]), "=r"((r)[18]), "=r"((r)[19]), \
          "=r"((r)[20]), "=r"((r)[21]), "=r"((r)[22]), "=r"((r)[23]), \
          "=r"((r)[24]), "=r"((r)[25]), "=r"((r)[26]), "=r"((r)[27]), \
          "=r"((r)[28]), "=r"((r)[29]), "=r"((r)[30]), "=r"((r)[31]) \
        : "r"(tmem_addr))
#endif  // TC_OK

// ---------------- kernel A: fold (blocks 0,1) + partition & zero (blocks>=2) --
__global__ __launch_bounds__(256) void prep_kernel(
    const float* __restrict__ esame,
    const float* __restrict__ Wq, const float* __restrict__ bq,
    const float* __restrict__ Wks, const float* __restrict__ bks,
    const float* __restrict__ Wkd, const float* __restrict__ bkd,
    int E, int N)
{
    __shared__ float sWq[4096], sWk[4096], sbq[64], sbk[64];
    int tid = threadIdx.x;
    int bidx = blockIdx.x;

    if (bidx < 2) {
        int b = bidx;
        const float* Wk = b ? Wkd : Wks;
        const float* bk = b ? bkd : bks;
        float* MT   = b ? g_Md : g_Ms;
        float* dvec = b ? g_dd : g_ds;
        float* uvec = b ? g_ud : g_us;

        for (int i = tid; i < 4096; i += 256) { sWq[i] = Wq[i]; sWk[i] = Wk[i]; }
        if (tid < 64) { sbq[tid] = bq[tid]; sbk[tid] = bk[tid]; }
        __syncthreads();
#pragma unroll
        for (int ii = 0; ii < 16; ii++) {
            int o = tid + ii * 256;
            int j = o >> 6, c = o & 63;
            float s = 0.0f;
#pragma unroll 8
            for (int m = 0; m < 64; m++) s += sWk[m * 64 + c] * sWq[m * 64 + j];
            MT[c * 64 + j] = s;
        }
        if (tid < 64) {
            float sd = 0.0f, su = 0.0f;
#pragma unroll 8
            for (int m = 0; m < 64; m++) {
                sd += sWk[m * 64 + tid] * sbq[m];
                su += sbk[m] * sWq[m * 64 + tid];
            }
            dvec[tid] = sd; uvec[tid] = su;
        }
        if (tid == 0) {
            float s = 0.0f;
            for (int m = 0; m < 64; m++) s += sbk[m] * sbq[m];
            g_ec[b] = s;
        }
    } else {
        int gi = (bidx - 2) * 256 + tid;
        {
            float4 z = make_float4(0.f, 0.f, 0.f, 0.f);
            int total4 = N * D / 4;
            int nthr = (gridDim.x - 2) * 256;
            for (int p = gi; p < total4; p += nthr)
                *(((float4*)g_aggr) + p) = z;
            if (gi < N) g_den[gi] = 0.0f;
        }
        int e = gi;
        int lane = tid & 31;
        bool act = e < E;
        float es = act ? esame[e] : 0.0f;
        bool s = act && (es >= 0.5f);
        bool d = act && (es < 0.5f);
        unsigned ms = __ballot_sync(0xffffffffu, s);
        unsigned md = __ballot_sync(0xffffffffu, d);
        int bs = 0, bd = 0;
        if (lane == 0) {
            if (ms) bs = atomicAdd(&g_cnt[0], __popc(ms));
            if (md) bd = atomicAdd(&g_cnt[1], __popc(md));
        }
        bs = __shfl_sync(0xffffffffu, bs, 0);
        bd = __shfl_sync(0xffffffffu, bd, 0);
        unsigned lower = (1u << lane) - 1u;
        if (s) g_perm_s[bs + __popc(ms & lower)] = e;
        if (d) g_perm_d[bd + __popc(md & lower)] = e;
    }
}

// ---------------- kernel 1: tensor-core node kernel ---------------------------
#define NOFF_AHI 0
#define NOFF_ALO 16384
#define NOFF_MSH 32768
#define NOFF_MSL 40960
#define NOFF_MDH 49152
#define NOFF_MDL 57344
#define NOFF_DS  65536
#define NOFF_DD  65792
#define NOFF_G   66048
#define NOFF_B   66304
#define NOFF_US  66560
#define NOFF_UD  66816
#define NOFF_TMP 67072
#define NOFF_MBR 67080
#define NODE_SMEM_BYTES (1024 + 67088 + 48)

__global__ __launch_bounds__(128)
void node_tc_kernel(const float* __restrict__ x, const float* __restrict__ gamma,
                    const float* __restrict__ beta, int N)
{
    int tid = threadIdx.x;
    int n0 = blockIdx.x * 128;
    int cnt = min(128, N - n0);
    int n = n0 + tid;
    bool act = tid < cnt;

#if TC_OK
    extern __shared__ char dsm_raw[];
    uint32_t raw_u = smem_u32(dsm_raw);
    uint32_t base_u = (raw_u + 1023u) & ~1023u;
    char* sb_ = dsm_raw + (base_u - raw_u);
    int wid = tid >> 5;

    if (wid == 0) {
        TC_ALLOC(base_u + NOFF_TMP, 128);
        TC_RELINQ();
    }
    if (tid == 0) MBAR_INIT(base_u + NOFF_MBR, 1);

    float* sds = (float*)(sb_ + NOFF_DS);
    float* sdd = (float*)(sb_ + NOFF_DD);
    float* sg  = (float*)(sb_ + NOFF_G);
    float* sbv = (float*)(sb_ + NOFF_B);
    float* sus = (float*)(sb_ + NOFF_US);
    float* sud = (float*)(sb_ + NOFF_UD);

    for (int i = tid; i < 2048; i += 128) {
        int c = i >> 5, k2 = (i & 31) * 2;
        uint32_t byte = (uint32_t)(c * 128 + k2 * 2);
        uint32_t swo = SW128(byte);
        uint32_t hp, lp;
        split2(g_Ms[c * 64 + k2], g_Ms[c * 64 + k2 + 1], hp, lp);
        *(uint32_t*)(sb_ + NOFF_MSH + swo) = hp;
        *(uint32_t*)(sb_ + NOFF_MSL + swo) = lp;
        split2(g_Md[c * 64 + k2], g_Md[c * 64 + k2 + 1], hp, lp);
        *(uint32_t*)(sb_ + NOFF_MDH + swo) = hp;
        *(uint32_t*)(sb_ + NOFF_MDL + swo) = lp;
    }
    if (tid < 64) {
        sds[tid] = g_ds[tid]; sdd[tid] = g_dd[tid];
        sg[tid] = gamma[tid]; sbv[tid] = beta[tid];
        sus[tid] = g_us[tid]; sud[tid] = g_ud[tid];
    }
    __syncthreads();

    float4 xv[16];
    float mu = 0.0f, inv = 0.0f;
    if (act) {
        const float4* xr = (const float4*)(x + (size_t)n * 64);
        float s = 0.0f, t2 = 0.0f;
#pragma unroll
        for (int kk = 0; kk < 16; kk++) {
            xv[kk] = xr[kk];
            s  += xv[kk].x + xv[kk].y + xv[kk].z + xv[kk].w;
            t2 += xv[kk].x * xv[kk].x + xv[kk].y * xv[kk].y
                + xv[kk].z * xv[kk].z + xv[kk].w * xv[kk].w;
        }
        mu = s * (1.0f / 64.0f);
        float var = t2 * (1.0f / 64.0f) - mu * mu;
        inv = rsqrtf(var + 1e-5f);
    }
    {
        float cs = 0.0f, cd = 0.0f;
        uint32_t hb[4], lb[4];
        uint4* gh = (uint4*)(g_xnh + (size_t)n * 32);
        uint4* gl = (uint4*)(g_xnl + (size_t)n * 32);
#pragma unroll
        for (int kk = 0; kk < 16; kk++) {
            float a0 = 0.f, a1 = 0.f, a2 = 0.f, a3 = 0.f;
            if (act) {
                int c0 = kk * 4;
                a0 = (xv[kk].x - mu) * inv * sg[c0]     + sbv[c0];
                a1 = (xv[kk].y - mu) * inv * sg[c0 + 1] + sbv[c0 + 1];
                a2 = (xv[kk].z - mu) * inv * sg[c0 + 2] + sbv[c0 + 2];
                a3 = (xv[kk].w - mu) * inv * sg[c0 + 3] + sbv[c0 + 3];
                cs += a0 * sus[c0] + a1 * sus[c0 + 1] + a2 * sus[c0 + 2] + a3 * sus[c0 + 3];
                cd += a0 * sud[c0] + a1 * sud[c0 + 1] + a2 * sud[c0 + 2] + a3 * sud[c0 + 3];
            }
            int h8 = (kk & 1) * 2;
            split2(a0, a1, hb[h8],     lb[h8]);
            split2(a2, a3, hb[h8 + 1], lb[h8 + 1]);
            if (kk & 1) {
                uint32_t byte = (uint32_t)(tid * 128 + (kk >> 1) * 16);
                uint32_t swo = SW128(byte);
                uint4 h4 = make_uint4(hb[0], hb[1], hb[2], hb[3]);
                uint4 l4 = make_uint4(lb[0], lb[1], lb[2], lb[3]);
                *(uint4*)(sb_ + NOFF_AHI + swo) = h4;
                *(uint4*)(sb_ + NOFF_ALO + swo) = l4;
                if (act) { gh[kk >> 1] = h4; gl[kk >> 1] = l4; }
            }
        }
        if (act) {
            g_c_s[n] = cs + g_ec[0];
            g_c_d[n] = cd + g_ec[1];
        }
    }
    __syncthreads();

    uint32_t tmem;
    asm volatile("ld.shared.b32 %0, [%1];" : "=r"(tmem) : "r"(base_u + NOFF_TMP));

    if (tid == 0) {
        FENCE_PROXY();
        uint64_t aH = mkdesc(base_u + NOFF_AHI), aL = mkdesc(base_u + NOFF_ALO);
        uint64_t sH = mkdesc(base_u + NOFF_MSH), sL = mkdesc(base_u + NOFF_MSL);
        uint64_t dH = mkdesc(base_u + NOFF_MDH), dL = mkdesc(base_u + NOFF_MDL);
#pragma unroll
        for (int kc = 0; kc < 4; kc++) {
            mma_f16_ss(tmem, aH + kc * 2, sH + kc * 2, kc > 0 ? 1u : 0u);
            mma_f16_ss(tmem, aH + kc * 2, sL + kc * 2, 1u);
            mma_f16_ss(tmem, aL + kc * 2, sH + kc * 2, 1u);
        }
#pragma unroll
        for (int kc = 0; kc < 4; kc++) {
            mma_f16_ss(tmem + 64, aH + kc * 2, dH + kc * 2, kc > 0 ? 1u : 0u);
            mma_f16_ss(tmem + 64, aH + kc * 2, dL + kc * 2, 1u);
            mma_f16_ss(tmem + 64, aL + kc * 2, dH + kc * 2, 1u);
        }
        TC_COMMIT(base_u + NOFF_MBR);
    }

    mbar_wait(base_u + NOFF_MBR, 0);
    TC_FENCE_AFTER();

    {
        uint32_t d1[64];
        TC_LD_X32(d1, tmem);
        TC_LD_X32(d1 + 32, tmem + 32);
        TC_WAIT_LD();
        if (act) {
            float* qp = g_qh_s + (size_t)n * 64;
#pragma unroll
            for (int c = 0; c < 64; c += 4) {
                *(float4*)(qp + c) = make_float4(
                    __uint_as_float(d1[c])     + sds[c],
                    __uint_as_float(d1[c + 1]) + sds[c + 1],
                    __uint_as_float(d1[c + 2]) + sds[c + 2],
                    __uint_as_float(d1[c + 3]) + sds[c + 3]);
            }
        }
    }
    {
        uint32_t d2[64];
        TC_LD_X32(d2, tmem + 64);
        TC_LD_X32(d2 + 32, tmem + 96);
        TC_WAIT_LD();
        if (act) {
            float* qp = g_qh_d + (size_t)n * 64;
#pragma unroll
            for (int c = 0; c < 64; c += 4) {
                *(float4*)(qp + c) = make_float4(
                    __uint_as_float(d2[c])     + sdd[c],
                    __uint_as_float(d2[c + 1]) + sdd[c + 1],
                    __uint_as_float(d2[c + 2]) + sdd[c + 2],
                    __uint_as_float(d2[c + 3]) + sdd[c + 3]);
            }
        }
    }

    __syncthreads();
    if (tid == 0) MBAR_INVAL(base_u + NOFF_MBR);
    __syncthreads();
    if (wid == 0) TC_DEALLOC(tmem, 128);

#else
    if (act) {
        float xr[64];
        float s = 0.0f, t2 = 0.0f;
        for (int k = 0; k < 64; k++) {
            xr[k] = x[(size_t)n * 64 + k];
            s += xr[k]; t2 += xr[k] * xr[k];
        }
        float mu = s / 64.0f;
        float inv = rsqrtf(t2 / 64.0f - mu * mu + 1e-5f);
        float xn[64];
        float cs = 0.0f, cd = 0.0f;
        for (int k = 0; k < 64; k++) {
            xn[k] = (xr[k] - mu) * inv * gamma[k] + beta[k];
            cs += xn[k] * g_us[k];
            cd += xn[k] * g_ud[k];
        }
        g_c_s[n] = cs + g_ec[0];
        g_c_d[n] = cd + g_ec[1];
        for (int k2 = 0; k2 < 32; k2++) {
            uint32_t hp, lp;
            split2(xn[2 * k2], xn[2 * k2 + 1], hp, lp);
            g_xnh[(size_t)n * 32 + k2] = hp;
            g_xnl[(size_t)n * 32 + k2] = lp;
        }
        for (int c = 0; c < 64; c++) {
            float qs = g_ds[c], qd = g_dd[c];
            for (int j = 0; j < 64; j++) {
                qs += xn[j] * g_Ms[c * 64 + j];
                qd += xn[j] * g_Md[c * 64 + j];
            }
            g_qh_s[(size_t)n * 64 + c] = qs;
            g_qh_d[(size_t)n * 64 + c] = qd;
        }
    }
#endif
}

// ---------------- kernel 2: pipelined tensor-core edge kernel -----------------
#define OFF_AHI 0
#define OFF_ALO 16384
#define OFF_W1H 32768
#define OFF_W1L 40960
#define OFF_W2H 49152
#define OFF_W2L 57344
#define OFF_SBT 65536
#define OFF_SBV 65792
#define OFF_WTL 66048
#define OFF_SDV 66304
#define OFF_TMP 66560
#define OFF_MBR 66568
#define EDGE_SMEM_BYTES (1024 + 66576 + 48)

#if TC_OK
// issue async gather of one edge row into A buffers (or zero-fill if inactive)
__device__ __forceinline__ void gather_async(char* sb, uint32_t base_u, int e,
                                             bool act, int src) {
    const uint32_t* xh = g_xnh + (size_t)src * 32;
    const uint32_t* xl = g_xnl + (size_t)src * 32;
#pragma unroll
    for (int kk = 0; kk < 8; kk++) {
        uint32_t byte = (uint32_t)(e * 128 + kk * 16);
        uint32_t swo = SW128(byte);
        if (act) {
            CP_ASYNC16(base_u + OFF_AHI + swo, xh + kk * 4);
            CP_ASYNC16(base_u + OFF_ALO + swo, xl + kk * 4);
        } else {
            uint4 z = make_uint4(0, 0, 0, 0);
            *(uint4*)(sb + OFF_AHI + swo) = z;
            *(uint4*)(sb + OFF_ALO + swo) = z;
        }
    }
    CP_COMMIT();
}
#endif

__global__ __launch_bounds__(128)
void edge_tc_kernel(
    const int* __restrict__ ei, const float* __restrict__ etime,
    const float* __restrict__ Wt,
    const float* __restrict__ bt,
    const float* __restrict__ Wvs, const float* __restrict__ bvs,
    const float* __restrict__ Wvd, const float* __restrict__ bvd,
    int E)
{
    int tid = threadIdx.x;
    int bid = blockIdx.x;

    int cs = g_cnt[0], cd = g_cnt[1];
    int ts = (cs + 127) >> 7;
    int td = (cd + 127) >> 7;
    int total = ts + td;

#if TC_OK
    extern __shared__ char dsm_raw[];
    uint32_t raw_u = smem_u32(dsm_raw);
    uint32_t base_u = (raw_u + 1023u) & ~1023u;
    char* sb = dsm_raw + (base_u - raw_u);
    int wid = tid >> 5;

    if (wid == 0) {
        TC_ALLOC(base_u + OFF_TMP, 128);
        TC_RELINQ();
    }
    if (tid == 0) MBAR_INIT(base_u + OFF_MBR, 1);

    float* sbt  = (float*)(sb + OFF_SBT);
    float* sbv  = (float*)(sb + OFF_SBV);
    float* wtl  = (float*)(sb + OFF_WTL);
    float* sdiv = (float*)(sb + OFF_SDV);

    // ---- one-time: W1 (= Wt), bt, wtl, sdiv ----
    for (int i = tid; i < 2048; i += 128) {
        int m = i >> 5, k2 = (i & 31) * 2;
        uint32_t byte = (uint32_t)(m * 128 + k2 * 2);
        uint32_t swo = SW128(byte);
        uint32_t hp, lp;
        split2(Wt[m * 65 + k2], Wt[m * 65 + k2 + 1], hp, lp);
        *(uint32_t*)(sb + OFF_W1H + swo) = hp;
        *(uint32_t*)(sb + OFF_W1L + swo) = lp;
    }
    if (tid < 64) {
        sbt[tid] = bt[tid];
        wtl[tid] = Wt[tid * 65 + 64];
        sdiv[tid] = powf(10000.0f, -(float)(2 * (tid >> 1)) / 64.0f);
    }

    // ---- prologue gather for first tile ----
    int ti = bid;
    bool c_act = false; int c_dn = 0; float c_t = 0.0f;
    if (ti < total) {
        const int* list; int off, cnt;
        if (ti < ts) { list = g_perm_s; off = ti << 7; cnt = min(128, cs - off); }
        else         { list = g_perm_d; off = (ti - ts) << 7; cnt = min(128, cd - off); }
        int src = 0;
        if (tid < cnt) {
            int pe = list[off + tid];
            src = ei[pe]; c_dn = ei[E + pe]; c_t = etime[pe];
            c_act = true;
        }
        gather_async(sb, base_u, tid, c_act, src);
    } else {
        CP_COMMIT();
    }

    int cur_same = -1;
    int ph = 0;
    for (; ti < total; ti += gridDim.x) {
        int same = (ti < ts) ? 1 : 0;
        const float* Wv = same ? Wvs : Wvd;
        const float* bv = same ? bvs : bvd;
        const float* qh = same ? g_qh_s : g_qh_d;
        const float* cv = same ? g_c_s  : g_c_d;

        CP_WAIT0();
        __syncthreads();   // gather visible; prev tile fully done with smem

        if (same != cur_same) {
            for (int i = tid; i < 2048; i += 128) {
                int m = i >> 5, k2 = (i & 31) * 2;
                uint32_t byte = (uint32_t)(m * 128 + k2 * 2);
                uint32_t swo = SW128(byte);
                uint32_t hp, lp;
                split2(Wv[m * 64 + k2], Wv[m * 64 + k2 + 1], hp, lp);
                *(uint32_t*)(sb + OFF_W2H + swo) = hp;
                *(uint32_t*)(sb + OFF_W2L + swo) = lp;
            }
            if (tid < 64) sbv[tid] = bv[tid];
            cur_same = same;
        }

        uint32_t tmem;
        asm volatile("ld.shared.b32 %0, [%1];" : "=r"(tmem) : "r"(base_u + OFF_TMP));

        // ---- MMA1 ----
        if (tid == 0) {
            FENCE_PROXY();
            uint64_t aH = mkdesc(base_u + OFF_AHI), aL = mkdesc(base_u + OFF_ALO);
            uint64_t bH = mkdesc(base_u + OFF_W1H), bL = mkdesc(base_u + OFF_W1L);
#pragma unroll
            for (int kc = 0; kc < 4; kc++) {
                mma_f16_ss(tmem, aH + kc * 2, bH + kc * 2, kc > 0 ? 1u : 0u);
                mma_f16_ss(tmem, aH + kc * 2, bL + kc * 2, 1u);
                mma_f16_ss(tmem, aL + kc * 2, bH + kc * 2, 1u);
            }
            TC_COMMIT(base_u + OFF_MBR);
        }

        // ---- prefetch q-row while MMA1 runs ----
        float4 qv[16];
        {
            const float4* qp = (const float4*)(qh + (size_t)c_dn * 64);
#pragma unroll
            for (int i = 0; i < 16; i++) qv[i] = qp[i];
        }
        float cvd = cv[c_dn];

        mbar_wait(base_u + OFF_MBR, ph); ph ^= 1;
        TC_FENCE_AFTER();

        // ---- epilogue 1 ----
        uint32_t d1[64];
        TC_LD_X32(d1, tmem);
        TC_LD_X32(d1 + 32, tmem + 32);
        TC_WAIT_LD();

        float ex = 0.0f;
        {
            float att = 0.0f;
            float t200 = c_t * 200.0f;
            uint32_t hbuf[4], lbuf[4];
#pragma unroll
            for (int m0 = 0; m0 < 64; m0 += 4) {
                float4 q4 = qv[m0 >> 2];
                float xt4[4];
#pragma unroll
                for (int j = 0; j < 4; j += 2) {
                    int m = m0 + j;
                    float arg = t200 * sdiv[m];
                    float sn = __sinf(arg), cc = __cosf(arg);
                    float xe = __uint_as_float(d1[m])     + sbt[m]     + c_t * wtl[m];
                    float xo = __uint_as_float(d1[m + 1]) + sbt[m + 1] + c_t * wtl[m + 1];
                    xt4[j]     = gelu_erf(xe) + sn;
                    xt4[j + 1] = gelu_erf(xo) + cc;
                }
                att += xt4[0] * q4.x + xt4[1] * q4.y + xt4[2] * q4.z + xt4[3] * q4.w;
                int half8 = (m0 & 4) ? 2 : 0;
                split2(xt4[0], xt4[1], hbuf[half8],     lbuf[half8]);
                split2(xt4[2], xt4[3], hbuf[half8 + 1], lbuf[half8 + 1]);
                if (m0 & 4) {
                    uint32_t byte = (uint32_t)(tid * 128 + (m0 - 4) * 2);
                    uint32_t swo = SW128(byte);
                    *(uint4*)(sb + OFF_AHI + swo) = make_uint4(hbuf[0], hbuf[1], hbuf[2], hbuf[3]);
                    *(uint4*)(sb + OFF_ALO + swo) = make_uint4(lbuf[0], lbuf[1], lbuf[2], lbuf[3]);
                }
            }
            if (c_act) {
                ex = __expf((att + cvd) * 0.125f);
                atomicAdd(&g_den[c_dn], ex);
            }
        }
        __syncthreads();

        // ---- MMA2 ----
        if (tid == 0) {
            FENCE_PROXY();
            uint64_t aH = mkdesc(base_u + OFF_AHI), aL = mkdesc(base_u + OFF_ALO);
            uint64_t bH = mkdesc(base_u + OFF_W2H), bL = mkdesc(base_u + OFF_W2L);
#pragma unroll
            for (int kc = 0; kc < 4; kc++) {
                mma_f16_ss(tmem + 64, aH + kc * 2, bH + kc * 2, kc > 0 ? 1u : 0u);
                mma_f16_ss(tmem + 64, aH + kc * 2, bL + kc * 2, 1u);
                mma_f16_ss(tmem + 64, aL + kc * 2, bH + kc * 2, 1u);
            }
            TC_COMMIT(base_u + OFF_MBR);
        }

        // ---- prefetch next tile meta while MMA2 runs ----
        int tn = ti + gridDim.x;
        bool n_act = false; int n_src = 0, n_dn = 0; float n_t = 0.0f;
        if (tn < total) {
            const int* nlist; int noff, ncnt;
            if (tn < ts) { nlist = g_perm_s; noff = tn << 7; ncnt = min(128, cs - noff); }
            else         { nlist = g_perm_d; noff = (tn - ts) << 7; ncnt = min(128, cd - noff); }
            if (tid < ncnt) {
                int pe = nlist[noff + tid];
                n_src = ei[pe]; n_dn = ei[E + pe]; n_t = etime[pe];
                n_act = true;
            }
        }

        mbar_wait(base_u + OFF_MBR, ph); ph ^= 1;
        TC_FENCE_AFTER();

        uint32_t d2[64];
        TC_LD_X32(d2, tmem + 64);
        TC_LD_X32(d2 + 32, tmem + 96);
        TC_WAIT_LD();

        // ---- A buffers now free: issue next tile's gather (overlaps reds) ----
        if (tn < total) gather_async(sb, base_u, tid, n_act, n_src);

        if (c_act) {
            float* dp = g_aggr + (size_t)c_dn * 64;
#pragma unroll
            for (int m0 = 0; m0 < 64; m0 += 4) {
                float v0 = (__uint_as_float(d2[m0])     + sbv[m0])     * ex;
                float v1 = (__uint_as_float(d2[m0 + 1]) + sbv[m0 + 1]) * ex;
                float v2 = (__uint_as_float(d2[m0 + 2]) + sbv[m0 + 2]) * ex;
                float v3 = (__uint_as_float(d2[m0 + 3]) + sbv[m0 + 3]) * ex;
                asm volatile("red.global.add.v4.f32 [%0], {%1, %2, %3, %4};"
                             :: "l"(dp + m0), "f"(v0), "f"(v1), "f"(v2), "f"(v3) : "memory");
            }
        }

        c_act = n_act; c_dn = n_dn; c_t = n_t;
    }

    CP_WAIT0();
    __syncthreads();
    if (tid == 0) MBAR_INVAL(base_u + OFF_MBR);
    __syncthreads();
    {
        uint32_t tmem;
        asm volatile("ld.shared.b32 %0, [%1];" : "=r"(tmem) : "r"(base_u + OFF_TMP));
        if (wid == 0) TC_DEALLOC(tmem, 128);
    }

#else   // ---------------- fp32 fallback (non-'a' PTX pass only) -------------
    for (int ti = bid; ti < total; ti += gridDim.x) {
        int same, off, cnt;
        const int* list;
        if (ti < ts) { list = g_perm_s; off = ti << 7; cnt = min(128, cs - off); same = 1; }
        else         { list = g_perm_d; off = (ti - ts) << 7; cnt = min(128, cd - off); same = 0; }
        const float* Wv = same ? Wvs : Wvd;
        const float* bv = same ? bvs : bvd;
        const float* qh = same ? g_qh_s : g_qh_d;
        const float* cv = same ? g_c_s  : g_c_d;
        int e = tid;
        if (e < cnt) {
            int pe = list[off + e];
            int src = ei[pe], dn = ei[E + pe];
            float t = etime[pe];
            float t200 = t * 200.0f;
            float xrow[64];
            for (int k2 = 0; k2 < 32; k2++) {
                uint32_t h = g_xnh[(size_t)src * 32 + k2];
                uint32_t l = g_xnl[(size_t)src * 32 + k2];
                xrow[2 * k2]     = __uint_as_float(h << 16) + __uint_as_float(l << 16);
                xrow[2 * k2 + 1] = __uint_as_float(h & 0xffff0000u) + __uint_as_float(l & 0xffff0000u);
            }
            float xt[64];
            float att = 0.0f;
            for (int m = 0; m < 64; m++) {
                float a = bt[m] + t * Wt[m * 65 + 64];
                for (int k = 0; k < 64; k++) a += xrow[k] * Wt[m * 65 + k];
                float dv = powf(10000.0f, -(float)(2 * (m / 2)) / 64.0f);
                float te = (m & 1) ? cosf(t200 * dv) : sinf(t200 * dv);
                xt[m] = gelu_erf(a) + te;
                att += xt[m] * qh[(size_t)dn * 64 + m];
            }
            float ex = expf((att + cv[dn]) * 0.125f);
            atomicAdd(&g_den[dn], ex);
            for (int m = 0; m < 64; m++) {
                float v = bv[m];
                for (int k = 0; k < 64; k++) v += xt[k] * Wv[m * 64 + k];
                atomicAdd(&g_aggr[(size_t)dn * 64 + m], ex * v);
            }
        }
    }
#endif
}

// ---------------- kernel 5: epilogue (normalize) + cnt reset ------------------
__global__ void final_kernel(const float* __restrict__ x, float* __restrict__ out, int N) {
    int i = blockIdx.x * blockDim.x + threadIdx.x;
    if (i < N * D) {
        float den = g_den[i >> 6];
        out[i] = x[i] + gelu_erf(g_aggr[i] / (den + 1e-16f));
    }
    if (i == 0) { g_cnt[0] = 0; g_cnt[1] = 0; }
}

// ---------------- launch ------------------------------------------------------
extern "C" void kernel_launch(void* const* d_in, const int* in_sizes, int n_in,
                              void* d_out, int out_size) {
    const float* x     = (const float*)d_in[0];
    const int*   ei    = (const int*)  d_in[1];
    const float* etime = (const float*)d_in[2];
    const float* esame = (const float*)d_in[4];
    const float* lng   = (const float*)d_in[5];
    const float* lnb   = (const float*)d_in[6];
    const float* Wt    = (const float*)d_in[7];
    const float* bt    = (const float*)d_in[8];
    const float* Wq    = (const float*)d_in[9];
    const float* bq    = (const float*)d_in[10];
    const float* Wks   = (const float*)d_in[11];
    const float* bks   = (const float*)d_in[12];
    const float* Wkd   = (const float*)d_in[13];
    const float* bkd   = (const float*)d_in[14];
    const float* Wvs   = (const float*)d_in[15];
    const float* bvs   = (const float*)d_in[16];
    const float* Wvd   = (const float*)d_in[17];
    const float* bvd   = (const float*)d_in[18];
    float* out = (float*)d_out;

    int N = in_sizes[0] / D;
    int E = in_sizes[2];
    if (N > MAXN) N = MAXN;
    if (E > MAXE) E = MAXE;

    cudaFuncSetAttribute(node_tc_kernel, cudaFuncAttributeMaxDynamicSharedMemorySize,
                         NODE_SMEM_BYTES);
    cudaFuncSetAttribute(edge_tc_kernel, cudaFuncAttributeMaxDynamicSharedMemorySize,
                         EDGE_SMEM_BYTES);

    int max_tiles = (E + 127) / 128 + 2;
    int edge_grid = max_tiles < 444 ? max_tiles : 444;

    prep_kernel<<<2 + (E + 255) / 256, 256>>>(esame, Wq, bq, Wks, bks, Wkd, bkd, E, N);
    node_tc_kernel<<<(N + 127) / 128, 128, NODE_SMEM_BYTES>>>(x, lng, lnb, N);
    edge_tc_kernel<<<edge_grid, 128, EDGE_SMEM_BYTES>>>(
        ei, etime, Wt, bt, Wvs, bvs, Wvd, bvd, E);
    final_kernel<<<(N * D + 255) / 256, 256>>>(x, out, N);
}

// round 17
// speedup vs baseline: 1.3963x; 1.0412x over previous
#include <cuda_runtime.h>
#include <cuda_bf16.h>
#include <math.h>
#include <stdint.h>

#define MAXN 50000
#define MAXE 800000
#define D 64

// tcgen05 is arch-SPECIFIC: only emit it in the sm_103a/'a'-target device pass.
#if !defined(__CUDA_ARCH__) || defined(__CUDA_ARCH_FEAT_SM103_ALL) || \
    defined(__CUDA_ARCH_FEAT_SM100_ALL) || defined(__CUDA_ARCH_SPECIFIC__) || \
    defined(__CUDA_ARCH_FAMILY_SPECIFIC__)
#define TC_OK 1
#else
#define TC_OK 0
#endif

typedef unsigned long long ull;

// ---------------- scratch ---------------------------------------------------
__device__ uint32_t g_xnh[MAXN * 32];
__device__ uint32_t g_xnl[MAXN * 32];
__device__ float g_qh_s[MAXN * D];
__device__ float g_qh_d[MAXN * D];
__device__ float g_c_s [MAXN];
__device__ float g_c_d [MAXN];
__device__ float g_den [MAXN];        // zeroed in prep_kernel each run
__device__ float g_aggr[MAXN * D];    // static zero; re-zeroed by final_kernel
__device__ int   g_perm_s[MAXE];
__device__ int   g_perm_d[MAXE];
__device__ int   g_cnt[2];            // static zero; reset by final_kernel
__device__ float g_Ms[4096];          // fp32 (fallback path)
__device__ float g_Md[4096];
__device__ float g_ds[64], g_dd[64];
__device__ float g_us[64], g_ud[64];
__device__ float g_ec[2];
__device__ float g_wtl[64];
// pre-split, pre-swizzled bf16 hi/lo weights (word index = swizzled byte/4)
__device__ uint32_t g_W1h[2048], g_W1l[2048];
__device__ uint32_t g_W2sh[2048], g_W2sl[2048];
__device__ uint32_t g_W2dh[2048], g_W2dl[2048];
__device__ uint32_t g_Msh[2048], g_Msl[2048];
__device__ uint32_t g_Mdh[2048], g_Mdl[2048];

__device__ __forceinline__ float gelu_erf(float x) {
    return 0.5f * x * (1.0f + erff(x * 0.70710678118654752440f));
}

// ---------------- bf16 pack helpers ------------------------------------------
__device__ __forceinline__ uint32_t packbf(float x0, float x1) {
    uint32_t r;
    asm("cvt.rn.bf16x2.f32 %0, %2, %1;" : "=r"(r) : "f"(x0), "f"(x1));
    return r;
}
__device__ __forceinline__ void split2(float x0, float x1, uint32_t& hp, uint32_t& lp) {
    hp = packbf(x0, x1);
    float h0 = __uint_as_float(hp << 16);
    float h1 = __uint_as_float(hp & 0xffff0000u);
    lp = packbf(x0 - h0, x1 - h1);
}

__device__ __forceinline__ uint32_t smem_u32(const void* p) {
    uint32_t a;
    asm("{ .reg .u64 t; cvta.to.shared.u64 t, %1; cvt.u32.u64 %0, t; }"
        : "=r"(a) : "l"(p));
    return a;
}
#define SW128(o) ((o) ^ (((o) >> 3) & 0x70))

__device__ __forceinline__ uint64_t mkdesc(uint32_t addr) {
    const uint64_t base = (2ull << 61) | (1ull << 46) | (64ull << 32) | (1ull << 16);
    return base | ((addr >> 4) & 0x3FFF);
}

// idesc kind::f16, bf16 x bf16 -> f32, M=128, N=64
#define MMA_IDESC 0x08100490u

#if TC_OK
__device__ __forceinline__ void mma_f16_ss(uint32_t d_tmem, uint64_t a_desc,
                                           uint64_t b_desc, uint32_t en) {
    asm volatile(
        "{\n\t"
        ".reg .pred p;\n\t"
        "setp.ne.u32 p, %5, 0;\n\t"
        "tcgen05.mma.cta_group::1.kind::f16 [%0], %1, %2, %3, {%4, %4, %4, %4}, p;\n\t"
        "}"
        :: "r"(d_tmem), "l"(a_desc), "l"(b_desc), "r"(MMA_IDESC), "r"(0u), "r"(en)
        : "memory");
}

#define TC_ALLOC(smem_addr, n) \
    asm volatile("tcgen05.alloc.cta_group::1.sync.aligned.shared::cta.b32 [%0], %1;" \
                 :: "r"(smem_addr), "r"((uint32_t)(n)) : "memory")
#define TC_RELINQ() \
    asm volatile("tcgen05.relinquish_alloc_permit.cta_group::1.sync.aligned;")
#define TC_DEALLOC(tmem, n) \
    asm volatile("tcgen05.dealloc.cta_group::1.sync.aligned.b32 %0, %1;" \
                 :: "r"(tmem), "r"((uint32_t)(n)))
#define TC_COMMIT(mbar) \
    asm volatile("tcgen05.commit.cta_group::1.mbarrier::arrive::one.shared::cluster.b64 [%0];" \
                 :: "r"(mbar) : "memory")
#define TC_FENCE_AFTER() \
    asm volatile("tcgen05.fence::after_thread_sync;" ::: "memory")
#define TC_WAIT_LD() \
    asm volatile("tcgen05.wait::ld.sync.aligned;" ::: "memory")
#define FENCE_PROXY() \
    asm volatile("fence.proxy.async.shared::cta;" ::: "memory")
#define MBAR_INIT(mbar, n) \
    asm volatile("mbarrier.init.shared.b64 [%0], %1;" :: "r"(mbar), "r"((uint32_t)(n)) : "memory")
#define MBAR_INVAL(mbar) \
    asm volatile("mbarrier.inval.shared.b64 [%0];" :: "r"(mbar) : "memory")
#define CP_ASYNC16(dst_u32, gptr) \
    asm volatile("cp.async.cg.shared.global [%0], [%1], 16;" \
                 :: "r"(dst_u32), "l"(gptr) : "memory")
#define CP_COMMIT() asm volatile("cp.async.commit_group;" ::: "memory")
#define CP_WAIT0()  asm volatile("cp.async.wait_group 0;" ::: "memory")

__device__ __forceinline__ void mbar_wait(uint32_t mbar, uint32_t parity) {
    asm volatile(
        "{\n\t"
        ".reg .pred P;\n\t"
        "WLOOP%=:\n\t"
        "mbarrier.try_wait.parity.acquire.cta.shared::cta.b64 P, [%0], %1, 0x989680;\n\t"
        "@P bra.uni WDONE%=;\n\t"
        "bra.uni WLOOP%=;\n\t"
        "WDONE%=:\n\t"
        "}"
        :: "r"(mbar), "r"(parity) : "memory");
}

#define TC_LD_X32(r, tmem_addr) \
    asm volatile( \
        "tcgen05.ld.sync.aligned.32x32b.x32.b32 " \
        "{%0, %1, %2, %3, %4, %5, %6, %7, " \
        " %8, %9, %10, %11, %12, %13, %14, %15, " \
        " %16, %17, %18, %19, %20, %21, %22, %23, " \
        " %24, %25, %26, %27, %28, %29, %30, %31}, [%32];" \
        : "=r"((r)[0]),  "=r"((r)[1]),  "=r"((r)[2]),  "=r"((r)[3]), \
          "=r"((r)[4]),  "=r"((r)[5]),  "=r"((r)[6]),  "=r"((r)[7]), \
          "=r"((r)[8]),  "=r"((r)[9]),  "=r"((r)[10]), "=r"((r)[11]), \
          "=r"((r)[12]), "=r"((r)[13]), "=r"((r)[14]), "=r"((r)[15]), \
          "=r"((r)[16]), "=r"((r)[17]), "=r"((r)[18]), "=r"((r)[19]), \
          "=r"((r)[20]), "=r"((r)[21]), "=r"((r)[22]), "=r"((r)[23]), \
          "=r"((r)[24]), "=r"((r)[25]), "=r"((r)[26]), "=r"((r)[27]), \
          "=r"((r)[28]), "=r"((r)[29]), "=r"((r)[30]), "=r"((r)[31]) \
        : "r"(tmem_addr))
#endif  // TC_OK

// split an m-major [64x64] weight block into packed swizzled bf16 hi/lo arrays
__device__ __forceinline__ void split_weight_block(
    const float* __restrict__ W, int row_stride, int tid,
    uint32_t* __restrict__ oh, uint32_t* __restrict__ ol)
{
    for (int p = tid; p < 2048; p += 256) {
        int m = p >> 5, k2 = (p & 31) * 2;
        uint32_t byte = (uint32_t)(m * 128 + (p & 31) * 4);
        uint32_t swo = SW128(byte);
        uint32_t hp, lp;
        split2(W[m * row_stride + k2], W[m * row_stride + k2 + 1], hp, lp);
        oh[swo >> 2] = hp;
        ol[swo >> 2] = lp;
    }
}

// ---------------- kernel A: fold+split (blocks 0-4) + partition (blocks>=5) --
__global__ __launch_bounds__(256) void prep_kernel(
    const float* __restrict__ esame,
    const float* __restrict__ Wq, const float* __restrict__ bq,
    const float* __restrict__ Wks, const float* __restrict__ bks,
    const float* __restrict__ Wkd, const float* __restrict__ bkd,
    const float* __restrict__ Wt,
    const float* __restrict__ Wvs, const float* __restrict__ Wvd,
    int E, int N)
{
    __shared__ float sWq[4096], sWk[4096], sbq[64], sbk[64];
    int tid = threadIdx.x;
    int bidx = blockIdx.x;

    if (bidx < 2) {
        // ---- fold + split M into packed bf16 ----
        int b = bidx;
        const float* Wk = b ? Wkd : Wks;
        const float* bk = b ? bkd : bks;
        float* MT   = b ? g_Md : g_Ms;
        float* dvec = b ? g_dd : g_ds;
        float* uvec = b ? g_ud : g_us;
        uint32_t* mh = b ? g_Mdh : g_Msh;
        uint32_t* ml = b ? g_Mdl : g_Msl;

        for (int i = tid; i < 4096; i += 256) { sWq[i] = Wq[i]; sWk[i] = Wk[i]; }
        if (tid < 64) { sbq[tid] = bq[tid]; sbk[tid] = bk[tid]; }
        __syncthreads();
#pragma unroll
        for (int ii = 0; ii < 16; ii++) {
            int o = tid + ii * 256;
            int j = o >> 6, c = o & 63;
            float s = 0.0f;
#pragma unroll 8
            for (int m = 0; m < 64; m++) s += sWk[m * 64 + c] * sWq[m * 64 + j];
            MT[c * 64 + j] = s;
        }
        if (tid < 64) {
            float sd = 0.0f, su = 0.0f;
#pragma unroll 8
            for (int m = 0; m < 64; m++) {
                sd += sWk[m * 64 + tid] * sbq[m];
                su += sbk[m] * sWq[m * 64 + tid];
            }
            dvec[tid] = sd; uvec[tid] = su;
        }
        if (tid == 0) {
            float s = 0.0f;
            for (int m = 0; m < 64; m++) s += sbk[m] * sbq[m];
            g_ec[b] = s;
        }
        __syncthreads();   // MT global writes visible within block
        split_weight_block(MT, 64, tid, mh, ml);
    } else if (bidx == 2) {
        split_weight_block(Wt, 65, tid, g_W1h, g_W1l);
        if (tid < 64) g_wtl[tid] = Wt[tid * 65 + 64];
    } else if (bidx == 3) {
        split_weight_block(Wvs, 64, tid, g_W2sh, g_W2sl);
    } else if (bidx == 4) {
        split_weight_block(Wvd, 64, tid, g_W2dh, g_W2dl);
    } else {
        int gi = (bidx - 5) * 256 + tid;
        if (gi < N) g_den[gi] = 0.0f;
        int e = gi;
        int lane = tid & 31;
        bool act = e < E;
        float es = act ? esame[e] : 0.0f;
        bool s = act && (es >= 0.5f);
        bool d = act && (es < 0.5f);
        unsigned ms = __ballot_sync(0xffffffffu, s);
        unsigned md = __ballot_sync(0xffffffffu, d);
        int bs = 0, bd = 0;
        if (lane == 0) {
            if (ms) bs = atomicAdd(&g_cnt[0], __popc(ms));
            if (md) bd = atomicAdd(&g_cnt[1], __popc(md));
        }
        bs = __shfl_sync(0xffffffffu, bs, 0);
        bd = __shfl_sync(0xffffffffu, bd, 0);
        unsigned lower = (1u << lane) - 1u;
        if (s) g_perm_s[bs + __popc(ms & lower)] = e;
        if (d) g_perm_d[bd + __popc(md & lower)] = e;
    }
}

// ---------------- kernel 1: tensor-core node kernel ---------------------------
#define NOFF_AHI 0
#define NOFF_ALO 16384
#define NOFF_MSH 32768
#define NOFF_MSL 40960
#define NOFF_MDH 49152
#define NOFF_MDL 57344
#define NOFF_DS  65536
#define NOFF_DD  65792
#define NOFF_G   66048
#define NOFF_B   66304
#define NOFF_US  66560
#define NOFF_UD  66816
#define NOFF_TMP 67072
#define NOFF_MBR 67080
#define NODE_SMEM_BYTES (1024 + 67088 + 48)

__global__ __launch_bounds__(128)
void node_tc_kernel(const float* __restrict__ x, const float* __restrict__ gamma,
                    const float* __restrict__ beta, int N)
{
    int tid = threadIdx.x;
    int n0 = blockIdx.x * 128;
    int cnt = min(128, N - n0);
    int n = n0 + tid;
    bool act = tid < cnt;

#if TC_OK
    extern __shared__ char dsm_raw[];
    uint32_t raw_u = smem_u32(dsm_raw);
    uint32_t base_u = (raw_u + 1023u) & ~1023u;
    char* sb_ = dsm_raw + (base_u - raw_u);
    int wid = tid >> 5;

    if (wid == 0) {
        TC_ALLOC(base_u + NOFF_TMP, 128);
        TC_RELINQ();
    }
    if (tid == 0) MBAR_INIT(base_u + NOFF_MBR, 1);

    float* sds = (float*)(sb_ + NOFF_DS);
    float* sdd = (float*)(sb_ + NOFF_DD);
    float* sg  = (float*)(sb_ + NOFF_G);
    float* sbv = (float*)(sb_ + NOFF_B);
    float* sus = (float*)(sb_ + NOFF_US);
    float* sud = (float*)(sb_ + NOFF_UD);

    // ---- identity copies of pre-split M blocks ----
    {
        const uint4* msh = (const uint4*)g_Msh;
        const uint4* msl = (const uint4*)g_Msl;
        const uint4* mdh = (const uint4*)g_Mdh;
        const uint4* mdl = (const uint4*)g_Mdl;
        for (int i = tid; i < 512; i += 128) {
            *(uint4*)(sb_ + NOFF_MSH + i * 16) = msh[i];
            *(uint4*)(sb_ + NOFF_MSL + i * 16) = msl[i];
            *(uint4*)(sb_ + NOFF_MDH + i * 16) = mdh[i];
            *(uint4*)(sb_ + NOFF_MDL + i * 16) = mdl[i];
        }
    }
    if (tid < 64) {
        sds[tid] = g_ds[tid]; sdd[tid] = g_dd[tid];
        sg[tid] = gamma[tid]; sbv[tid] = beta[tid];
        sus[tid] = g_us[tid]; sud[tid] = g_ud[tid];
    }
    __syncthreads();

    float4 xv[16];
    float mu = 0.0f, inv = 0.0f;
    if (act) {
        const float4* xr = (const float4*)(x + (size_t)n * 64);
        float s = 0.0f, t2 = 0.0f;
#pragma unroll
        for (int kk = 0; kk < 16; kk++) {
            xv[kk] = xr[kk];
            s  += xv[kk].x + xv[kk].y + xv[kk].z + xv[kk].w;
            t2 += xv[kk].x * xv[kk].x + xv[kk].y * xv[kk].y
                + xv[kk].z * xv[kk].z + xv[kk].w * xv[kk].w;
        }
        mu = s * (1.0f / 64.0f);
        float var = t2 * (1.0f / 64.0f) - mu * mu;
        inv = rsqrtf(var + 1e-5f);
    }
    {
        float cs = 0.0f, cd = 0.0f;
        uint32_t hb[4], lb[4];
        uint4* gh = (uint4*)(g_xnh + (size_t)n * 32);
        uint4* gl = (uint4*)(g_xnl + (size_t)n * 32);
#pragma unroll
        for (int kk = 0; kk < 16; kk++) {
            float a0 = 0.f, a1 = 0.f, a2 = 0.f, a3 = 0.f;
            if (act) {
                int c0 = kk * 4;
                a0 = (xv[kk].x - mu) * inv * sg[c0]     + sbv[c0];
                a1 = (xv[kk].y - mu) * inv * sg[c0 + 1] + sbv[c0 + 1];
                a2 = (xv[kk].z - mu) * inv * sg[c0 + 2] + sbv[c0 + 2];
                a3 = (xv[kk].w - mu) * inv * sg[c0 + 3] + sbv[c0 + 3];
                cs += a0 * sus[c0] + a1 * sus[c0 + 1] + a2 * sus[c0 + 2] + a3 * sus[c0 + 3];
                cd += a0 * sud[c0] + a1 * sud[c0 + 1] + a2 * sud[c0 + 2] + a3 * sud[c0 + 3];
            }
            int h8 = (kk & 1) * 2;
            split2(a0, a1, hb[h8],     lb[h8]);
            split2(a2, a3, hb[h8 + 1], lb[h8 + 1]);
            if (kk & 1) {
                uint32_t byte = (uint32_t)(tid * 128 + (kk >> 1) * 16);
                uint32_t swo = SW128(byte);
                uint4 h4 = make_uint4(hb[0], hb[1], hb[2], hb[3]);
                uint4 l4 = make_uint4(lb[0], lb[1], lb[2], lb[3]);
                *(uint4*)(sb_ + NOFF_AHI + swo) = h4;
                *(uint4*)(sb_ + NOFF_ALO + swo) = l4;
                if (act) { gh[kk >> 1] = h4; gl[kk >> 1] = l4; }
            }
        }
        if (act) {
            g_c_s[n] = cs + g_ec[0];
            g_c_d[n] = cd + g_ec[1];
        }
    }
    __syncthreads();

    uint32_t tmem;
    asm volatile("ld.shared.b32 %0, [%1];" : "=r"(tmem) : "r"(base_u + NOFF_TMP));

    if (tid == 0) {
        FENCE_PROXY();
        uint64_t aH = mkdesc(base_u + NOFF_AHI), aL = mkdesc(base_u + NOFF_ALO);
        uint64_t sH = mkdesc(base_u + NOFF_MSH), sL = mkdesc(base_u + NOFF_MSL);
        uint64_t dH = mkdesc(base_u + NOFF_MDH), dL = mkdesc(base_u + NOFF_MDL);
#pragma unroll
        for (int kc = 0; kc < 4; kc++) {
            mma_f16_ss(tmem, aH + kc * 2, sH + kc * 2, kc > 0 ? 1u : 0u);
            mma_f16_ss(tmem, aH + kc * 2, sL + kc * 2, 1u);
            mma_f16_ss(tmem, aL + kc * 2, sH + kc * 2, 1u);
        }
#pragma unroll
        for (int kc = 0; kc < 4; kc++) {
            mma_f16_ss(tmem + 64, aH + kc * 2, dH + kc * 2, kc > 0 ? 1u : 0u);
            mma_f16_ss(tmem + 64, aH + kc * 2, dL + kc * 2, 1u);
            mma_f16_ss(tmem + 64, aL + kc * 2, dH + kc * 2, 1u);
        }
        TC_COMMIT(base_u + NOFF_MBR);
    }

    mbar_wait(base_u + NOFF_MBR, 0);
    TC_FENCE_AFTER();

    {
        uint32_t d1[64];
        TC_LD_X32(d1, tmem);
        TC_LD_X32(d1 + 32, tmem + 32);
        TC_WAIT_LD();
        if (act) {
            float* qp = g_qh_s + (size_t)n * 64;
#pragma unroll
            for (int c = 0; c < 64; c += 4) {
                *(float4*)(qp + c) = make_float4(
                    __uint_as_float(d1[c])     + sds[c],
                    __uint_as_float(d1[c + 1]) + sds[c + 1],
                    __uint_as_float(d1[c + 2]) + sds[c + 2],
                    __uint_as_float(d1[c + 3]) + sds[c + 3]);
            }
        }
    }
    {
        uint32_t d2[64];
        TC_LD_X32(d2, tmem + 64);
        TC_LD_X32(d2 + 32, tmem + 96);
        TC_WAIT_LD();
        if (act) {
            float* qp = g_qh_d + (size_t)n * 64;
#pragma unroll
            for (int c = 0; c < 64; c += 4) {
                *(float4*)(qp + c) = make_float4(
                    __uint_as_float(d2[c])     + sdd[c],
                    __uint_as_float(d2[c + 1]) + sdd[c + 1],
                    __uint_as_float(d2[c + 2]) + sdd[c + 2],
                    __uint_as_float(d2[c + 3]) + sdd[c + 3]);
            }
        }
    }

    __syncthreads();
    if (tid == 0) MBAR_INVAL(base_u + NOFF_MBR);
    __syncthreads();
    if (wid == 0) TC_DEALLOC(tmem, 128);

#else
    if (act) {
        float xr[64];
        float s = 0.0f, t2 = 0.0f;
        for (int k = 0; k < 64; k++) {
            xr[k] = x[(size_t)n * 64 + k];
            s += xr[k]; t2 += xr[k] * xr[k];
        }
        float mu = s / 64.0f;
        float inv = rsqrtf(t2 / 64.0f - mu * mu + 1e-5f);
        float xn[64];
        float cs = 0.0f, cd = 0.0f;
        for (int k = 0; k < 64; k++) {
            xn[k] = (xr[k] - mu) * inv * gamma[k] + beta[k];
            cs += xn[k] * g_us[k];
            cd += xn[k] * g_ud[k];
        }
        g_c_s[n] = cs + g_ec[0];
        g_c_d[n] = cd + g_ec[1];
        for (int k2 = 0; k2 < 32; k2++) {
            uint32_t hp, lp;
            split2(xn[2 * k2], xn[2 * k2 + 1], hp, lp);
            g_xnh[(size_t)n * 32 + k2] = hp;
            g_xnl[(size_t)n * 32 + k2] = lp;
        }
        for (int c = 0; c < 64; c++) {
            float qs = g_ds[c], qd = g_dd[c];
            for (int j = 0; j < 64; j++) {
                qs += xn[j] * g_Ms[c * 64 + j];
                qd += xn[j] * g_Md[c * 64 + j];
            }
            g_qh_s[(size_t)n * 64 + c] = qs;
            g_qh_d[(size_t)n * 64 + c] = qd;
        }
    }
#endif
}

// ---------------- kernel 2: pipelined tensor-core edge kernel -----------------
#define OFF_AHI 0
#define OFF_ALO 16384
#define OFF_W1H 32768
#define OFF_W1L 40960
#define OFF_W2H 49152
#define OFF_W2L 57344
#define OFF_SBT 65536
#define OFF_SBV 65792
#define OFF_WTL 66048
#define OFF_SDV 66304
#define OFF_TMP 66560
#define OFF_MBR 66568
#define EDGE_SMEM_BYTES (1024 + 66576 + 48)

#if TC_OK
__device__ __forceinline__ void gather_async(char* sb, uint32_t base_u, int e,
                                             bool act, int src) {
    const uint32_t* xh = g_xnh + (size_t)src * 32;
    const uint32_t* xl = g_xnl + (size_t)src * 32;
#pragma unroll
    for (int kk = 0; kk < 8; kk++) {
        uint32_t byte = (uint32_t)(e * 128 + kk * 16);
        uint32_t swo = SW128(byte);
        if (act) {
            CP_ASYNC16(base_u + OFF_AHI + swo, xh + kk * 4);
            CP_ASYNC16(base_u + OFF_ALO + swo, xl + kk * 4);
        } else {
            uint4 z = make_uint4(0, 0, 0, 0);
            *(uint4*)(sb + OFF_AHI + swo) = z;
            *(uint4*)(sb + OFF_ALO + swo) = z;
        }
    }
    CP_COMMIT();
}
#endif

__global__ __launch_bounds__(128)
void edge_tc_kernel(
    const int* __restrict__ ei, const float* __restrict__ etime,
    const float* __restrict__ Wt,
    const float* __restrict__ bt,
    const float* __restrict__ Wvs, const float* __restrict__ bvs,
    const float* __restrict__ Wvd, const float* __restrict__ bvd,
    int E)
{
    int tid = threadIdx.x;
    int bid = blockIdx.x;

    int cs = g_cnt[0], cd = g_cnt[1];
    int ts = (cs + 127) >> 7;
    int td = (cd + 127) >> 7;
    int total = ts + td;

#if TC_OK
    extern __shared__ char dsm_raw[];
    uint32_t raw_u = smem_u32(dsm_raw);
    uint32_t base_u = (raw_u + 1023u) & ~1023u;
    char* sb = dsm_raw + (base_u - raw_u);
    int wid = tid >> 5;

    if (wid == 0) {
        TC_ALLOC(base_u + OFF_TMP, 128);
        TC_RELINQ();
    }
    if (tid == 0) MBAR_INIT(base_u + OFF_MBR, 1);

    float* sbt  = (float*)(sb + OFF_SBT);
    float* sbv  = (float*)(sb + OFF_SBV);
    float* wtl  = (float*)(sb + OFF_WTL);
    float* sdiv = (float*)(sb + OFF_SDV);

    // ---- one-time: W1 identity copy, bt, wtl, sdiv ----
    {
        const uint4* h4 = (const uint4*)g_W1h;
        const uint4* l4 = (const uint4*)g_W1l;
        for (int i = tid; i < 512; i += 128) {
            *(uint4*)(sb + OFF_W1H + i * 16) = h4[i];
            *(uint4*)(sb + OFF_W1L + i * 16) = l4[i];
        }
    }
    if (tid < 64) {
        sbt[tid] = bt[tid];
        wtl[tid] = g_wtl[tid];
        sdiv[tid] = powf(10000.0f, -(float)(2 * (tid >> 1)) / 64.0f);
    }

    // ---- prologue gather for first tile ----
    int ti = bid;
    bool c_act = false; int c_dn = 0; float c_t = 0.0f;
    if (ti < total) {
        const int* list; int off, cnt;
        if (ti < ts) { list = g_perm_s; off = ti << 7; cnt = min(128, cs - off); }
        else         { list = g_perm_d; off = (ti - ts) << 7; cnt = min(128, cd - off); }
        int src = 0;
        if (tid < cnt) {
            int pe = list[off + tid];
            src = ei[pe]; c_dn = ei[E + pe]; c_t = etime[pe];
            c_act = true;
        }
        gather_async(sb, base_u, tid, c_act, src);
    } else {
        CP_COMMIT();
    }

    int cur_same = -1;
    int ph = 0;
    for (; ti < total; ti += gridDim.x) {
        int same = (ti < ts) ? 1 : 0;
        const float* bv = same ? bvs : bvd;
        const float* qh = same ? g_qh_s : g_qh_d;
        const float* cv = same ? g_c_s  : g_c_d;

        CP_WAIT0();
        __syncthreads();   // gather visible; prev tile fully done with smem

        if (same != cur_same) {
            const uint4* h4 = (const uint4*)(same ? g_W2sh : g_W2dh);
            const uint4* l4 = (const uint4*)(same ? g_W2sl : g_W2dl);
            for (int i = tid; i < 512; i += 128) {
                *(uint4*)(sb + OFF_W2H + i * 16) = h4[i];
                *(uint4*)(sb + OFF_W2L + i * 16) = l4[i];
            }
            if (tid < 64) sbv[tid] = bv[tid];
            cur_same = same;
        }

        uint32_t tmem;
        asm volatile("ld.shared.b32 %0, [%1];" : "=r"(tmem) : "r"(base_u + OFF_TMP));

        // ---- MMA1 ----
        if (tid == 0) {
            FENCE_PROXY();
            uint64_t aH = mkdesc(base_u + OFF_AHI), aL = mkdesc(base_u + OFF_ALO);
            uint64_t bH = mkdesc(base_u + OFF_W1H), bL = mkdesc(base_u + OFF_W1L);
#pragma unroll
            for (int kc = 0; kc < 4; kc++) {
                mma_f16_ss(tmem, aH + kc * 2, bH + kc * 2, kc > 0 ? 1u : 0u);
                mma_f16_ss(tmem, aH + kc * 2, bL + kc * 2, 1u);
                mma_f16_ss(tmem, aL + kc * 2, bH + kc * 2, 1u);
            }
            TC_COMMIT(base_u + OFF_MBR);
        }

        // ---- prefetch q-row while MMA1 runs ----
        float4 qv[16];
        {
            const float4* qp = (const float4*)(qh + (size_t)c_dn * 64);
#pragma unroll
            for (int i = 0; i < 16; i++) qv[i] = qp[i];
        }
        float cvd = cv[c_dn];

        mbar_wait(base_u + OFF_MBR, ph); ph ^= 1;
        TC_FENCE_AFTER();

        // ---- epilogue 1 ----
        uint32_t d1[64];
        TC_LD_X32(d1, tmem);
        TC_LD_X32(d1 + 32, tmem + 32);
        TC_WAIT_LD();

        float ex = 0.0f;
        {
            float att = 0.0f;
            float t200 = c_t * 200.0f;
            uint32_t hbuf[4], lbuf[4];
#pragma unroll
            for (int m0 = 0; m0 < 64; m0 += 4) {
                float4 q4 = qv[m0 >> 2];
                float xt4[4];
#pragma unroll
                for (int j = 0; j < 4; j += 2) {
                    int m = m0 + j;
                    float arg = t200 * sdiv[m];
                    float sn = __sinf(arg), cc = __cosf(arg);
                    float xe = __uint_as_float(d1[m])     + sbt[m]     + c_t * wtl[m];
                    float xo = __uint_as_float(d1[m + 1]) + sbt[m + 1] + c_t * wtl[m + 1];
                    xt4[j]     = gelu_erf(xe) + sn;
                    xt4[j + 1] = gelu_erf(xo) + cc;
                }
                att += xt4[0] * q4.x + xt4[1] * q4.y + xt4[2] * q4.z + xt4[3] * q4.w;
                int half8 = (m0 & 4) ? 2 : 0;
                split2(xt4[0], xt4[1], hbuf[half8],     lbuf[half8]);
                split2(xt4[2], xt4[3], hbuf[half8 + 1], lbuf[half8 + 1]);
                if (m0 & 4) {
                    uint32_t byte = (uint32_t)(tid * 128 + (m0 - 4) * 2);
                    uint32_t swo = SW128(byte);
                    *(uint4*)(sb + OFF_AHI + swo) = make_uint4(hbuf[0], hbuf[1], hbuf[2], hbuf[3]);
                    *(uint4*)(sb + OFF_ALO + swo) = make_uint4(lbuf[0], lbuf[1], lbuf[2], lbuf[3]);
                }
            }
            if (c_act) {
                ex = __expf((att + cvd) * 0.125f);
                atomicAdd(&g_den[c_dn], ex);
            }
        }
        __syncthreads();

        // ---- MMA2 ----
        if (tid == 0) {
            FENCE_PROXY();
            uint64_t aH = mkdesc(base_u + OFF_AHI), aL = mkdesc(base_u + OFF_ALO);
            uint64_t bH = mkdesc(base_u + OFF_W2H), bL = mkdesc(base_u + OFF_W2L);
#pragma unroll
            for (int kc = 0; kc < 4; kc++) {
                mma_f16_ss(tmem + 64, aH + kc * 2, bH + kc * 2, kc > 0 ? 1u : 0u);
                mma_f16_ss(tmem + 64, aH + kc * 2, bL + kc * 2, 1u);
                mma_f16_ss(tmem + 64, aL + kc * 2, bH + kc * 2, 1u);
            }
            TC_COMMIT(base_u + OFF_MBR);
        }

        // ---- prefetch next tile meta while MMA2 runs ----
        int tn = ti + gridDim.x;
        bool n_act = false; int n_src = 0, n_dn = 0; float n_t = 0.0f;
        if (tn < total) {
            const int* nlist; int noff, ncnt;
            if (tn < ts) { nlist = g_perm_s; noff = tn << 7; ncnt = min(128, cs - noff); }
            else         { nlist = g_perm_d; noff = (tn - ts) << 7; ncnt = min(128, cd - noff); }
            if (tid < ncnt) {
                int pe = nlist[noff + tid];
                n_src = ei[pe]; n_dn = ei[E + pe]; n_t = etime[pe];
                n_act = true;
            }
        }

        mbar_wait(base_u + OFF_MBR, ph); ph ^= 1;
        TC_FENCE_AFTER();

        uint32_t d2[64];
        TC_LD_X32(d2, tmem + 64);
        TC_LD_X32(d2 + 32, tmem + 96);
        TC_WAIT_LD();

        // ---- A buffers now free: issue next tile's gather (overlaps reds) ----
        if (tn < total) gather_async(sb, base_u, tid, n_act, n_src);

        if (c_act) {
            float* dp = g_aggr + (size_t)c_dn * 64;
#pragma unroll
            for (int m0 = 0; m0 < 64; m0 += 4) {
                float v0 = (__uint_as_float(d2[m0])     + sbv[m0])     * ex;
                float v1 = (__uint_as_float(d2[m0 + 1]) + sbv[m0 + 1]) * ex;
                float v2 = (__uint_as_float(d2[m0 + 2]) + sbv[m0 + 2]) * ex;
                float v3 = (__uint_as_float(d2[m0 + 3]) + sbv[m0 + 3]) * ex;
                asm volatile("red.global.add.v4.f32 [%0], {%1, %2, %3, %4};"
                             :: "l"(dp + m0), "f"(v0), "f"(v1), "f"(v2), "f"(v3) : "memory");
            }
        }

        c_act = n_act; c_dn = n_dn; c_t = n_t;
    }

    CP_WAIT0();
    __syncthreads();
    if (tid == 0) MBAR_INVAL(base_u + OFF_MBR);
    __syncthreads();
    {
        uint32_t tmem;
        asm volatile("ld.shared.b32 %0, [%1];" : "=r"(tmem) : "r"(base_u + OFF_TMP));
        if (wid == 0) TC_DEALLOC(tmem, 128);
    }

#else   // ---------------- fp32 fallback (non-'a' PTX pass only) -------------
    for (int ti = bid; ti < total; ti += gridDim.x) {
        int same, off, cnt;
        const int* list;
        if (ti < ts) { list = g_perm_s; off = ti << 7; cnt = min(128, cs - off); same = 1; }
        else         { list = g_perm_d; off = (ti - ts) << 7; cnt = min(128, cd - off); same = 0; }
        const float* Wv = same ? Wvs : Wvd;
        const float* bv = same ? bvs : bvd;
        const float* qh = same ? g_qh_s : g_qh_d;
        const float* cv = same ? g_c_s  : g_c_d;
        int e = tid;
        if (e < cnt) {
            int pe = list[off + e];
            int src = ei[pe], dn = ei[E + pe];
            float t = etime[pe];
            float t200 = t * 200.0f;
            float xrow[64];
            for (int k2 = 0; k2 < 32; k2++) {
                uint32_t h = g_xnh[(size_t)src * 32 + k2];
                uint32_t l = g_xnl[(size_t)src * 32 + k2];
                xrow[2 * k2]     = __uint_as_float(h << 16) + __uint_as_float(l << 16);
                xrow[2 * k2 + 1] = __uint_as_float(h & 0xffff0000u) + __uint_as_float(l & 0xffff0000u);
            }
            float xt[64];
            float att = 0.0f;
            for (int m = 0; m < 64; m++) {
                float a = bt[m] + t * Wt[m * 65 + 64];
                for (int k = 0; k < 64; k++) a += xrow[k] * Wt[m * 65 + k];
                float dv = powf(10000.0f, -(float)(2 * (m / 2)) / 64.0f);
                float te = (m & 1) ? cosf(t200 * dv) : sinf(t200 * dv);
                xt[m] = gelu_erf(a) + te;
                att += xt[m] * qh[(size_t)dn * 64 + m];
            }
            float ex = expf((att + cv[dn]) * 0.125f);
            atomicAdd(&g_den[dn], ex);
            for (int m = 0; m < 64; m++) {
                float v = bv[m];
                for (int k = 0; k < 64; k++) v += xt[k] * Wv[m * 64 + k];
                atomicAdd(&g_aggr[(size_t)dn * 64 + m], ex * v);
            }
        }
    }
#endif
}

// ---------------- kernel 5: epilogue (float4) + cleanup -----------------------
__global__ void final_kernel(const float* __restrict__ x, float* __restrict__ out, int N) {
    int i4 = blockIdx.x * blockDim.x + threadIdx.x;   // float4 index
    int total4 = N * 16;                              // N*64/4
    if (i4 < total4) {
        float den = g_den[i4 >> 4] + 1e-16f;
        float4 a = ((float4*)g_aggr)[i4];
        float4 xv = ((const float4*)x)[i4];
        float4 o;
        o.x = xv.x + gelu_erf(a.x / den);
        o.y = xv.y + gelu_erf(a.y / den);
        o.z = xv.z + gelu_erf(a.z / den);
        o.w = xv.w + gelu_erf(a.w / den);
        ((float4*)out)[i4] = o;
        ((float4*)g_aggr)[i4] = make_float4(0.f, 0.f, 0.f, 0.f);   // same-index: race-free
    }
    if (i4 == 0) { g_cnt[0] = 0; g_cnt[1] = 0; }
}

// ---------------- launch ------------------------------------------------------
extern "C" void kernel_launch(void* const* d_in, const int* in_sizes, int n_in,
                              void* d_out, int out_size) {
    const float* x     = (const float*)d_in[0];
    const int*   ei    = (const int*)  d_in[1];
    const float* etime = (const float*)d_in[2];
    const float* esame = (const float*)d_in[4];
    const float* lng   = (const float*)d_in[5];
    const float* lnb   = (const float*)d_in[6];
    const float* Wt    = (const float*)d_in[7];
    const float* bt    = (const float*)d_in[8];
    const float* Wq    = (const float*)d_in[9];
    const float* bq    = (const float*)d_in[10];
    const float* Wks   = (const float*)d_in[11];
    const float* bks   = (const float*)d_in[12];
    const float* Wkd   = (const float*)d_in[13];
    const float* bkd   = (const float*)d_in[14];
    const float* Wvs   = (const float*)d_in[15];
    const float* bvs   = (const float*)d_in[16];
    const float* Wvd   = (const float*)d_in[17];
    const float* bvd   = (const float*)d_in[18];
    float* out = (float*)d_out;

    int N = in_sizes[0] / D;
    int E = in_sizes[2];
    if (N > MAXN) N = MAXN;
    if (E > MAXE) E = MAXE;

    cudaFuncSetAttribute(node_tc_kernel, cudaFuncAttributeMaxDynamicSharedMemorySize,
                         NODE_SMEM_BYTES);
    cudaFuncSetAttribute(edge_tc_kernel, cudaFuncAttributeMaxDynamicSharedMemorySize,
                         EDGE_SMEM_BYTES);

    int max_tiles = (E + 127) / 128 + 2;
    int edge_grid = max_tiles < 444 ? max_tiles : 444;

    prep_kernel<<<5 + (E + 255) / 256, 256>>>(esame, Wq, bq, Wks, bks, Wkd, bkd,
                                              Wt, Wvs, Wvd, E, N);
    node_tc_kernel<<<(N + 127) / 128, 128, NODE_SMEM_BYTES>>>(x, lng, lnb, N);
    edge_tc_kernel<<<edge_grid, 128, EDGE_SMEM_BYTES>>>(
        ei, etime, Wt, bt, Wvs, bvs, Wvd, bvd, E);
    final_kernel<<<(N * 16 + 255) / 256, 256>>>(x, out, N);
}